// round 5
// baseline (speedup 1.0000x reference)
#include <cuda_runtime.h>
#include <cuda_bf16.h>
#include <math.h>

#define BATCH 4
#define TLEN  2048
#define DMODEL 1024
#define DINT   1024
#define MTOT  (BATCH * TLEN)     // 8192
#define HALFD (DINT / 2)         // 512

// ---------------------------------------------------------------------------
// Scratch (device globals; no allocation allowed)
// ---------------------------------------------------------------------------
__device__ float g_Q[MTOT * DINT];                       // f32 (rope input)
__device__ float g_K[MTOT * DINT];
__device__ float g_S[BATCH * TLEN * TLEN];               // scores f32
__device__ __nv_bfloat16 g_Qhi[MTOT * DINT], g_Qlo[MTOT * DINT];
__device__ __nv_bfloat16 g_Khi[MTOT * DINT], g_Klo[MTOT * DINT];
__device__ __nv_bfloat16 g_Vhi[MTOT * DINT], g_Vlo[MTOT * DINT];
__device__ __nv_bfloat16 g_Phi[BATCH * TLEN * TLEN], g_Plo[BATCH * TLEN * TLEN];
__device__ __nv_bfloat16 g_Xhi[MTOT * DMODEL], g_Xlo[MTOT * DMODEL];
__device__ __nv_bfloat16 g_Whi[3 * DINT * DMODEL], g_Wlo[3 * DINT * DMODEL];
__device__ float g_invfreq[HALFD];

// ---------------------------------------------------------------------------
// Helpers
// ---------------------------------------------------------------------------
__device__ __forceinline__ unsigned smem_u32(const void* p) {
    return (unsigned)__cvta_generic_to_shared(p);
}
__device__ __forceinline__ void cp16(unsigned dst, const void* src) {
    asm volatile("cp.async.cg.shared.global [%0], [%1], 16;" :: "r"(dst), "l"(src));
}
__device__ __forceinline__ void cp_commit() {
    asm volatile("cp.async.commit_group;");
}
template <int N>
__device__ __forceinline__ void cp_wait() {
    asm volatile("cp.async.wait_group %0;" :: "n"(N));
}
__device__ __forceinline__ void ldm_x4(unsigned a, unsigned& r0, unsigned& r1,
                                       unsigned& r2, unsigned& r3) {
    asm volatile("ldmatrix.sync.aligned.m8n8.x4.shared.b16 {%0,%1,%2,%3}, [%4];"
                 : "=r"(r0), "=r"(r1), "=r"(r2), "=r"(r3) : "r"(a));
}
__device__ __forceinline__ void ldm_x4_t(unsigned a, unsigned& r0, unsigned& r1,
                                         unsigned& r2, unsigned& r3) {
    asm volatile("ldmatrix.sync.aligned.m8n8.x4.trans.shared.b16 {%0,%1,%2,%3}, [%4];"
                 : "=r"(r0), "=r"(r1), "=r"(r2), "=r"(r3) : "r"(a));
}
__device__ __forceinline__ void mma16816(float* c, const unsigned* a,
                                         unsigned b0, unsigned b1) {
    asm volatile("mma.sync.aligned.m16n8k16.row.col.f32.bf16.bf16.f32 "
                 "{%0,%1,%2,%3}, {%4,%5,%6,%7}, {%8,%9}, {%0,%1,%2,%3};"
                 : "+f"(c[0]), "+f"(c[1]), "+f"(c[2]), "+f"(c[3])
                 : "r"(a[0]), "r"(a[1]), "r"(a[2]), "r"(a[3]), "r"(b0), "r"(b1));
}
__device__ __forceinline__ void split2(float x, float y,
                                       __nv_bfloat162& h, __nv_bfloat162& l) {
    h.x = __float2bfloat16_rn(x);
    h.y = __float2bfloat16_rn(y);
    l.x = __float2bfloat16_rn(x - __bfloat162float(h.x));
    l.y = __float2bfloat16_rn(y - __bfloat162float(h.y));
}

// smem stage layout (bytes): Ahi[128*40] Alo[128*40] Bhi[64*40] Blo[64*40]
#define STAGE_BYTES 30720
#define SA_LO (128 * 40)
#define SB_HI (2 * 128 * 40)
#define SB_LO (2 * 128 * 40 + 64 * 40)
// PV stage: Phi[128*40] Plo[128*40] Vhi[32*72] Vlo[32*72]
#define SV_HI (2 * 128 * 40)
#define SV_LO (2 * 128 * 40 + 32 * 72)

// ---------------------------------------------------------------------------
// TN loaders / compute (A 128xk, B 64xk, both k-contiguous, pre-split bf16)
// ---------------------------------------------------------------------------
__device__ __forceinline__ void load_tn(char* st,
    const __nv_bfloat16* Ahi, const __nv_bfloat16* Alo, int strideA,
    const __nv_bfloat16* Bhi, const __nv_bfloat16* Blo, int strideB, int tid)
{
    __nv_bfloat16* s = (__nv_bfloat16*)st;
    const int r   = tid >> 1;           // 0..127
    const int ch0 = (tid & 1) * 2;      // chunk 0/2
    #pragma unroll
    for (int j = 0; j < 2; ++j) {
        int ch = ch0 + j;
        cp16(smem_u32(&s[r * 40 + ch * 8]),         Ahi + (size_t)r * strideA + ch * 8);
        cp16(smem_u32(&s[SA_LO + r * 40 + ch * 8]), Alo + (size_t)r * strideA + ch * 8);
    }
    const int rb = tid >> 2, chb = tid & 3;   // 64 x 4
    cp16(smem_u32(&s[SB_HI + rb * 40 + chb * 8]), Bhi + (size_t)rb * strideB + chb * 8);
    cp16(smem_u32(&s[SB_LO + rb * 40 + chb * 8]), Blo + (size_t)rb * strideB + chb * 8);
}

__device__ __forceinline__ void compute_tn(const char* st, int lane, int wm, int wn,
                                           float acc[2][4][4])
{
    const __nv_bfloat16* sAhi = (const __nv_bfloat16*)st;
    const __nv_bfloat16* sAlo = sAhi + SA_LO;
    const __nv_bfloat16* sBhi = sAhi + SB_HI;
    const __nv_bfloat16* sBlo = sAhi + SB_LO;
    const int lr  = (lane & 7) + ((lane >> 3) & 1) * 8;
    const int lc8 = (lane >> 4) * 8;
    #pragma unroll
    for (int ks = 0; ks < 2; ++ks) {
        const int kb = ks * 16 + lc8;
        unsigned ah[2][4], al[2][4], bh[2][4], bl[2][4];
        #pragma unroll
        for (int mf = 0; mf < 2; ++mf) {
            int row = wm * 32 + mf * 16 + lr;
            ldm_x4(smem_u32(&sAhi[row * 40 + kb]), ah[mf][0], ah[mf][1], ah[mf][2], ah[mf][3]);
            ldm_x4(smem_u32(&sAlo[row * 40 + kb]), al[mf][0], al[mf][1], al[mf][2], al[mf][3]);
        }
        #pragma unroll
        for (int g = 0; g < 2; ++g) {
            int row = wn * 32 + g * 16 + lr;
            ldm_x4(smem_u32(&sBhi[row * 40 + kb]), bh[g][0], bh[g][1], bh[g][2], bh[g][3]);
            ldm_x4(smem_u32(&sBlo[row * 40 + kb]), bl[g][0], bl[g][1], bl[g][2], bl[g][3]);
        }
        #pragma unroll
        for (int mf = 0; mf < 2; ++mf)
            #pragma unroll
            for (int nf = 0; nf < 4; ++nf) {
                int g = nf >> 1, sdx = nf & 1;
                mma16816(acc[mf][nf], ah[mf], bh[g][sdx], bh[g][sdx + 2]);
                mma16816(acc[mf][nf], ah[mf], bl[g][sdx], bl[g][sdx + 2]);
                mma16816(acc[mf][nf], al[mf], bh[g][sdx], bh[g][sdx + 2]);
            }
    }
}

__device__ __forceinline__ void pipe_tn(
    const __nv_bfloat16* Ahi, const __nv_bfloat16* Alo, int strideA,
    const __nv_bfloat16* Bhi, const __nv_bfloat16* Blo, int strideB,
    int nIter, char* sm, float acc[2][4][4])
{
    const int tid = threadIdx.x, lane = tid & 31, warp = tid >> 5;
    const int wm = warp & 3, wn = warp >> 2;
    load_tn(sm, Ahi, Alo, strideA, Bhi, Blo, strideB, tid);
    cp_commit();
    for (int i = 0; i < nIter; ++i) {
        if (i + 1 < nIter) {
            load_tn(sm + ((i + 1) & 1) * STAGE_BYTES,
                    Ahi + (i + 1) * 32, Alo + (i + 1) * 32, strideA,
                    Bhi + (i + 1) * 32, Blo + (i + 1) * 32, strideB, tid);
            cp_commit();
            cp_wait<1>();
        } else {
            cp_wait<0>();
        }
        __syncthreads();
        compute_tn(sm + (i & 1) * STAGE_BYTES, lane, wm, wn, acc);
        __syncthreads();
    }
}

// ---------------------------------------------------------------------------
// init + splits
// ---------------------------------------------------------------------------
__global__ void init_freq_kernel() {
    int p = blockIdx.x * blockDim.x + threadIdx.x;
    if (p < HALFD) {
        double e = exp(-((double)(2 * p) / (double)DINT) * 9.210340371976184);
        g_invfreq[p] = (float)e;
    }
}

__global__ __launch_bounds__(256)
void split_kernel(const float2* __restrict__ src, __nv_bfloat162* __restrict__ hi,
                  __nv_bfloat162* __restrict__ lo, int n2) {
    int i = blockIdx.x * blockDim.x + threadIdx.x;
    if (i < n2) {
        float2 v = src[i];
        __nv_bfloat162 h, l;
        split2(v.x, v.y, h, l);
        hi[i] = h; lo[i] = l;
    }
}

// ---------------------------------------------------------------------------
// Kernel 1: QKV GEMM (pipelined). M=8192, N=3072, K=1024.
// Writes Q,K f32; V split bf16.
// ---------------------------------------------------------------------------
__global__ __launch_bounds__(256)
void qkv_gemm_pipe() {
    extern __shared__ char sm[];
    const int m0 = blockIdx.y * 128, n0 = blockIdx.x * 64;
    float acc[2][4][4] = {};
    pipe_tn(g_Xhi + (size_t)m0 * DMODEL, g_Xlo + (size_t)m0 * DMODEL, DMODEL,
            g_Whi + (size_t)n0 * DMODEL, g_Wlo + (size_t)n0 * DMODEL, DMODEL,
            DMODEL / 32, sm, acc);

    const int tid = threadIdx.x, lane = tid & 31, warp = tid >> 5;
    const int wm = warp & 3, wn = warp >> 2;
    if (n0 < 2 * DINT) {
        float* dst = (n0 < DINT) ? g_Q : g_K;
        int nb = (n0 < DINT) ? n0 : n0 - DINT;
        #pragma unroll
        for (int mf = 0; mf < 2; ++mf)
            #pragma unroll
            for (int nf = 0; nf < 4; ++nf) {
                int r = m0 + wm * 32 + mf * 16 + (lane >> 2);
                int c = nb + wn * 32 + nf * 8 + (lane & 3) * 2;
                *(float2*)&dst[(size_t)r * DINT + c]       = make_float2(acc[mf][nf][0], acc[mf][nf][1]);
                *(float2*)&dst[(size_t)(r + 8) * DINT + c] = make_float2(acc[mf][nf][2], acc[mf][nf][3]);
            }
    } else {
        int nb = n0 - 2 * DINT;
        #pragma unroll
        for (int mf = 0; mf < 2; ++mf)
            #pragma unroll
            for (int nf = 0; nf < 4; ++nf) {
                int r = m0 + wm * 32 + mf * 16 + (lane >> 2);
                int c = nb + wn * 32 + nf * 8 + (lane & 3) * 2;
                __nv_bfloat162 h, l;
                split2(acc[mf][nf][0], acc[mf][nf][1], h, l);
                *(__nv_bfloat162*)&g_Vhi[(size_t)r * DINT + c] = h;
                *(__nv_bfloat162*)&g_Vlo[(size_t)r * DINT + c] = l;
                split2(acc[mf][nf][2], acc[mf][nf][3], h, l);
                *(__nv_bfloat162*)&g_Vhi[(size_t)(r + 8) * DINT + c] = h;
                *(__nv_bfloat162*)&g_Vlo[(size_t)(r + 8) * DINT + c] = l;
            }
    }
}

// ---------------------------------------------------------------------------
// Kernel 2: RoPE + L2 norm + scale; writes pre-split bf16 Q,K.
// ---------------------------------------------------------------------------
__global__ __launch_bounds__(256)
void rope_norm_kernel(const float* __restrict__ sqk, float sqk_mul) {
    const int token = blockIdx.x;
    const int tpos = token & (TLEN - 1);
    const bool isQ = (blockIdx.y == 0);
    const float* row = (isQ ? g_Q : g_K) + (size_t)token * DINT;
    __nv_bfloat16* outhi = (isQ ? g_Qhi : g_Khi) + (size_t)token * DINT;
    __nv_bfloat16* outlo = (isQ ? g_Qlo : g_Klo) + (size_t)token * DINT;

    const int tid = threadIdx.x;
    float na[2], nb[2];
    float ss = 0.0f;
    #pragma unroll
    for (int h = 0; h < 2; ++h) {
        int p = tid + h * 256;
        float a = row[p];
        float b = row[p + HALFD];
        float ang = (float)tpos * g_invfreq[p];
        float s, c;
        sincosf(ang, &s, &c);
        na[h] = a * c - b * s;
        nb[h] = b * c + a * s;
        ss += na[h] * na[h] + nb[h] * nb[h];
    }
    __shared__ float warp_red[8];
    #pragma unroll
    for (int o = 16; o > 0; o >>= 1) ss += __shfl_xor_sync(0xffffffffu, ss, o);
    if ((tid & 31) == 0) warp_red[tid >> 5] = ss;
    __syncthreads();
    __shared__ float total_sh;
    if (tid == 0) {
        float t = 0.0f;
        #pragma unroll
        for (int w = 0; w < 8; ++w) t += warp_red[w];
        total_sh = t;
    }
    __syncthreads();
    float rnorm = 1.0f / sqrtf(total_sh);
    #pragma unroll
    for (int h = 0; h < 2; ++h) {
        int p = tid + h * 256;
        float va = na[h] * rnorm * (sqk[p] * sqk_mul);
        float vb = nb[h] * rnorm * (sqk[p + HALFD] * sqk_mul);
        __nv_bfloat16 ha = __float2bfloat16_rn(va);
        __nv_bfloat16 hb = __float2bfloat16_rn(vb);
        outhi[p]         = ha;
        outlo[p]         = __float2bfloat16_rn(va - __bfloat162float(ha));
        outhi[p + HALFD] = hb;
        outlo[p + HALFD] = __float2bfloat16_rn(vb - __bfloat162float(hb));
    }
}

// ---------------------------------------------------------------------------
// Kernel 3: scores S = scale * Q K^T (pipelined, causal block skip)
// ---------------------------------------------------------------------------
__global__ __launch_bounds__(256)
void qk_gemm_pipe(float scale) {
    const int b  = blockIdx.z;
    const int q0 = blockIdx.y * 128;
    const int k0n = blockIdx.x * 64;
    if (k0n >= q0 + 128) return;
    extern __shared__ char sm[];

    float acc[2][4][4] = {};
    pipe_tn(g_Qhi + ((size_t)b * TLEN + q0) * DINT, g_Qlo + ((size_t)b * TLEN + q0) * DINT, DINT,
            g_Khi + ((size_t)b * TLEN + k0n) * DINT, g_Klo + ((size_t)b * TLEN + k0n) * DINT, DINT,
            DINT / 32, sm, acc);

    float* S = g_S + (size_t)b * TLEN * TLEN;
    const int tid = threadIdx.x, lane = tid & 31, warp = tid >> 5;
    const int wm = warp & 3, wn = warp >> 2;
    #pragma unroll
    for (int mf = 0; mf < 2; ++mf)
        #pragma unroll
        for (int nf = 0; nf < 4; ++nf) {
            int q = q0 + wm * 32 + mf * 16 + (lane >> 2);
            int c = k0n + wn * 32 + nf * 8 + (lane & 3) * 2;
            *(float2*)&S[(size_t)q * TLEN + c] =
                make_float2(acc[mf][nf][0] * scale, acc[mf][nf][1] * scale);
            *(float2*)&S[(size_t)(q + 8) * TLEN + c] =
                make_float2(acc[mf][nf][2] * scale, acc[mf][nf][3] * scale);
        }
}

// ---------------------------------------------------------------------------
// Kernel 4: causal softmax; writes pre-split bf16 P (exact zeros above diag).
// ---------------------------------------------------------------------------
__global__ __launch_bounds__(256)
void softmax_kernel() {
    const int q = blockIdx.x;
    const int b = blockIdx.y;
    const float* row = g_S + ((size_t)b * TLEN + q) * TLEN;
    __nv_bfloat16* phi = g_Phi + ((size_t)b * TLEN + q) * TLEN;
    __nv_bfloat16* plo = g_Plo + ((size_t)b * TLEN + q) * TLEN;
    const int tid = threadIdx.x;

    float vals[8];
    float m = -INFINITY;
    #pragma unroll
    for (int i = 0; i < 8; ++i) {
        int k = i * 256 + tid;
        float v = (k <= q) ? row[k] : -INFINITY;
        vals[i] = v;
        m = fmaxf(m, v);
    }
    __shared__ float warp_red[8];
    __shared__ float bcast;
    #pragma unroll
    for (int o = 16; o > 0; o >>= 1) m = fmaxf(m, __shfl_xor_sync(0xffffffffu, m, o));
    if ((tid & 31) == 0) warp_red[tid >> 5] = m;
    __syncthreads();
    if (tid == 0) {
        float t = warp_red[0];
        #pragma unroll
        for (int w = 1; w < 8; ++w) t = fmaxf(t, warp_red[w]);
        bcast = t;
    }
    __syncthreads();
    const float rowmax = bcast;

    float sum = 0.0f;
    #pragma unroll
    for (int i = 0; i < 8; ++i) {
        int k = i * 256 + tid;
        float e = (k <= q) ? expf(vals[i] - rowmax) : 0.0f;
        vals[i] = e;
        sum += e;
    }
    #pragma unroll
    for (int o = 16; o > 0; o >>= 1) sum += __shfl_xor_sync(0xffffffffu, sum, o);
    if ((tid & 31) == 0) warp_red[tid >> 5] = sum;
    __syncthreads();
    if (tid == 0) {
        float t = 0.0f;
        #pragma unroll
        for (int w = 0; w < 8; ++w) t += warp_red[w];
        bcast = t;
    }
    __syncthreads();
    const float inv = 1.0f / bcast;
    #pragma unroll
    for (int i = 0; i < 8; ++i) {
        int k = i * 256 + tid;
        float p = vals[i] * inv;
        __nv_bfloat16 h = __float2bfloat16_rn(p);
        phi[k] = h;
        plo[k] = __float2bfloat16_rn(p - __bfloat162float(h));
    }
}

// ---------------------------------------------------------------------------
// Kernel 5: O = P V (pipelined). P k-contig (non-trans A); V n-contig (trans B).
// ---------------------------------------------------------------------------
__device__ __forceinline__ void load_pv(char* st,
    const __nv_bfloat16* Phi, const __nv_bfloat16* Plo,
    const __nv_bfloat16* Vhi, const __nv_bfloat16* Vlo, int tid)
{
    __nv_bfloat16* s = (__nv_bfloat16*)st;
    const int r   = tid >> 1;
    const int ch0 = (tid & 1) * 2;
    #pragma unroll
    for (int j = 0; j < 2; ++j) {
        int ch = ch0 + j;
        cp16(smem_u32(&s[r * 40 + ch * 8]),         Phi + (size_t)r * TLEN + ch * 8);
        cp16(smem_u32(&s[SA_LO + r * 40 + ch * 8]), Plo + (size_t)r * TLEN + ch * 8);
    }
    const int rv = tid >> 3, chv = tid & 7;    // 32 x 8
    cp16(smem_u32(&s[SV_HI + rv * 72 + chv * 8]), Vhi + (size_t)rv * DINT + chv * 8);
    cp16(smem_u32(&s[SV_LO + rv * 72 + chv * 8]), Vlo + (size_t)rv * DINT + chv * 8);
}

__global__ __launch_bounds__(256)
void pv_gemm_pipe(float* __restrict__ out) {
    const int b  = blockIdx.z;
    const int q0 = blockIdx.y * 128;
    const int n0 = blockIdx.x * 64;
    extern __shared__ char sm[];

    const __nv_bfloat16* Phi = g_Phi + ((size_t)b * TLEN + q0) * TLEN;
    const __nv_bfloat16* Plo = g_Plo + ((size_t)b * TLEN + q0) * TLEN;
    const __nv_bfloat16* Vhi = g_Vhi + (size_t)b * TLEN * DINT + n0;
    const __nv_bfloat16* Vlo = g_Vlo + (size_t)b * TLEN * DINT + n0;
    const int nIter = (q0 + 128) / 32;

    const int tid = threadIdx.x, lane = tid & 31, warp = tid >> 5;
    const int wm = warp & 3, wn = warp >> 2;
    const int lrA = (lane & 7) + ((lane >> 3) & 1) * 8;
    const int lcA8 = (lane >> 4) * 8;
    const int lrV = (lane & 7) + ((lane >> 4) & 1) * 8;
    const int lcV8 = ((lane >> 3) & 1) * 8;

    float acc[2][4][4] = {};

    load_pv(sm, Phi, Plo, Vhi, Vlo, tid);
    cp_commit();
    for (int i = 0; i < nIter; ++i) {
        if (i + 1 < nIter) {
            load_pv(sm + ((i + 1) & 1) * STAGE_BYTES,
                    Phi + (i + 1) * 32, Plo + (i + 1) * 32,
                    Vhi + (size_t)(i + 1) * 32 * DINT, Vlo + (size_t)(i + 1) * 32 * DINT, tid);
            cp_commit();
            cp_wait<1>();
        } else {
            cp_wait<0>();
        }
        __syncthreads();
        {
            const char* st = sm + (i & 1) * STAGE_BYTES;
            const __nv_bfloat16* sPhi = (const __nv_bfloat16*)st;
            const __nv_bfloat16* sPlo = sPhi + SA_LO;
            const __nv_bfloat16* sVhi = sPhi + SV_HI;
            const __nv_bfloat16* sVlo = sPhi + SV_LO;
            #pragma unroll
            for (int ks = 0; ks < 2; ++ks) {
                const int kbA = ks * 16 + lcA8;
                const int kbV = ks * 16 + lrV;
                unsigned ah[2][4], al[2][4], bh[2][4], bl[2][4];
                #pragma unroll
                for (int mf = 0; mf < 2; ++mf) {
                    int row = wm * 32 + mf * 16 + lrA;
                    ldm_x4(smem_u32(&sPhi[row * 40 + kbA]), ah[mf][0], ah[mf][1], ah[mf][2], ah[mf][3]);
                    ldm_x4(smem_u32(&sPlo[row * 40 + kbA]), al[mf][0], al[mf][1], al[mf][2], al[mf][3]);
                }
                #pragma unroll
                for (int g = 0; g < 2; ++g) {
                    int col = wn * 32 + g * 16 + lcV8;
                    ldm_x4_t(smem_u32(&sVhi[kbV * 72 + col]), bh[g][0], bh[g][1], bh[g][2], bh[g][3]);
                    ldm_x4_t(smem_u32(&sVlo[kbV * 72 + col]), bl[g][0], bl[g][1], bl[g][2], bl[g][3]);
                }
                #pragma unroll
                for (int mf = 0; mf < 2; ++mf)
                    #pragma unroll
                    for (int nf = 0; nf < 4; ++nf) {
                        int g = nf >> 1, sdx = nf & 1;
                        mma16816(acc[mf][nf], ah[mf], bh[g][sdx], bh[g][sdx + 2]);
                        mma16816(acc[mf][nf], ah[mf], bl[g][sdx], bl[g][sdx + 2]);
                        mma16816(acc[mf][nf], al[mf], bh[g][sdx], bh[g][sdx + 2]);
                    }
            }
        }
        __syncthreads();
    }

    #pragma unroll
    for (int mf = 0; mf < 2; ++mf)
        #pragma unroll
        for (int nf = 0; nf < 4; ++nf) {
            int q = q0 + wm * 32 + mf * 16 + (lane >> 2);
            int c = n0 + wn * 32 + nf * 8 + (lane & 3) * 2;
            *(float2*)&out[((size_t)(b * TLEN + q)) * DINT + c] =
                make_float2(acc[mf][nf][0], acc[mf][nf][1]);
            *(float2*)&out[((size_t)(b * TLEN + q + 8)) * DINT + c] =
                make_float2(acc[mf][nf][2], acc[mf][nf][3]);
        }
}

// ---------------------------------------------------------------------------
// Launch
// ---------------------------------------------------------------------------
extern "C" void kernel_launch(void* const* d_in, const int* in_sizes, int n_in,
                              void* d_out, int out_size) {
    (void)n_in; (void)out_size; (void)in_sizes;
    const float* input_vecs = (const float*)d_in[0];
    const float* qkv_w      = (const float*)d_in[1];
    const float* sqk        = (const float*)d_in[2];
    float* out              = (float*)d_out;

    const float sqk_mul = sqrtf((float)DMODEL);
    const float scale   = sqrtf((float)DMODEL);
    const int DSMEM = 2 * STAGE_BYTES;   // 61440

    cudaFuncSetAttribute(qkv_gemm_pipe, cudaFuncAttributeMaxDynamicSharedMemorySize, DSMEM);
    cudaFuncSetAttribute(qk_gemm_pipe,  cudaFuncAttributeMaxDynamicSharedMemorySize, DSMEM);
    cudaFuncSetAttribute(pv_gemm_pipe,  cudaFuncAttributeMaxDynamicSharedMemorySize, DSMEM);

    init_freq_kernel<<<2, 256>>>();

    // Split X and W into bf16 hi/lo
    __nv_bfloat162 *xhi, *xlo, *whi, *wlo;
    cudaGetSymbolAddress((void**)&xhi, g_Xhi);
    cudaGetSymbolAddress((void**)&xlo, g_Xlo);
    cudaGetSymbolAddress((void**)&whi, g_Whi);
    cudaGetSymbolAddress((void**)&wlo, g_Wlo);
    int nx2 = MTOT * DMODEL / 2, nw2 = 3 * DINT * DMODEL / 2;
    split_kernel<<<(nx2 + 255) / 256, 256>>>((const float2*)input_vecs, xhi, xlo, nx2);
    split_kernel<<<(nw2 + 255) / 256, 256>>>((const float2*)qkv_w, whi, wlo, nw2);

    qkv_gemm_pipe<<<dim3(3 * DINT / 64, MTOT / 128), 256, DSMEM>>>();

    rope_norm_kernel<<<dim3(MTOT, 2), 256>>>(sqk, sqk_mul);

    qk_gemm_pipe<<<dim3(TLEN / 64, TLEN / 128, BATCH), 256, DSMEM>>>(scale);

    softmax_kernel<<<dim3(TLEN, BATCH), 256>>>();

    pv_gemm_pipe<<<dim3(DINT / 64, TLEN / 128, BATCH), 256, DSMEM>>>(out);
}

// round 7
// speedup vs baseline: 1.0280x; 1.0280x over previous
#include <cuda_runtime.h>
#include <cuda_bf16.h>
#include <math.h>

#define BATCH 4
#define TLEN  2048
#define DMODEL 1024
#define DINT   1024
#define MTOT  (BATCH * TLEN)     // 8192
#define HALFD (DINT / 2)         // 512

// ---------------------------------------------------------------------------
// Scratch (device globals; no allocation allowed)
// ---------------------------------------------------------------------------
__device__ float g_Q[MTOT * DINT];                       // f32 (rope input)
__device__ float g_K[MTOT * DINT];
__device__ float g_S[BATCH * TLEN * TLEN];               // scores f32
__device__ __nv_bfloat16 g_Qhi[MTOT * DINT], g_Qlo[MTOT * DINT];
__device__ __nv_bfloat16 g_Khi[MTOT * DINT], g_Klo[MTOT * DINT];
__device__ __nv_bfloat16 g_Vhi[MTOT * DINT], g_Vlo[MTOT * DINT];
__device__ __nv_bfloat16 g_Phi[BATCH * TLEN * TLEN], g_Plo[BATCH * TLEN * TLEN];
__device__ __nv_bfloat16 g_Xhi[MTOT * DMODEL], g_Xlo[MTOT * DMODEL];
__device__ __nv_bfloat16 g_Whi[3 * DINT * DMODEL], g_Wlo[3 * DINT * DMODEL];
__device__ float g_invfreq[HALFD];

// ---------------------------------------------------------------------------
// Helpers
// ---------------------------------------------------------------------------
__device__ __forceinline__ unsigned smem_u32(const void* p) {
    return (unsigned)__cvta_generic_to_shared(p);
}
__device__ __forceinline__ void cp16(unsigned dst, const void* src) {
    asm volatile("cp.async.cg.shared.global [%0], [%1], 16;" :: "r"(dst), "l"(src));
}
__device__ __forceinline__ void cp_commit() {
    asm volatile("cp.async.commit_group;");
}
template <int N>
__device__ __forceinline__ void cp_wait() {
    asm volatile("cp.async.wait_group %0;" :: "n"(N));
}
__device__ __forceinline__ void ldm_x4(unsigned a, unsigned& r0, unsigned& r1,
                                       unsigned& r2, unsigned& r3) {
    asm volatile("ldmatrix.sync.aligned.m8n8.x4.shared.b16 {%0,%1,%2,%3}, [%4];"
                 : "=r"(r0), "=r"(r1), "=r"(r2), "=r"(r3) : "r"(a));
}
__device__ __forceinline__ void ldm_x4_t(unsigned a, unsigned& r0, unsigned& r1,
                                         unsigned& r2, unsigned& r3) {
    asm volatile("ldmatrix.sync.aligned.m8n8.x4.trans.shared.b16 {%0,%1,%2,%3}, [%4];"
                 : "=r"(r0), "=r"(r1), "=r"(r2), "=r"(r3) : "r"(a));
}
__device__ __forceinline__ void mma16816(float* c, const unsigned* a,
                                         unsigned b0, unsigned b1) {
    asm volatile("mma.sync.aligned.m16n8k16.row.col.f32.bf16.bf16.f32 "
                 "{%0,%1,%2,%3}, {%4,%5,%6,%7}, {%8,%9}, {%0,%1,%2,%3};"
                 : "+f"(c[0]), "+f"(c[1]), "+f"(c[2]), "+f"(c[3])
                 : "r"(a[0]), "r"(a[1]), "r"(a[2]), "r"(a[3]), "r"(b0), "r"(b1));
}
__device__ __forceinline__ void split2(float x, float y,
                                       __nv_bfloat162& h, __nv_bfloat162& l) {
    h.x = __float2bfloat16_rn(x);
    h.y = __float2bfloat16_rn(y);
    l.x = __float2bfloat16_rn(x - __bfloat162float(h.x));
    l.y = __float2bfloat16_rn(y - __bfloat162float(h.y));
}

// smem stage layout (bytes): Ahi[128*40] Alo[128*40] Bhi[64*40] Blo[64*40]
#define STAGE_BYTES 30720
#define SA_LO (128 * 40)
#define SB_HI (2 * 128 * 40)
#define SB_LO (2 * 128 * 40 + 64 * 40)
// PV stage: Phi[128*40] Plo[128*40] Vhi[32*72] Vlo[32*72]
#define SV_HI (2 * 128 * 40)
#define SV_LO (2 * 128 * 40 + 32 * 72)

// ---------------------------------------------------------------------------
// TN loaders / compute (A 128xk, B 64xk, both k-contiguous, pre-split bf16)
// ---------------------------------------------------------------------------
__device__ __forceinline__ void load_tn(char* st,
    const __nv_bfloat16* Ahi, const __nv_bfloat16* Alo, int strideA,
    const __nv_bfloat16* Bhi, const __nv_bfloat16* Blo, int strideB, int tid)
{
    __nv_bfloat16* s = (__nv_bfloat16*)st;
    const int r   = tid >> 1;           // 0..127
    const int ch0 = (tid & 1) * 2;      // chunk 0/2
    #pragma unroll
    for (int j = 0; j < 2; ++j) {
        int ch = ch0 + j;
        cp16(smem_u32(&s[r * 40 + ch * 8]),         Ahi + (size_t)r * strideA + ch * 8);
        cp16(smem_u32(&s[SA_LO + r * 40 + ch * 8]), Alo + (size_t)r * strideA + ch * 8);
    }
    const int rb = tid >> 2, chb = tid & 3;   // 64 x 4
    cp16(smem_u32(&s[SB_HI + rb * 40 + chb * 8]), Bhi + (size_t)rb * strideB + chb * 8);
    cp16(smem_u32(&s[SB_LO + rb * 40 + chb * 8]), Blo + (size_t)rb * strideB + chb * 8);
}

// Pass-major MMA ordering: all 8 independent fragments per pass, so the
// same-accumulator dependent chain (hh -> hl -> lh) has reuse distance 8.
__device__ __forceinline__ void compute_tn(const char* st, int lane, int wm, int wn,
                                           float acc[2][4][4])
{
    const __nv_bfloat16* sAhi = (const __nv_bfloat16*)st;
    const __nv_bfloat16* sAlo = sAhi + SA_LO;
    const __nv_bfloat16* sBhi = sAhi + SB_HI;
    const __nv_bfloat16* sBlo = sAhi + SB_LO;
    const int lr  = (lane & 7) + ((lane >> 3) & 1) * 8;
    const int lc8 = (lane >> 4) * 8;
    #pragma unroll
    for (int ks = 0; ks < 2; ++ks) {
        const int kb = ks * 16 + lc8;
        unsigned ah[2][4], al[2][4], bh[2][4], bl[2][4];
        #pragma unroll
        for (int mf = 0; mf < 2; ++mf) {
            int row = wm * 32 + mf * 16 + lr;
            ldm_x4(smem_u32(&sAhi[row * 40 + kb]), ah[mf][0], ah[mf][1], ah[mf][2], ah[mf][3]);
            ldm_x4(smem_u32(&sAlo[row * 40 + kb]), al[mf][0], al[mf][1], al[mf][2], al[mf][3]);
        }
        #pragma unroll
        for (int g = 0; g < 2; ++g) {
            int row = wn * 32 + g * 16 + lr;
            ldm_x4(smem_u32(&sBhi[row * 40 + kb]), bh[g][0], bh[g][1], bh[g][2], bh[g][3]);
            ldm_x4(smem_u32(&sBlo[row * 40 + kb]), bl[g][0], bl[g][1], bl[g][2], bl[g][3]);
        }
        #pragma unroll
        for (int mf = 0; mf < 2; ++mf)
            #pragma unroll
            for (int nf = 0; nf < 4; ++nf) {
                int g = nf >> 1, sdx = nf & 1;
                mma16816(acc[mf][nf], ah[mf], bh[g][sdx], bh[g][sdx + 2]);
            }
        #pragma unroll
        for (int mf = 0; mf < 2; ++mf)
            #pragma unroll
            for (int nf = 0; nf < 4; ++nf) {
                int g = nf >> 1, sdx = nf & 1;
                mma16816(acc[mf][nf], ah[mf], bl[g][sdx], bl[g][sdx + 2]);
            }
        #pragma unroll
        for (int mf = 0; mf < 2; ++mf)
            #pragma unroll
            for (int nf = 0; nf < 4; ++nf) {
                int g = nf >> 1, sdx = nf & 1;
                mma16816(acc[mf][nf], al[mf], bh[g][sdx], bh[g][sdx + 2]);
            }
    }
}

__device__ __forceinline__ void pipe_tn(
    const __nv_bfloat16* Ahi, const __nv_bfloat16* Alo, int strideA,
    const __nv_bfloat16* Bhi, const __nv_bfloat16* Blo, int strideB,
    int nIter, char* sm, float acc[2][4][4])
{
    const int tid = threadIdx.x, lane = tid & 31, warp = tid >> 5;
    const int wm = warp & 3, wn = warp >> 2;
    load_tn(sm, Ahi, Alo, strideA, Bhi, Blo, strideB, tid);
    cp_commit();
    for (int i = 0; i < nIter; ++i) {
        if (i + 1 < nIter) {
            load_tn(sm + ((i + 1) & 1) * STAGE_BYTES,
                    Ahi + (i + 1) * 32, Alo + (i + 1) * 32, strideA,
                    Bhi + (i + 1) * 32, Blo + (i + 1) * 32, strideB, tid);
            cp_commit();
            cp_wait<1>();
        } else {
            cp_wait<0>();
        }
        __syncthreads();
        compute_tn(sm + (i & 1) * STAGE_BYTES, lane, wm, wn, acc);
        __syncthreads();
    }
}

// ---------------------------------------------------------------------------
// init + splits
// ---------------------------------------------------------------------------
__global__ void init_freq_kernel() {
    int p = blockIdx.x * blockDim.x + threadIdx.x;
    if (p < HALFD) {
        double e = exp(-((double)(2 * p) / (double)DINT) * 9.210340371976184);
        g_invfreq[p] = (float)e;
    }
}

__global__ __launch_bounds__(256)
void split_kernel(const float2* __restrict__ src, __nv_bfloat162* __restrict__ hi,
                  __nv_bfloat162* __restrict__ lo, int n2) {
    int i = blockIdx.x * blockDim.x + threadIdx.x;
    if (i < n2) {
        float2 v = src[i];
        __nv_bfloat162 h, l;
        split2(v.x, v.y, h, l);
        hi[i] = h; lo[i] = l;
    }
}

// ---------------------------------------------------------------------------
// Kernel 1: QKV GEMM (pipelined). M=8192, N=3072, K=1024.
// ---------------------------------------------------------------------------
__global__ __launch_bounds__(256)
void qkv_gemm_pipe() {
    extern __shared__ char sm[];
    const int m0 = blockIdx.y * 128, n0 = blockIdx.x * 64;
    float acc[2][4][4] = {};
    pipe_tn(g_Xhi + (size_t)m0 * DMODEL, g_Xlo + (size_t)m0 * DMODEL, DMODEL,
            g_Whi + (size_t)n0 * DMODEL, g_Wlo + (size_t)n0 * DMODEL, DMODEL,
            DMODEL / 32, sm, acc);

    const int tid = threadIdx.x, lane = tid & 31, warp = tid >> 5;
    const int wm = warp & 3, wn = warp >> 2;
    if (n0 < 2 * DINT) {
        float* dst = (n0 < DINT) ? g_Q : g_K;
        int nb = (n0 < DINT) ? n0 : n0 - DINT;
        #pragma unroll
        for (int mf = 0; mf < 2; ++mf)
            #pragma unroll
            for (int nf = 0; nf < 4; ++nf) {
                int r = m0 + wm * 32 + mf * 16 + (lane >> 2);
                int c = nb + wn * 32 + nf * 8 + (lane & 3) * 2;
                *(float2*)&dst[(size_t)r * DINT + c]       = make_float2(acc[mf][nf][0], acc[mf][nf][1]);
                *(float2*)&dst[(size_t)(r + 8) * DINT + c] = make_float2(acc[mf][nf][2], acc[mf][nf][3]);
            }
    } else {
        int nb = n0 - 2 * DINT;
        #pragma unroll
        for (int mf = 0; mf < 2; ++mf)
            #pragma unroll
            for (int nf = 0; nf < 4; ++nf) {
                int r = m0 + wm * 32 + mf * 16 + (lane >> 2);
                int c = nb + wn * 32 + nf * 8 + (lane & 3) * 2;
                __nv_bfloat162 h, l;
                split2(acc[mf][nf][0], acc[mf][nf][1], h, l);
                *(__nv_bfloat162*)&g_Vhi[(size_t)r * DINT + c] = h;
                *(__nv_bfloat162*)&g_Vlo[(size_t)r * DINT + c] = l;
                split2(acc[mf][nf][2], acc[mf][nf][3], h, l);
                *(__nv_bfloat162*)&g_Vhi[(size_t)(r + 8) * DINT + c] = h;
                *(__nv_bfloat162*)&g_Vlo[(size_t)(r + 8) * DINT + c] = l;
            }
    }
}

// ---------------------------------------------------------------------------
// Kernel 2: RoPE + L2 norm + scale; writes pre-split bf16 Q,K.
// ---------------------------------------------------------------------------
__global__ __launch_bounds__(256)
void rope_norm_kernel(const float* __restrict__ sqk, float sqk_mul) {
    const int token = blockIdx.x;
    const int tpos = token & (TLEN - 1);
    const bool isQ = (blockIdx.y == 0);
    const float* row = (isQ ? g_Q : g_K) + (size_t)token * DINT;
    __nv_bfloat16* outhi = (isQ ? g_Qhi : g_Khi) + (size_t)token * DINT;
    __nv_bfloat16* outlo = (isQ ? g_Qlo : g_Klo) + (size_t)token * DINT;

    const int tid = threadIdx.x;
    float na[2], nb[2];
    float ss = 0.0f;
    #pragma unroll
    for (int h = 0; h < 2; ++h) {
        int p = tid + h * 256;
        float a = row[p];
        float b = row[p + HALFD];
        float ang = (float)tpos * g_invfreq[p];
        float s, c;
        sincosf(ang, &s, &c);
        na[h] = a * c - b * s;
        nb[h] = b * c + a * s;
        ss += na[h] * na[h] + nb[h] * nb[h];
    }
    __shared__ float warp_red[8];
    #pragma unroll
    for (int o = 16; o > 0; o >>= 1) ss += __shfl_xor_sync(0xffffffffu, ss, o);
    if ((tid & 31) == 0) warp_red[tid >> 5] = ss;
    __syncthreads();
    __shared__ float total_sh;
    if (tid == 0) {
        float t = 0.0f;
        #pragma unroll
        for (int w = 0; w < 8; ++w) t += warp_red[w];
        total_sh = t;
    }
    __syncthreads();
    float rnorm = 1.0f / sqrtf(total_sh);
    #pragma unroll
    for (int h = 0; h < 2; ++h) {
        int p = tid + h * 256;
        float va = na[h] * rnorm * (sqk[p] * sqk_mul);
        float vb = nb[h] * rnorm * (sqk[p + HALFD] * sqk_mul);
        __nv_bfloat16 ha = __float2bfloat16_rn(va);
        __nv_bfloat16 hb = __float2bfloat16_rn(vb);
        outhi[p]         = ha;
        outlo[p]         = __float2bfloat16_rn(va - __bfloat162float(ha));
        outhi[p + HALFD] = hb;
        outlo[p + HALFD] = __float2bfloat16_rn(vb - __bfloat162float(hb));
    }
}

// ---------------------------------------------------------------------------
// Kernel 3: scores S = scale * Q K^T (pipelined, causal block skip)
// ---------------------------------------------------------------------------
__global__ __launch_bounds__(256)
void qk_gemm_pipe(float scale) {
    const int b  = blockIdx.z;
    const int q0 = blockIdx.y * 128;
    const int k0n = blockIdx.x * 64;
    if (k0n >= q0 + 128) return;
    extern __shared__ char sm[];

    float acc[2][4][4] = {};
    pipe_tn(g_Qhi + ((size_t)b * TLEN + q0) * DINT, g_Qlo + ((size_t)b * TLEN + q0) * DINT, DINT,
            g_Khi + ((size_t)b * TLEN + k0n) * DINT, g_Klo + ((size_t)b * TLEN + k0n) * DINT, DINT,
            DINT / 32, sm, acc);

    float* S = g_S + (size_t)b * TLEN * TLEN;
    const int tid = threadIdx.x, lane = tid & 31, warp = tid >> 5;
    const int wm = warp & 3, wn = warp >> 2;
    #pragma unroll
    for (int mf = 0; mf < 2; ++mf)
        #pragma unroll
        for (int nf = 0; nf < 4; ++nf) {
            int q = q0 + wm * 32 + mf * 16 + (lane >> 2);
            int c = k0n + wn * 32 + nf * 8 + (lane & 3) * 2;
            *(float2*)&S[(size_t)q * TLEN + c] =
                make_float2(acc[mf][nf][0] * scale, acc[mf][nf][1] * scale);
            *(float2*)&S[(size_t)(q + 8) * TLEN + c] =
                make_float2(acc[mf][nf][2] * scale, acc[mf][nf][3] * scale);
        }
}

// ---------------------------------------------------------------------------
// Kernel 4: causal softmax; writes pre-split bf16 P (exact zeros above diag).
// ---------------------------------------------------------------------------
__global__ __launch_bounds__(256)
void softmax_kernel() {
    const int q = blockIdx.x;
    const int b = blockIdx.y;
    const float* row = g_S + ((size_t)b * TLEN + q) * TLEN;
    __nv_bfloat16* phi = g_Phi + ((size_t)b * TLEN + q) * TLEN;
    __nv_bfloat16* plo = g_Plo + ((size_t)b * TLEN + q) * TLEN;
    const int tid = threadIdx.x;

    float vals[8];
    float m = -INFINITY;
    #pragma unroll
    for (int i = 0; i < 8; ++i) {
        int k = i * 256 + tid;
        float v = (k <= q) ? row[k] : -INFINITY;
        vals[i] = v;
        m = fmaxf(m, v);
    }
    __shared__ float warp_red[8];
    __shared__ float bcast;
    #pragma unroll
    for (int o = 16; o > 0; o >>= 1) m = fmaxf(m, __shfl_xor_sync(0xffffffffu, m, o));
    if ((tid & 31) == 0) warp_red[tid >> 5] = m;
    __syncthreads();
    if (tid == 0) {
        float t = warp_red[0];
        #pragma unroll
        for (int w = 1; w < 8; ++w) t = fmaxf(t, warp_red[w]);
        bcast = t;
    }
    __syncthreads();
    const float rowmax = bcast;

    float sum = 0.0f;
    #pragma unroll
    for (int i = 0; i < 8; ++i) {
        int k = i * 256 + tid;
        float e = (k <= q) ? expf(vals[i] - rowmax) : 0.0f;
        vals[i] = e;
        sum += e;
    }
    #pragma unroll
    for (int o = 16; o > 0; o >>= 1) sum += __shfl_xor_sync(0xffffffffu, sum, o);
    if ((tid & 31) == 0) warp_red[tid >> 5] = sum;
    __syncthreads();
    if (tid == 0) {
        float t = 0.0f;
        #pragma unroll
        for (int w = 0; w < 8; ++w) t += warp_red[w];
        bcast = t;
    }
    __syncthreads();
    const float inv = 1.0f / bcast;
    #pragma unroll
    for (int i = 0; i < 8; ++i) {
        int k = i * 256 + tid;
        float p = vals[i] * inv;
        __nv_bfloat16 h = __float2bfloat16_rn(p);
        phi[k] = h;
        plo[k] = __float2bfloat16_rn(p - __bfloat162float(h));
    }
}

// ---------------------------------------------------------------------------
// Kernel 5: O = P V (pipelined). P k-contig (non-trans A); V n-contig (trans B).
// ---------------------------------------------------------------------------
__device__ __forceinline__ void load_pv(char* st,
    const __nv_bfloat16* Phi, const __nv_bfloat16* Plo,
    const __nv_bfloat16* Vhi, const __nv_bfloat16* Vlo, int tid)
{
    __nv_bfloat16* s = (__nv_bfloat16*)st;
    const int r   = tid >> 1;
    const int ch0 = (tid & 1) * 2;
    #pragma unroll
    for (int j = 0; j < 2; ++j) {
        int ch = ch0 + j;
        cp16(smem_u32(&s[r * 40 + ch * 8]),         Phi + (size_t)r * TLEN + ch * 8);
        cp16(smem_u32(&s[SA_LO + r * 40 + ch * 8]), Plo + (size_t)r * TLEN + ch * 8);
    }
    const int rv = tid >> 3, chv = tid & 7;
    cp16(smem_u32(&s[SV_HI + rv * 72 + chv * 8]), Vhi + (size_t)rv * DINT + chv * 8);
    cp16(smem_u32(&s[SV_LO + rv * 72 + chv * 8]), Vlo + (size_t)rv * DINT + chv * 8);
}

__global__ __launch_bounds__(256)
void pv_gemm_pipe(float* __restrict__ out) {
    const int b  = blockIdx.z;
    const int q0 = blockIdx.y * 128;
    const int n0 = blockIdx.x * 64;
    extern __shared__ char sm[];

    const __nv_bfloat16* Phi = g_Phi + ((size_t)b * TLEN + q0) * TLEN;
    const __nv_bfloat16* Plo = g_Plo + ((size_t)b * TLEN + q0) * TLEN;
    const __nv_bfloat16* Vhi = g_Vhi + (size_t)b * TLEN * DINT + n0;
    const __nv_bfloat16* Vlo = g_Vlo + (size_t)b * TLEN * DINT + n0;
    const int nIter = (q0 + 128) / 32;

    const int tid = threadIdx.x, lane = tid & 31, warp = tid >> 5;
    const int wm = warp & 3, wn = warp >> 2;
    const int lrA = (lane & 7) + ((lane >> 3) & 1) * 8;
    const int lcA8 = (lane >> 4) * 8;
    const int lrV = (lane & 7) + ((lane >> 4) & 1) * 8;
    const int lcV8 = ((lane >> 3) & 1) * 8;

    float acc[2][4][4] = {};

    load_pv(sm, Phi, Plo, Vhi, Vlo, tid);
    cp_commit();
    for (int i = 0; i < nIter; ++i) {
        if (i + 1 < nIter) {
            load_pv(sm + ((i + 1) & 1) * STAGE_BYTES,
                    Phi + (i + 1) * 32, Plo + (i + 1) * 32,
                    Vhi + (size_t)(i + 1) * 32 * DINT, Vlo + (size_t)(i + 1) * 32 * DINT, tid);
            cp_commit();
            cp_wait<1>();
        } else {
            cp_wait<0>();
        }
        __syncthreads();
        {
            const char* st = sm + (i & 1) * STAGE_BYTES;
            const __nv_bfloat16* sPhi = (const __nv_bfloat16*)st;
            const __nv_bfloat16* sPlo = sPhi + SA_LO;
            const __nv_bfloat16* sVhi = sPhi + SV_HI;
            const __nv_bfloat16* sVlo = sPhi + SV_LO;
            #pragma unroll
            for (int ks = 0; ks < 2; ++ks) {
                const int kbA = ks * 16 + lcA8;
                const int kbV = ks * 16 + lrV;
                unsigned ah[2][4], al[2][4], bh[2][4], bl[2][4];
                #pragma unroll
                for (int mf = 0; mf < 2; ++mf) {
                    int rrow = wm * 32 + mf * 16 + lrA;
                    ldm_x4(smem_u32(&sPhi[rrow * 40 + kbA]), ah[mf][0], ah[mf][1], ah[mf][2], ah[mf][3]);
                    ldm_x4(smem_u32(&sPlo[rrow * 40 + kbA]), al[mf][0], al[mf][1], al[mf][2], al[mf][3]);
                }
                #pragma unroll
                for (int g = 0; g < 2; ++g) {
                    int col = wn * 32 + g * 16 + lcV8;
                    ldm_x4_t(smem_u32(&sVhi[kbV * 72 + col]), bh[g][0], bh[g][1], bh[g][2], bh[g][3]);
                    ldm_x4_t(smem_u32(&sVlo[kbV * 72 + col]), bl[g][0], bl[g][1], bl[g][2], bl[g][3]);
                }
                #pragma unroll
                for (int mf = 0; mf < 2; ++mf)
                    #pragma unroll
                    for (int nf = 0; nf < 4; ++nf) {
                        int g = nf >> 1, sdx = nf & 1;
                        mma16816(acc[mf][nf], ah[mf], bh[g][sdx], bh[g][sdx + 2]);
                    }
                #pragma unroll
                for (int mf = 0; mf < 2; ++mf)
                    #pragma unroll
                    for (int nf = 0; nf < 4; ++nf) {
                        int g = nf >> 1, sdx = nf & 1;
                        mma16816(acc[mf][nf], ah[mf], bl[g][sdx], bl[g][sdx + 2]);
                    }
                #pragma unroll
                for (int mf = 0; mf < 2; ++mf)
                    #pragma unroll
                    for (int nf = 0; nf < 4; ++nf) {
                        int g = nf >> 1, sdx = nf & 1;
                        mma16816(acc[mf][nf], al[mf], bh[g][sdx], bh[g][sdx + 2]);
                    }
            }
        }
        __syncthreads();
    }

    #pragma unroll
    for (int mf = 0; mf < 2; ++mf)
        #pragma unroll
        for (int nf = 0; nf < 4; ++nf) {
            int q = q0 + wm * 32 + mf * 16 + (lane >> 2);
            int c = n0 + wn * 32 + nf * 8 + (lane & 3) * 2;
            *(float2*)&out[((size_t)(b * TLEN + q)) * DINT + c] =
                make_float2(acc[mf][nf][0], acc[mf][nf][1]);
            *(float2*)&out[((size_t)(b * TLEN + q + 8)) * DINT + c] =
                make_float2(acc[mf][nf][2], acc[mf][nf][3]);
        }
}

// ---------------------------------------------------------------------------
// Launch
// ---------------------------------------------------------------------------
extern "C" void kernel_launch(void* const* d_in, const int* in_sizes, int n_in,
                              void* d_out, int out_size) {
    (void)n_in; (void)out_size; (void)in_sizes;
    const float* input_vecs = (const float*)d_in[0];
    const float* qkv_w      = (const float*)d_in[1];
    const float* sqk        = (const float*)d_in[2];
    float* out              = (float*)d_out;

    const float sqk_mul = sqrtf((float)DMODEL);
    const float scale   = sqrtf((float)DMODEL);
    const int DSMEM = 2 * STAGE_BYTES;   // 61440

    cudaFuncSetAttribute(qkv_gemm_pipe, cudaFuncAttributeMaxDynamicSharedMemorySize, DSMEM);
    cudaFuncSetAttribute(qk_gemm_pipe,  cudaFuncAttributeMaxDynamicSharedMemorySize, DSMEM);
    cudaFuncSetAttribute(pv_gemm_pipe,  cudaFuncAttributeMaxDynamicSharedMemorySize, DSMEM);

    init_freq_kernel<<<2, 256>>>();

    __nv_bfloat162 *xhi, *xlo, *whi, *wlo;
    cudaGetSymbolAddress((void**)&xhi, g_Xhi);
    cudaGetSymbolAddress((void**)&xlo, g_Xlo);
    cudaGetSymbolAddress((void**)&whi, g_Whi);
    cudaGetSymbolAddress((void**)&wlo, g_Wlo);
    int nx2 = MTOT * DMODEL / 2, nw2 = 3 * DINT * DMODEL / 2;
    split_kernel<<<(nx2 + 255) / 256, 256>>>((const float2*)input_vecs, xhi, xlo, nx2);
    split_kernel<<<(nw2 + 255) / 256, 256>>>((const float2*)qkv_w, whi, wlo, nw2);

    qkv_gemm_pipe<<<dim3(3 * DINT / 64, MTOT / 128), 256, DSMEM>>>();

    rope_norm_kernel<<<dim3(MTOT, 2), 256>>>(sqk, sqk_mul);

    qk_gemm_pipe<<<dim3(TLEN / 64, TLEN / 128, BATCH), 256, DSMEM>>>(scale);

    softmax_kernel<<<dim3(TLEN, BATCH), 256>>>();

    pv_gemm_pipe<<<dim3(DINT / 64, TLEN / 128, BATCH), 256, DSMEM>>>(out);
}

// round 8
// speedup vs baseline: 2.4206x; 2.3547x over previous
#include <cuda_runtime.h>
#include <cuda_fp16.h>
#include <math.h>

#define BATCH 4
#define TLEN  2048
#define DMODEL 1024
#define DINT   1024
#define MTOT  (BATCH * TLEN)     // 8192
#define HALFD (DINT / 2)         // 512

// ---------------------------------------------------------------------------
// Scratch (device globals; no allocation allowed)
// ---------------------------------------------------------------------------
__device__ float g_Q[MTOT * DINT];                 // f32 (rope input)
__device__ float g_K[MTOT * DINT];
__device__ float g_S[BATCH * TLEN * TLEN];         // scores f32
__device__ __half g_Qh[MTOT * DINT];               // post-rope fp16
__device__ __half g_Kh[MTOT * DINT];
__device__ __half g_Vh[MTOT * DINT];
__device__ __half g_Ph[BATCH * TLEN * TLEN];       // probs fp16
__device__ __half g_Xh[MTOT * DMODEL];
__device__ __half g_Wh[3 * DINT * DMODEL];
__device__ float g_invfreq[HALFD];

// ---------------------------------------------------------------------------
// Helpers
// ---------------------------------------------------------------------------
__device__ __forceinline__ unsigned smem_u32(const void* p) {
    return (unsigned)__cvta_generic_to_shared(p);
}
__device__ __forceinline__ void cp16(unsigned dst, const void* src) {
    asm volatile("cp.async.cg.shared.global [%0], [%1], 16;" :: "r"(dst), "l"(src));
}
__device__ __forceinline__ void cp_commit() {
    asm volatile("cp.async.commit_group;");
}
template <int N>
__device__ __forceinline__ void cp_wait() {
    asm volatile("cp.async.wait_group %0;" :: "n"(N));
}
__device__ __forceinline__ void ldm_x4(unsigned a, unsigned& r0, unsigned& r1,
                                       unsigned& r2, unsigned& r3) {
    asm volatile("ldmatrix.sync.aligned.m8n8.x4.shared.b16 {%0,%1,%2,%3}, [%4];"
                 : "=r"(r0), "=r"(r1), "=r"(r2), "=r"(r3) : "r"(a));
}
__device__ __forceinline__ void ldm_x4_t(unsigned a, unsigned& r0, unsigned& r1,
                                         unsigned& r2, unsigned& r3) {
    asm volatile("ldmatrix.sync.aligned.m8n8.x4.trans.shared.b16 {%0,%1,%2,%3}, [%4];"
                 : "=r"(r0), "=r"(r1), "=r"(r2), "=r"(r3) : "r"(a));
}
__device__ __forceinline__ void mma16816(float* c, const unsigned* a,
                                         unsigned b0, unsigned b1) {
    asm volatile("mma.sync.aligned.m16n8k16.row.col.f32.f16.f16.f32 "
                 "{%0,%1,%2,%3}, {%4,%5,%6,%7}, {%8,%9}, {%0,%1,%2,%3};"
                 : "+f"(c[0]), "+f"(c[1]), "+f"(c[2]), "+f"(c[3])
                 : "r"(a[0]), "r"(a[1]), "r"(a[2]), "r"(a[3]), "r"(b0), "r"(b1));
}

// Stage layouts (halfs): TN: A[128*40] B[64*40]; PV: P[128*40] V[32*72]
#define SB_OFF   (128 * 40)                   // half offset of B within a stage
#define STG_TN   ((128 * 40 + 64 * 40) * 2)   // 15360 B
#define STG_PV   ((128 * 40 + 32 * 72) * 2)   // 14848 B
#define NSTG 4

// ---------------------------------------------------------------------------
// TN loader / compute (A 128xk, B 64xk, both k-contiguous fp16)
// ---------------------------------------------------------------------------
__device__ __forceinline__ void load_tn(char* st,
    const __half* A, int strideA, const __half* B, int strideB, int tid)
{
    __half* s = (__half*)st;
    #pragma unroll
    for (int j = 0; j < 2; ++j) {               // A: 128 rows x 4 chunks(16B)
        int idx = j * 256 + tid;
        int r = idx >> 2, c = idx & 3;
        cp16(smem_u32(&s[r * 40 + c * 8]), A + (size_t)r * strideA + c * 8);
    }
    {                                           // B: 64 rows x 4 chunks
        int r = tid >> 2, c = tid & 3;
        cp16(smem_u32(&s[SB_OFF + r * 40 + c * 8]), B + (size_t)r * strideB + c * 8);
    }
}

__device__ __forceinline__ void compute_tn(const char* st, int lane, int wm, int wn,
                                           float acc[2][4][4])
{
    const __half* sA = (const __half*)st;
    const __half* sB = sA + SB_OFF;
    const int lr  = (lane & 7) + ((lane >> 3) & 1) * 8;
    const int lc8 = (lane >> 4) * 8;
    #pragma unroll
    for (int ks = 0; ks < 2; ++ks) {
        const int kb = ks * 16 + lc8;
        unsigned a[2][4], b[2][4];
        #pragma unroll
        for (int mf = 0; mf < 2; ++mf) {
            int row = wm * 32 + mf * 16 + lr;
            ldm_x4(smem_u32(&sA[row * 40 + kb]), a[mf][0], a[mf][1], a[mf][2], a[mf][3]);
        }
        #pragma unroll
        for (int g = 0; g < 2; ++g) {
            int row = wn * 32 + g * 16 + lr;
            ldm_x4(smem_u32(&sB[row * 40 + kb]), b[g][0], b[g][1], b[g][2], b[g][3]);
        }
        #pragma unroll
        for (int mf = 0; mf < 2; ++mf)
            #pragma unroll
            for (int nf = 0; nf < 4; ++nf) {
                int g = nf >> 1, sdx = nf & 1;
                mma16816(acc[mf][nf], a[mf], b[g][sdx], b[g][sdx + 2]);
            }
    }
}

__device__ __forceinline__ void pipe_tn(
    const __half* A, int strideA, const __half* B, int strideB,
    int nIter, char* sm, float acc[2][4][4])
{
    const int tid = threadIdx.x, lane = tid & 31, warp = tid >> 5;
    const int wm = warp & 3, wn = warp >> 2;
    #pragma unroll
    for (int j = 0; j < 3; ++j)
        if (j < nIter) {
            load_tn(sm + j * STG_TN, A + j * 32, strideA, B + j * 32, strideB, tid);
            cp_commit();
        }
    for (int i = 0; i < nIter; ++i) {
        if (i <= nIter - 3)      cp_wait<2>();
        else if (i == nIter - 2) cp_wait<1>();
        else                     cp_wait<0>();
        __syncthreads();
        if (i + 3 < nIter) {
            load_tn(sm + ((i + 3) & (NSTG - 1)) * STG_TN,
                    A + (i + 3) * 32, strideA, B + (i + 3) * 32, strideB, tid);
            cp_commit();
        }
        compute_tn(sm + (i & (NSTG - 1)) * STG_TN, lane, wm, wn, acc);
    }
    __syncthreads();
}

// ---------------------------------------------------------------------------
// init + fp16 conversion
// ---------------------------------------------------------------------------
__global__ void init_freq_kernel() {
    int p = blockIdx.x * blockDim.x + threadIdx.x;
    if (p < HALFD) {
        double e = exp(-((double)(2 * p) / (double)DINT) * 9.210340371976184);
        g_invfreq[p] = (float)e;
    }
}

__global__ __launch_bounds__(256)
void cvt_kernel(const float2* __restrict__ src, __half2* __restrict__ dst, int n2) {
    int i = blockIdx.x * blockDim.x + threadIdx.x;
    if (i < n2) {
        float2 v = src[i];
        dst[i] = __float22half2_rn(v);
    }
}

// ---------------------------------------------------------------------------
// Kernel 1: QKV GEMM. M=8192, N=3072, K=1024. Q,K -> f32; V -> fp16.
// ---------------------------------------------------------------------------
__global__ __launch_bounds__(256)
void qkv_gemm_pipe() {
    extern __shared__ char sm[];
    const int m0 = blockIdx.y * 128, n0 = blockIdx.x * 64;
    float acc[2][4][4] = {};
    pipe_tn(g_Xh + (size_t)m0 * DMODEL, DMODEL,
            g_Wh + (size_t)n0 * DMODEL, DMODEL, DMODEL / 32, sm, acc);

    const int tid = threadIdx.x, lane = tid & 31, warp = tid >> 5;
    const int wm = warp & 3, wn = warp >> 2;
    if (n0 < 2 * DINT) {
        float* dst = (n0 < DINT) ? g_Q : g_K;
        int nb = (n0 < DINT) ? n0 : n0 - DINT;
        #pragma unroll
        for (int mf = 0; mf < 2; ++mf)
            #pragma unroll
            for (int nf = 0; nf < 4; ++nf) {
                int r = m0 + wm * 32 + mf * 16 + (lane >> 2);
                int c = nb + wn * 32 + nf * 8 + (lane & 3) * 2;
                *(float2*)&dst[(size_t)r * DINT + c]       = make_float2(acc[mf][nf][0], acc[mf][nf][1]);
                *(float2*)&dst[(size_t)(r + 8) * DINT + c] = make_float2(acc[mf][nf][2], acc[mf][nf][3]);
            }
    } else {
        int nb = n0 - 2 * DINT;
        #pragma unroll
        for (int mf = 0; mf < 2; ++mf)
            #pragma unroll
            for (int nf = 0; nf < 4; ++nf) {
                int r = m0 + wm * 32 + mf * 16 + (lane >> 2);
                int c = nb + wn * 32 + nf * 8 + (lane & 3) * 2;
                *(__half2*)&g_Vh[(size_t)r * DINT + c] =
                    __float22half2_rn(make_float2(acc[mf][nf][0], acc[mf][nf][1]));
                *(__half2*)&g_Vh[(size_t)(r + 8) * DINT + c] =
                    __float22half2_rn(make_float2(acc[mf][nf][2], acc[mf][nf][3]));
            }
    }
}

// ---------------------------------------------------------------------------
// Kernel 2: RoPE + L2 norm + scale; writes fp16 Q,K.
// ---------------------------------------------------------------------------
__global__ __launch_bounds__(256)
void rope_norm_kernel(const float* __restrict__ sqk, float sqk_mul) {
    const int token = blockIdx.x;
    const int tpos = token & (TLEN - 1);
    const bool isQ = (blockIdx.y == 0);
    const float* row = (isQ ? g_Q : g_K) + (size_t)token * DINT;
    __half* outh = (isQ ? g_Qh : g_Kh) + (size_t)token * DINT;

    const int tid = threadIdx.x;
    float na[2], nb[2];
    float ss = 0.0f;
    #pragma unroll
    for (int h = 0; h < 2; ++h) {
        int p = tid + h * 256;
        float a = row[p];
        float b = row[p + HALFD];
        float ang = (float)tpos * g_invfreq[p];
        float s, c;
        sincosf(ang, &s, &c);
        na[h] = a * c - b * s;
        nb[h] = b * c + a * s;
        ss += na[h] * na[h] + nb[h] * nb[h];
    }
    __shared__ float warp_red[8];
    #pragma unroll
    for (int o = 16; o > 0; o >>= 1) ss += __shfl_xor_sync(0xffffffffu, ss, o);
    if ((tid & 31) == 0) warp_red[tid >> 5] = ss;
    __syncthreads();
    __shared__ float total_sh;
    if (tid == 0) {
        float t = 0.0f;
        #pragma unroll
        for (int w = 0; w < 8; ++w) t += warp_red[w];
        total_sh = t;
    }
    __syncthreads();
    float rnorm = 1.0f / sqrtf(total_sh);
    #pragma unroll
    for (int h = 0; h < 2; ++h) {
        int p = tid + h * 256;
        float va = na[h] * rnorm * (sqk[p] * sqk_mul);
        float vb = nb[h] * rnorm * (sqk[p + HALFD] * sqk_mul);
        outh[p]         = __float2half_rn(va);
        outh[p + HALFD] = __float2half_rn(vb);
    }
}

// ---------------------------------------------------------------------------
// Kernel 3: scores S = scale * Q K^T (causal block skip)
// ---------------------------------------------------------------------------
__global__ __launch_bounds__(256)
void qk_gemm_pipe(float scale) {
    const int b  = blockIdx.z;
    const int q0 = blockIdx.y * 128;
    const int k0n = blockIdx.x * 64;
    if (k0n >= q0 + 128) return;
    extern __shared__ char sm[];

    float acc[2][4][4] = {};
    pipe_tn(g_Qh + ((size_t)b * TLEN + q0) * DINT, DINT,
            g_Kh + ((size_t)b * TLEN + k0n) * DINT, DINT, DINT / 32, sm, acc);

    float* S = g_S + (size_t)b * TLEN * TLEN;
    const int tid = threadIdx.x, lane = tid & 31, warp = tid >> 5;
    const int wm = warp & 3, wn = warp >> 2;
    #pragma unroll
    for (int mf = 0; mf < 2; ++mf)
        #pragma unroll
        for (int nf = 0; nf < 4; ++nf) {
            int q = q0 + wm * 32 + mf * 16 + (lane >> 2);
            int c = k0n + wn * 32 + nf * 8 + (lane & 3) * 2;
            *(float2*)&S[(size_t)q * TLEN + c] =
                make_float2(acc[mf][nf][0] * scale, acc[mf][nf][1] * scale);
            *(float2*)&S[(size_t)(q + 8) * TLEN + c] =
                make_float2(acc[mf][nf][2] * scale, acc[mf][nf][3] * scale);
        }
}

// ---------------------------------------------------------------------------
// Kernel 4: causal softmax; writes fp16 P (exact zeros above diagonal).
// ---------------------------------------------------------------------------
__global__ __launch_bounds__(256)
void softmax_kernel() {
    const int q = blockIdx.x;
    const int b = blockIdx.y;
    const float* row = g_S + ((size_t)b * TLEN + q) * TLEN;
    __half* ph = g_Ph + ((size_t)b * TLEN + q) * TLEN;
    const int tid = threadIdx.x;

    float vals[8];
    float m = -INFINITY;
    #pragma unroll
    for (int i = 0; i < 8; ++i) {
        int k = i * 256 + tid;
        float v = (k <= q) ? row[k] : -INFINITY;
        vals[i] = v;
        m = fmaxf(m, v);
    }
    __shared__ float warp_red[8];
    __shared__ float bcast;
    #pragma unroll
    for (int o = 16; o > 0; o >>= 1) m = fmaxf(m, __shfl_xor_sync(0xffffffffu, m, o));
    if ((tid & 31) == 0) warp_red[tid >> 5] = m;
    __syncthreads();
    if (tid == 0) {
        float t = warp_red[0];
        #pragma unroll
        for (int w = 1; w < 8; ++w) t = fmaxf(t, warp_red[w]);
        bcast = t;
    }
    __syncthreads();
    const float rowmax = bcast;

    float sum = 0.0f;
    #pragma unroll
    for (int i = 0; i < 8; ++i) {
        int k = i * 256 + tid;
        float e = (k <= q) ? expf(vals[i] - rowmax) : 0.0f;
        vals[i] = e;
        sum += e;
    }
    #pragma unroll
    for (int o = 16; o > 0; o >>= 1) sum += __shfl_xor_sync(0xffffffffu, sum, o);
    if ((tid & 31) == 0) warp_red[tid >> 5] = sum;
    __syncthreads();
    if (tid == 0) {
        float t = 0.0f;
        #pragma unroll
        for (int w = 0; w < 8; ++w) t += warp_red[w];
        bcast = t;
    }
    __syncthreads();
    const float inv = 1.0f / bcast;
    #pragma unroll
    for (int i = 0; i < 8; ++i) {
        int k = i * 256 + tid;
        ph[k] = __float2half_rn(vals[i] * inv);
    }
}

// ---------------------------------------------------------------------------
// Kernel 5: O = P V.  P k-contig (non-trans A); V n-contig (trans B).
// ---------------------------------------------------------------------------
__device__ __forceinline__ void load_pv(char* st,
    const __half* P, const __half* V, int tid)
{
    __half* s = (__half*)st;
    #pragma unroll
    for (int j = 0; j < 2; ++j) {               // P: 128 x 32
        int idx = j * 256 + tid;
        int r = idx >> 2, c = idx & 3;
        cp16(smem_u32(&s[r * 40 + c * 8]), P + (size_t)r * TLEN + c * 8);
    }
    {                                           // V: 32 x 64
        int r = tid >> 3, c = tid & 7;
        cp16(smem_u32(&s[SB_OFF + r * 72 + c * 8]), V + (size_t)r * DINT + c * 8);
    }
}

__global__ __launch_bounds__(256)
void pv_gemm_pipe(float* __restrict__ out) {
    const int b  = blockIdx.z;
    const int q0 = blockIdx.y * 128;
    const int n0 = blockIdx.x * 64;
    extern __shared__ char sm[];

    const __half* P = g_Ph + ((size_t)b * TLEN + q0) * TLEN;
    const __half* V = g_Vh + (size_t)b * TLEN * DINT + n0;
    const int nIter = (q0 + 128) / 32;

    const int tid = threadIdx.x, lane = tid & 31, warp = tid >> 5;
    const int wm = warp & 3, wn = warp >> 2;
    const int lrA = (lane & 7) + ((lane >> 3) & 1) * 8;
    const int lcA8 = (lane >> 4) * 8;
    const int lrV = (lane & 7) + ((lane >> 4) & 1) * 8;
    const int lcV8 = ((lane >> 3) & 1) * 8;

    float acc[2][4][4] = {};

    #pragma unroll
    for (int j = 0; j < 3; ++j)
        if (j < nIter) {
            load_pv(sm + j * STG_PV, P + j * 32, V + (size_t)j * 32 * DINT, tid);
            cp_commit();
        }
    for (int i = 0; i < nIter; ++i) {
        if (i <= nIter - 3)      cp_wait<2>();
        else if (i == nIter - 2) cp_wait<1>();
        else                     cp_wait<0>();
        __syncthreads();
        if (i + 3 < nIter) {
            load_pv(sm + ((i + 3) & (NSTG - 1)) * STG_PV,
                    P + (i + 3) * 32, V + (size_t)(i + 3) * 32 * DINT, tid);
            cp_commit();
        }
        {
            const char* st = sm + (i & (NSTG - 1)) * STG_PV;
            const __half* sP = (const __half*)st;
            const __half* sV = sP + SB_OFF;
            #pragma unroll
            for (int ks = 0; ks < 2; ++ks) {
                const int kbA = ks * 16 + lcA8;
                const int kbV = ks * 16 + lrV;
                unsigned a[2][4], bv[2][4];
                #pragma unroll
                for (int mf = 0; mf < 2; ++mf) {
                    int rrow = wm * 32 + mf * 16 + lrA;
                    ldm_x4(smem_u32(&sP[rrow * 40 + kbA]), a[mf][0], a[mf][1], a[mf][2], a[mf][3]);
                }
                #pragma unroll
                for (int g = 0; g < 2; ++g) {
                    int col = wn * 32 + g * 16 + lcV8;
                    ldm_x4_t(smem_u32(&sV[kbV * 72 + col]), bv[g][0], bv[g][1], bv[g][2], bv[g][3]);
                }
                #pragma unroll
                for (int mf = 0; mf < 2; ++mf)
                    #pragma unroll
                    for (int nf = 0; nf < 4; ++nf) {
                        int g = nf >> 1, sdx = nf & 1;
                        mma16816(acc[mf][nf], a[mf], bv[g][sdx], bv[g][sdx + 2]);
                    }
            }
        }
    }

    #pragma unroll
    for (int mf = 0; mf < 2; ++mf)
        #pragma unroll
        for (int nf = 0; nf < 4; ++nf) {
            int q = q0 + wm * 32 + mf * 16 + (lane >> 2);
            int c = n0 + wn * 32 + nf * 8 + (lane & 3) * 2;
            *(float2*)&out[((size_t)(b * TLEN + q)) * DINT + c] =
                make_float2(acc[mf][nf][0], acc[mf][nf][1]);
            *(float2*)&out[((size_t)(b * TLEN + q + 8)) * DINT + c] =
                make_float2(acc[mf][nf][2], acc[mf][nf][3]);
        }
}

// ---------------------------------------------------------------------------
// Launch
// ---------------------------------------------------------------------------
extern "C" void kernel_launch(void* const* d_in, const int* in_sizes, int n_in,
                              void* d_out, int out_size) {
    (void)n_in; (void)out_size; (void)in_sizes;
    const float* input_vecs = (const float*)d_in[0];
    const float* qkv_w      = (const float*)d_in[1];
    const float* sqk        = (const float*)d_in[2];
    float* out              = (float*)d_out;

    const float sqk_mul = sqrtf((float)DMODEL);
    const float scale   = sqrtf((float)DMODEL);
    const int DSMEM_TN = NSTG * STG_TN;   // 61440
    const int DSMEM_PV = NSTG * STG_PV;   // 59392

    cudaFuncSetAttribute(qkv_gemm_pipe, cudaFuncAttributeMaxDynamicSharedMemorySize, DSMEM_TN);
    cudaFuncSetAttribute(qk_gemm_pipe,  cudaFuncAttributeMaxDynamicSharedMemorySize, DSMEM_TN);
    cudaFuncSetAttribute(pv_gemm_pipe,  cudaFuncAttributeMaxDynamicSharedMemorySize, DSMEM_PV);

    init_freq_kernel<<<2, 256>>>();

    __half2 *xh, *wh;
    cudaGetSymbolAddress((void**)&xh, g_Xh);
    cudaGetSymbolAddress((void**)&wh, g_Wh);
    int nx2 = MTOT * DMODEL / 2, nw2 = 3 * DINT * DMODEL / 2;
    cvt_kernel<<<(nx2 + 255) / 256, 256>>>((const float2*)input_vecs, xh, nx2);
    cvt_kernel<<<(nw2 + 255) / 256, 256>>>((const float2*)qkv_w, wh, nw2);

    qkv_gemm_pipe<<<dim3(3 * DINT / 64, MTOT / 128), 256, DSMEM_TN>>>();

    rope_norm_kernel<<<dim3(MTOT, 2), 256>>>(sqk, sqk_mul);

    qk_gemm_pipe<<<dim3(TLEN / 64, TLEN / 128, BATCH), 256, DSMEM_TN>>>(scale);

    softmax_kernel<<<dim3(TLEN, BATCH), 256>>>();

    pv_gemm_pipe<<<dim3(DINT / 64, TLEN / 128, BATCH), 256, DSMEM_PV>>>(out);
}

// round 10
// speedup vs baseline: 2.4612x; 1.0168x over previous
#include <cuda_runtime.h>
#include <cuda_fp16.h>
#include <math.h>

#define BATCH 4
#define TLEN  2048
#define DMODEL 1024
#define DINT   1024
#define MTOT  (BATCH * TLEN)     // 8192
#define HALFD (DINT / 2)         // 512

// ---------------------------------------------------------------------------
// Scratch (device globals; no allocation allowed)
// ---------------------------------------------------------------------------
__device__ float g_Q[MTOT * DINT];                 // f32 (rope input)
__device__ float g_K[MTOT * DINT];
__device__ float g_S[BATCH * TLEN * TLEN];         // scores f32
__device__ __half g_Qh[MTOT * DINT];               // post-rope fp16
__device__ __half g_Kh[MTOT * DINT];
__device__ __half g_Vh[MTOT * DINT];
__device__ __half g_Ph[BATCH * TLEN * TLEN];       // probs fp16
__device__ __half g_Xh[MTOT * DMODEL];
__device__ __half g_Wh[3 * DINT * DMODEL];
__device__ float g_invfreq[HALFD];

// ---------------------------------------------------------------------------
// Helpers
// ---------------------------------------------------------------------------
__device__ __forceinline__ unsigned smem_u32(const void* p) {
    return (unsigned)__cvta_generic_to_shared(p);
}
__device__ __forceinline__ void cp16(unsigned dst, const void* src) {
    asm volatile("cp.async.cg.shared.global [%0], [%1], 16;" :: "r"(dst), "l"(src));
}
__device__ __forceinline__ void cp_commit() {
    asm volatile("cp.async.commit_group;");
}
template <int N>
__device__ __forceinline__ void cp_wait() {
    asm volatile("cp.async.wait_group %0;" :: "n"(N));
}
__device__ __forceinline__ void ldm_x4(unsigned a, unsigned& r0, unsigned& r1,
                                       unsigned& r2, unsigned& r3) {
    asm volatile("ldmatrix.sync.aligned.m8n8.x4.shared.b16 {%0,%1,%2,%3}, [%4];"
                 : "=r"(r0), "=r"(r1), "=r"(r2), "=r"(r3) : "r"(a));
}
__device__ __forceinline__ void ldm_x4_t(unsigned a, unsigned& r0, unsigned& r1,
                                         unsigned& r2, unsigned& r3) {
    asm volatile("ldmatrix.sync.aligned.m8n8.x4.trans.shared.b16 {%0,%1,%2,%3}, [%4];"
                 : "=r"(r0), "=r"(r1), "=r"(r2), "=r"(r3) : "r"(a));
}
__device__ __forceinline__ void mma16816(float* c, const unsigned* a,
                                         unsigned b0, unsigned b1) {
    asm volatile("mma.sync.aligned.m16n8k16.row.col.f32.f16.f16.f32 "
                 "{%0,%1,%2,%3}, {%4,%5,%6,%7}, {%8,%9}, {%0,%1,%2,%3};"
                 : "+f"(c[0]), "+f"(c[1]), "+f"(c[2]), "+f"(c[3])
                 : "r"(a[0]), "r"(a[1]), "r"(a[2]), "r"(a[3]), "r"(b0), "r"(b1));
}

// CTA tile 128(M) x 128(N) x 32(K). 8 warps: wm in {0,1} (64 rows), wn in {0..3} (32 cols).
// Stage layouts (halfs): TN: A[128*40] B[128*40]; PV: P[128*40] V[32*136]
#define SB_OFF   (128 * 40)
#define STG_TN   ((128 * 40 + 128 * 40) * 2)   // 20480 B
#define STG_PV   ((128 * 40 + 32 * 136) * 2)   // 18944 B
#define NSTG 3

// ---------------------------------------------------------------------------
// TN loader / compute (A 128xk, B 128xk, both k-contiguous fp16)
// Each 32-half row = 4 x 16B chunks, loaded as 512 cp16 over 2 rounds.
// ---------------------------------------------------------------------------
__device__ __forceinline__ void load_tn(char* st,
    const __half* A, int strideA, const __half* B, int strideB, int tid)
{
    __half* s = (__half*)st;
    #pragma unroll
    for (int j = 0; j < 2; ++j) {   // A: 128 rows x 4 chunks(16B)
        int idx = j * 256 + tid;
        int r = idx >> 2, c = idx & 3;
        cp16(smem_u32(&s[r * 40 + c * 8]), A + (size_t)r * strideA + c * 8);
    }
    #pragma unroll
    for (int j = 0; j < 2; ++j) {   // B: 128 rows x 4 chunks(16B)
        int idx = j * 256 + tid;
        int r = idx >> 2, c = idx & 3;
        cp16(smem_u32(&s[SB_OFF + r * 40 + c * 8]), B + (size_t)r * strideB + c * 8);
    }
}

__device__ __forceinline__ void compute_tn(const char* st, int lane, int wm, int wn,
                                           float acc[4][4][4])
{
    const __half* sA = (const __half*)st;
    const __half* sB = sA + SB_OFF;
    const int lr  = (lane & 7) + ((lane >> 3) & 1) * 8;
    const int lc8 = (lane >> 4) * 8;
    #pragma unroll
    for (int ks = 0; ks < 2; ++ks) {
        const int kb = ks * 16 + lc8;
        unsigned a[4][4], b[2][4];
        #pragma unroll
        for (int mf = 0; mf < 4; ++mf) {
            int row = wm * 64 + mf * 16 + lr;
            ldm_x4(smem_u32(&sA[row * 40 + kb]), a[mf][0], a[mf][1], a[mf][2], a[mf][3]);
        }
        #pragma unroll
        for (int g = 0; g < 2; ++g) {
            int row = wn * 32 + g * 16 + lr;
            ldm_x4(smem_u32(&sB[row * 40 + kb]), b[g][0], b[g][1], b[g][2], b[g][3]);
        }
        #pragma unroll
        for (int mf = 0; mf < 4; ++mf)
            #pragma unroll
            for (int nf = 0; nf < 4; ++nf) {
                int g = nf >> 1, sdx = nf & 1;
                mma16816(acc[mf][nf], a[mf], b[g][sdx], b[g][sdx + 2]);
            }
    }
}

__device__ __forceinline__ void pipe_tn(
    const __half* A, int strideA, const __half* B, int strideB,
    int nIter, char* sm, float acc[4][4][4])
{
    const int tid = threadIdx.x, lane = tid & 31, warp = tid >> 5;
    const int wm = warp >> 2, wn = warp & 3;
    #pragma unroll
    for (int j = 0; j < 2; ++j)
        if (j < nIter) {
            load_tn(sm + j * STG_TN, A + j * 32, strideA, B + j * 32, strideB, tid);
            cp_commit();
        }
    for (int i = 0; i < nIter; ++i) {
        if (i + 1 < nIter) cp_wait<1>(); else cp_wait<0>();
        __syncthreads();
        if (i + 2 < nIter) {
            int s = (i + 2) % NSTG;
            load_tn(sm + s * STG_TN, A + (i + 2) * 32, strideA, B + (i + 2) * 32, strideB, tid);
            cp_commit();
        }
        compute_tn(sm + (i % NSTG) * STG_TN, lane, wm, wn, acc);
    }
    __syncthreads();
}

// ---------------------------------------------------------------------------
// init + fp16 conversion
// ---------------------------------------------------------------------------
__global__ void init_freq_kernel() {
    int p = blockIdx.x * blockDim.x + threadIdx.x;
    if (p < HALFD) {
        double e = exp(-((double)(2 * p) / (double)DINT) * 9.210340371976184);
        g_invfreq[p] = (float)e;
    }
}

__global__ __launch_bounds__(256)
void cvt_kernel(const float2* __restrict__ src, __half2* __restrict__ dst, int n2) {
    int i = blockIdx.x * blockDim.x + threadIdx.x;
    if (i < n2) {
        float2 v = src[i];
        dst[i] = __float22half2_rn(v);
    }
}

// ---------------------------------------------------------------------------
// Kernel 1: QKV GEMM. M=8192, N=3072, K=1024. Q,K -> f32; V -> fp16.
// grid (24, 64); each N tile of 128 maps wholly to Q, K, or V.
// ---------------------------------------------------------------------------
__global__ __launch_bounds__(256)
void qkv_gemm_pipe() {
    extern __shared__ char sm[];
    const int m0 = blockIdx.y * 128, n0 = blockIdx.x * 128;
    float acc[4][4][4] = {};
    pipe_tn(g_Xh + (size_t)m0 * DMODEL, DMODEL,
            g_Wh + (size_t)n0 * DMODEL, DMODEL, DMODEL / 32, sm, acc);

    const int tid = threadIdx.x, lane = tid & 31, warp = tid >> 5;
    const int wm = warp >> 2, wn = warp & 3;
    if (n0 < 2 * DINT) {
        float* dst = (n0 < DINT) ? g_Q : g_K;
        int nb = (n0 < DINT) ? n0 : n0 - DINT;
        #pragma unroll
        for (int mf = 0; mf < 4; ++mf)
            #pragma unroll
            for (int nf = 0; nf < 4; ++nf) {
                int r = m0 + wm * 64 + mf * 16 + (lane >> 2);
                int c = nb + wn * 32 + nf * 8 + (lane & 3) * 2;
                *(float2*)&dst[(size_t)r * DINT + c]       = make_float2(acc[mf][nf][0], acc[mf][nf][1]);
                *(float2*)&dst[(size_t)(r + 8) * DINT + c] = make_float2(acc[mf][nf][2], acc[mf][nf][3]);
            }
    } else {
        int nb = n0 - 2 * DINT;
        #pragma unroll
        for (int mf = 0; mf < 4; ++mf)
            #pragma unroll
            for (int nf = 0; nf < 4; ++nf) {
                int r = m0 + wm * 64 + mf * 16 + (lane >> 2);
                int c = nb + wn * 32 + nf * 8 + (lane & 3) * 2;
                *(__half2*)&g_Vh[(size_t)r * DINT + c] =
                    __float22half2_rn(make_float2(acc[mf][nf][0], acc[mf][nf][1]));
                *(__half2*)&g_Vh[(size_t)(r + 8) * DINT + c] =
                    __float22half2_rn(make_float2(acc[mf][nf][2], acc[mf][nf][3]));
            }
    }
}

// ---------------------------------------------------------------------------
// Kernel 2: RoPE + L2 norm + scale; writes fp16 Q,K.
// ---------------------------------------------------------------------------
__global__ __launch_bounds__(256)
void rope_norm_kernel(const float* __restrict__ sqk, float sqk_mul) {
    const int token = blockIdx.x;
    const int tpos = token & (TLEN - 1);
    const bool isQ = (blockIdx.y == 0);
    const float* row = (isQ ? g_Q : g_K) + (size_t)token * DINT;
    __half* outh = (isQ ? g_Qh : g_Kh) + (size_t)token * DINT;

    const int tid = threadIdx.x;
    float na[2], nb[2];
    float ss = 0.0f;
    #pragma unroll
    for (int h = 0; h < 2; ++h) {
        int p = tid + h * 256;
        float a = row[p];
        float b = row[p + HALFD];
        float ang = (float)tpos * g_invfreq[p];
        float s, c;
        sincosf(ang, &s, &c);
        na[h] = a * c - b * s;
        nb[h] = b * c + a * s;
        ss += na[h] * na[h] + nb[h] * nb[h];
    }
    __shared__ float warp_red[8];
    #pragma unroll
    for (int o = 16; o > 0; o >>= 1) ss += __shfl_xor_sync(0xffffffffu, ss, o);
    if ((tid & 31) == 0) warp_red[tid >> 5] = ss;
    __syncthreads();
    __shared__ float total_sh;
    if (tid == 0) {
        float t = 0.0f;
        #pragma unroll
        for (int w = 0; w < 8; ++w) t += warp_red[w];
        total_sh = t;
    }
    __syncthreads();
    float rnorm = 1.0f / sqrtf(total_sh);
    #pragma unroll
    for (int h = 0; h < 2; ++h) {
        int p = tid + h * 256;
        float va = na[h] * rnorm * (sqk[p] * sqk_mul);
        float vb = nb[h] * rnorm * (sqk[p + HALFD] * sqk_mul);
        outh[p]         = __float2half_rn(va);
        outh[p + HALFD] = __float2half_rn(vb);
    }
}

// ---------------------------------------------------------------------------
// Kernel 3: scores S = scale * Q K^T. grid (16, 16, 4), triangular skip.
// ---------------------------------------------------------------------------
__global__ __launch_bounds__(256)
void qk_gemm_pipe(float scale) {
    const int b  = blockIdx.z;
    const int q0 = blockIdx.y * 128;
    const int k0n = blockIdx.x * 128;
    if (k0n > q0) return;                      // tile fully above diagonal
    extern __shared__ char sm[];

    float acc[4][4][4] = {};
    pipe_tn(g_Qh + ((size_t)b * TLEN + q0) * DINT, DINT,
            g_Kh + ((size_t)b * TLEN + k0n) * DINT, DINT, DINT / 32, sm, acc);

    float* S = g_S + (size_t)b * TLEN * TLEN;
    const int tid = threadIdx.x, lane = tid & 31, warp = tid >> 5;
    const int wm = warp >> 2, wn = warp & 3;
    #pragma unroll
    for (int mf = 0; mf < 4; ++mf)
        #pragma unroll
        for (int nf = 0; nf < 4; ++nf) {
            int q = q0 + wm * 64 + mf * 16 + (lane >> 2);
            int c = k0n + wn * 32 + nf * 8 + (lane & 3) * 2;
            *(float2*)&S[(size_t)q * TLEN + c] =
                make_float2(acc[mf][nf][0] * scale, acc[mf][nf][1] * scale);
            *(float2*)&S[(size_t)(q + 8) * TLEN + c] =
                make_float2(acc[mf][nf][2] * scale, acc[mf][nf][3] * scale);
        }
}

// ---------------------------------------------------------------------------
// Kernel 4: causal softmax; writes fp16 P (exact zeros above diagonal).
// ---------------------------------------------------------------------------
__global__ __launch_bounds__(256)
void softmax_kernel() {
    const int q = blockIdx.x;
    const int b = blockIdx.y;
    const float* row = g_S + ((size_t)b * TLEN + q) * TLEN;
    __half* ph = g_Ph + ((size_t)b * TLEN + q) * TLEN;
    const int tid = threadIdx.x;

    float vals[8];
    float m = -INFINITY;
    #pragma unroll
    for (int i = 0; i < 8; ++i) {
        int k = i * 256 + tid;
        float v = (k <= q) ? row[k] : -INFINITY;
        vals[i] = v;
        m = fmaxf(m, v);
    }
    __shared__ float warp_red[8];
    __shared__ float bcast;
    #pragma unroll
    for (int o = 16; o > 0; o >>= 1) m = fmaxf(m, __shfl_xor_sync(0xffffffffu, m, o));
    if ((tid & 31) == 0) warp_red[tid >> 5] = m;
    __syncthreads();
    if (tid == 0) {
        float t = warp_red[0];
        #pragma unroll
        for (int w = 1; w < 8; ++w) t = fmaxf(t, warp_red[w]);
        bcast = t;
    }
    __syncthreads();
    const float rowmax = bcast;

    float sum = 0.0f;
    #pragma unroll
    for (int i = 0; i < 8; ++i) {
        int k = i * 256 + tid;
        float e = (k <= q) ? expf(vals[i] - rowmax) : 0.0f;
        vals[i] = e;
        sum += e;
    }
    #pragma unroll
    for (int o = 16; o > 0; o >>= 1) sum += __shfl_xor_sync(0xffffffffu, sum, o);
    if ((tid & 31) == 0) warp_red[tid >> 5] = sum;
    __syncthreads();
    if (tid == 0) {
        float t = 0.0f;
        #pragma unroll
        for (int w = 0; w < 8; ++w) t += warp_red[w];
        bcast = t;
    }
    __syncthreads();
    const float inv = 1.0f / bcast;
    #pragma unroll
    for (int i = 0; i < 8; ++i) {
        int k = i * 256 + tid;
        ph[k] = __float2half_rn(vals[i] * inv);
    }
}

// ---------------------------------------------------------------------------
// Kernel 5: O = P V. P k-contig (non-trans A); V n-contig (trans B).
// CTA 128(M) x 128(N), V tile 32x128. grid (8, 16, 4).
// ---------------------------------------------------------------------------
__device__ __forceinline__ void load_pv(char* st,
    const __half* P, const __half* V, int tid)
{
    __half* s = (__half*)st;
    #pragma unroll
    for (int j = 0; j < 2; ++j) {   // P: 128 rows x 4 chunks(16B)
        int idx = j * 256 + tid;
        int r = idx >> 2, c = idx & 3;
        cp16(smem_u32(&s[r * 40 + c * 8]), P + (size_t)r * TLEN + c * 8);
    }
    #pragma unroll
    for (int j = 0; j < 2; ++j) {   // V: 32 rows x 16 chunks
        int idx = j * 256 + tid;
        int r = idx >> 4, c = idx & 15;
        cp16(smem_u32(&s[SB_OFF + r * 136 + c * 8]), V + (size_t)r * DINT + c * 8);
    }
}

__global__ __launch_bounds__(256)
void pv_gemm_pipe(float* __restrict__ out) {
    const int b  = blockIdx.z;
    const int q0 = blockIdx.y * 128;
    const int n0 = blockIdx.x * 128;
    extern __shared__ char sm[];

    const __half* P = g_Ph + ((size_t)b * TLEN + q0) * TLEN;
    const __half* V = g_Vh + (size_t)b * TLEN * DINT + n0;
    const int nIter = (q0 + 128) / 32;

    const int tid = threadIdx.x, lane = tid & 31, warp = tid >> 5;
    const int wm = warp >> 2, wn = warp & 3;
    const int lrA = (lane & 7) + ((lane >> 3) & 1) * 8;
    const int lcA8 = (lane >> 4) * 8;
    const int lrV = (lane & 7) + ((lane >> 4) & 1) * 8;
    const int lcV8 = ((lane >> 3) & 1) * 8;

    float acc[4][4][4] = {};

    #pragma unroll
    for (int j = 0; j < 2; ++j)
        if (j < nIter) {
            load_pv(sm + j * STG_PV, P + j * 32, V + (size_t)j * 32 * DINT, tid);
            cp_commit();
        }
    for (int i = 0; i < nIter; ++i) {
        if (i + 1 < nIter) cp_wait<1>(); else cp_wait<0>();
        __syncthreads();
        if (i + 2 < nIter) {
            int s = (i + 2) % NSTG;
            load_pv(sm + s * STG_PV, P + (i + 2) * 32, V + (size_t)(i + 2) * 32 * DINT, tid);
            cp_commit();
        }
        {
            const char* st = sm + (i % NSTG) * STG_PV;
            const __half* sP = (const __half*)st;
            const __half* sV = sP + SB_OFF;
            #pragma unroll
            for (int ks = 0; ks < 2; ++ks) {
                const int kbA = ks * 16 + lcA8;
                const int kbV = ks * 16 + lrV;
                unsigned a[4][4], bv[2][4];
                #pragma unroll
                for (int mf = 0; mf < 4; ++mf) {
                    int rrow = wm * 64 + mf * 16 + lrA;
                    ldm_x4(smem_u32(&sP[rrow * 40 + kbA]), a[mf][0], a[mf][1], a[mf][2], a[mf][3]);
                }
                #pragma unroll
                for (int g = 0; g < 2; ++g) {
                    int col = wn * 32 + g * 16 + lcV8;
                    ldm_x4_t(smem_u32(&sV[kbV * 136 + col]), bv[g][0], bv[g][1], bv[g][2], bv[g][3]);
                }
                #pragma unroll
                for (int mf = 0; mf < 4; ++mf)
                    #pragma unroll
                    for (int nf = 0; nf < 4; ++nf) {
                        int g = nf >> 1, sdx = nf & 1;
                        mma16816(acc[mf][nf], a[mf], bv[g][sdx], bv[g][sdx + 2]);
                    }
            }
        }
    }

    #pragma unroll
    for (int mf = 0; mf < 4; ++mf)
        #pragma unroll
        for (int nf = 0; nf < 4; ++nf) {
            int q = q0 + wm * 64 + mf * 16 + (lane >> 2);
            int c = n0 + wn * 32 + nf * 8 + (lane & 3) * 2;
            *(float2*)&out[((size_t)(b * TLEN + q)) * DINT + c] =
                make_float2(acc[mf][nf][0], acc[mf][nf][1]);
            *(float2*)&out[((size_t)(b * TLEN + q + 8)) * DINT + c] =
                make_float2(acc[mf][nf][2], acc[mf][nf][3]);
        }
}

// ---------------------------------------------------------------------------
// Launch
// ---------------------------------------------------------------------------
extern "C" void kernel_launch(void* const* d_in, const int* in_sizes, int n_in,
                              void* d_out, int out_size) {
    (void)n_in; (void)out_size; (void)in_sizes;
    const float* input_vecs = (const float*)d_in[0];
    const float* qkv_w      = (const float*)d_in[1];
    const float* sqk        = (const float*)d_in[2];
    float* out              = (float*)d_out;

    const float sqk_mul = sqrtf((float)DMODEL);
    const float scale   = sqrtf((float)DMODEL);
    const int DSMEM_TN = NSTG * STG_TN;   // 61440
    const int DSMEM_PV = NSTG * STG_PV;   // 56832

    cudaFuncSetAttribute(qkv_gemm_pipe, cudaFuncAttributeMaxDynamicSharedMemorySize, DSMEM_TN);
    cudaFuncSetAttribute(qk_gemm_pipe,  cudaFuncAttributeMaxDynamicSharedMemorySize, DSMEM_TN);
    cudaFuncSetAttribute(pv_gemm_pipe,  cudaFuncAttributeMaxDynamicSharedMemorySize, DSMEM_PV);

    init_freq_kernel<<<2, 256>>>();

    __half2 *xh, *wh;
    cudaGetSymbolAddress((void**)&xh, g_Xh);
    cudaGetSymbolAddress((void**)&wh, g_Wh);
    int nx2 = MTOT * DMODEL / 2, nw2 = 3 * DINT * DMODEL / 2;
    cvt_kernel<<<(nx2 + 255) / 256, 256>>>((const float2*)input_vecs, xh, nx2);
    cvt_kernel<<<(nw2 + 255) / 256, 256>>>((const float2*)qkv_w, wh, nw2);

    qkv_gemm_pipe<<<dim3(3 * DINT / 128, MTOT / 128), 256, DSMEM_TN>>>();

    rope_norm_kernel<<<dim3(MTOT, 2), 256>>>(sqk, sqk_mul);

    qk_gemm_pipe<<<dim3(TLEN / 128, TLEN / 128, BATCH), 256, DSMEM_TN>>>(scale);

    softmax_kernel<<<dim3(TLEN, BATCH), 256>>>();

    pv_gemm_pipe<<<dim3(DINT / 128, TLEN / 128, BATCH), 256, DSMEM_PV>>>(out);
}

// round 11
// speedup vs baseline: 3.0322x; 1.2320x over previous
#include <cuda_runtime.h>
#include <cuda_fp16.h>
#include <math.h>

#define BATCH 4
#define TLEN  2048
#define DMODEL 1024
#define DINT   1024
#define MTOT  (BATCH * TLEN)     // 8192
#define HALFD (DINT / 2)         // 512

// ---------------------------------------------------------------------------
// Scratch (device globals; no allocation allowed)
// ---------------------------------------------------------------------------
__device__ float g_Q[MTOT * DINT];                 // f32 (rope input)
__device__ float g_K[MTOT * DINT];
__device__ float g_S[BATCH * TLEN * TLEN];         // scores f32
__device__ __half g_Qh[MTOT * DINT];               // post-rope fp16
__device__ __half g_Kh[MTOT * DINT];
__device__ __half g_Vh[MTOT * DINT];
__device__ __half g_Ph[BATCH * TLEN * TLEN];       // probs fp16
__device__ __half g_Xh[MTOT * DMODEL];
__device__ __half g_Wh[3 * DINT * DMODEL];
__device__ float g_invfreq[HALFD];

// ---------------------------------------------------------------------------
// Helpers
// ---------------------------------------------------------------------------
__device__ __forceinline__ unsigned smem_u32(const void* p) {
    return (unsigned)__cvta_generic_to_shared(p);
}
__device__ __forceinline__ void cp16(unsigned dst, const void* src) {
    asm volatile("cp.async.cg.shared.global [%0], [%1], 16;" :: "r"(dst), "l"(src));
}
__device__ __forceinline__ void cp_commit() {
    asm volatile("cp.async.commit_group;");
}
template <int N>
__device__ __forceinline__ void cp_wait() {
    asm volatile("cp.async.wait_group %0;" :: "n"(N));
}
__device__ __forceinline__ void ldm_x4(unsigned a, unsigned& r0, unsigned& r1,
                                       unsigned& r2, unsigned& r3) {
    asm volatile("ldmatrix.sync.aligned.m8n8.x4.shared.b16 {%0,%1,%2,%3}, [%4];"
                 : "=r"(r0), "=r"(r1), "=r"(r2), "=r"(r3) : "r"(a));
}
__device__ __forceinline__ void ldm_x4_t(unsigned a, unsigned& r0, unsigned& r1,
                                         unsigned& r2, unsigned& r3) {
    asm volatile("ldmatrix.sync.aligned.m8n8.x4.trans.shared.b16 {%0,%1,%2,%3}, [%4];"
                 : "=r"(r0), "=r"(r1), "=r"(r2), "=r"(r3) : "r"(a));
}
__device__ __forceinline__ void mma16816(float* c, const unsigned* a,
                                         unsigned b0, unsigned b1) {
    asm volatile("mma.sync.aligned.m16n8k16.row.col.f32.f16.f16.f32 "
                 "{%0,%1,%2,%3}, {%4,%5,%6,%7}, {%8,%9}, {%0,%1,%2,%3};"
                 : "+f"(c[0]), "+f"(c[1]), "+f"(c[2]), "+f"(c[3])
                 : "r"(a[0]), "r"(a[1]), "r"(a[2]), "r"(a[3]), "r"(b0), "r"(b1));
}

// CTA tile 128(M) x 128(N) x 32(K). 8 warps: wm in {0,1} (64 rows), wn in {0..3} (32 cols).
// Stage layouts (halfs): TN: A[128*40] B[128*40]; PV: P[128*40] V[32*136]
#define SB_OFF   (128 * 40)
#define STG_TN   ((128 * 40 + 128 * 40) * 2)   // 20480 B
#define STG_PV   ((128 * 40 + 32 * 136) * 2)   // 18944 B
#define NSTG 3

// ---------------------------------------------------------------------------
// TN loaders / fragment ops
// ---------------------------------------------------------------------------
__device__ __forceinline__ void load_tn(char* st,
    const __half* A, int strideA, const __half* B, int strideB, int tid)
{
    __half* s = (__half*)st;
    #pragma unroll
    for (int j = 0; j < 2; ++j) {   // A: 128 rows x 4 chunks(16B)
        int idx = j * 256 + tid;
        int r = idx >> 2, c = idx & 3;
        cp16(smem_u32(&s[r * 40 + c * 8]), A + (size_t)r * strideA + c * 8);
    }
    #pragma unroll
    for (int j = 0; j < 2; ++j) {   // B: 128 rows x 4 chunks(16B)
        int idx = j * 256 + tid;
        int r = idx >> 2, c = idx & 3;
        cp16(smem_u32(&s[SB_OFF + r * 40 + c * 8]), B + (size_t)r * strideB + c * 8);
    }
}

__device__ __forceinline__ void frags_tn(const char* st, int lane, int wm, int wn,
                                         int ks, unsigned a[4][4], unsigned b[2][4])
{
    const __half* sA = (const __half*)st;
    const __half* sB = sA + SB_OFF;
    const int lr  = (lane & 7) + ((lane >> 3) & 1) * 8;
    const int kb  = ks * 16 + (lane >> 4) * 8;
    #pragma unroll
    for (int mf = 0; mf < 4; ++mf) {
        int row = wm * 64 + mf * 16 + lr;
        ldm_x4(smem_u32(&sA[row * 40 + kb]), a[mf][0], a[mf][1], a[mf][2], a[mf][3]);
    }
    #pragma unroll
    for (int g = 0; g < 2; ++g) {
        int row = wn * 32 + g * 16 + lr;
        ldm_x4(smem_u32(&sB[row * 40 + kb]), b[g][0], b[g][1], b[g][2], b[g][3]);
    }
}

__device__ __forceinline__ void mma_tile(unsigned a[4][4], unsigned b[2][4],
                                         float acc[4][4][4])
{
    #pragma unroll
    for (int mf = 0; mf < 4; ++mf)
        #pragma unroll
        for (int nf = 0; nf < 4; ++nf) {
            int g = nf >> 1, sdx = nf & 1;
            mma16816(acc[mf][nf], a[mf], b[g][sdx], b[g][sdx + 2]);
        }
}

// Mainloop with register fragment double-buffering: ldmatrix for k-step j+1
// (or the next stage's ks=0, right after its barrier) overlaps the MMAs of j.
__device__ __forceinline__ void pipe_tn(
    const __half* A, int strideA, const __half* B, int strideB,
    int nIter, char* sm, float acc[4][4][4])
{
    const int tid = threadIdx.x, lane = tid & 31, warp = tid >> 5;
    const int wm = warp >> 2, wn = warp & 3;

    load_tn(sm, A, strideA, B, strideB, tid);
    cp_commit();
    load_tn(sm + STG_TN, A + 32, strideA, B + 32, strideB, tid);
    cp_commit();
    cp_wait<1>();
    __syncthreads();

    unsigned a0[4][4], b0[2][4], a1[4][4], b1[2][4];
    frags_tn(sm, lane, wm, wn, 0, a0, b0);

    for (int i = 0; i < nIter; ++i) {
        const char* cur = sm + (i % NSTG) * STG_TN;
        frags_tn(cur, lane, wm, wn, 1, a1, b1);      // prefetch ks=1
        mma_tile(a0, b0, acc);                        // compute ks=0
        if (i + 2 < nIter) {
            load_tn(sm + ((i + 2) % NSTG) * STG_TN,
                    A + (i + 2) * 32, strideA, B + (i + 2) * 32, strideB, tid);
            cp_commit();
        }
        if (i + 1 < nIter) {
            if (i + 2 < nIter) cp_wait<1>(); else cp_wait<0>();
            __syncthreads();
            frags_tn(sm + ((i + 1) % NSTG) * STG_TN, lane, wm, wn, 0, a0, b0);
        }
        mma_tile(a1, b1, acc);                        // compute ks=1
    }
    __syncthreads();
}

// ---------------------------------------------------------------------------
// init + fp16 conversion
// ---------------------------------------------------------------------------
__global__ void init_freq_kernel() {
    int p = blockIdx.x * blockDim.x + threadIdx.x;
    if (p < HALFD) {
        double e = exp(-((double)(2 * p) / (double)DINT) * 9.210340371976184);
        g_invfreq[p] = (float)e;
    }
}

__global__ __launch_bounds__(256)
void cvt_kernel(const float2* __restrict__ src, __half2* __restrict__ dst, int n2) {
    int i = blockIdx.x * blockDim.x + threadIdx.x;
    if (i < n2) {
        float2 v = src[i];
        dst[i] = __float22half2_rn(v);
    }
}

// ---------------------------------------------------------------------------
// Kernel 1: QKV GEMM. M=8192, N=3072, K=1024. Q,K -> f32; V -> fp16.
// ---------------------------------------------------------------------------
__global__ __launch_bounds__(256, 2)
void qkv_gemm_pipe() {
    extern __shared__ char sm[];
    const int m0 = blockIdx.y * 128, n0 = blockIdx.x * 128;
    float acc[4][4][4] = {};
    pipe_tn(g_Xh + (size_t)m0 * DMODEL, DMODEL,
            g_Wh + (size_t)n0 * DMODEL, DMODEL, DMODEL / 32, sm, acc);

    const int tid = threadIdx.x, lane = tid & 31, warp = tid >> 5;
    const int wm = warp >> 2, wn = warp & 3;
    if (n0 < 2 * DINT) {
        float* dst = (n0 < DINT) ? g_Q : g_K;
        int nb = (n0 < DINT) ? n0 : n0 - DINT;
        #pragma unroll
        for (int mf = 0; mf < 4; ++mf)
            #pragma unroll
            for (int nf = 0; nf < 4; ++nf) {
                int r = m0 + wm * 64 + mf * 16 + (lane >> 2);
                int c = nb + wn * 32 + nf * 8 + (lane & 3) * 2;
                *(float2*)&dst[(size_t)r * DINT + c]       = make_float2(acc[mf][nf][0], acc[mf][nf][1]);
                *(float2*)&dst[(size_t)(r + 8) * DINT + c] = make_float2(acc[mf][nf][2], acc[mf][nf][3]);
            }
    } else {
        int nb = n0 - 2 * DINT;
        #pragma unroll
        for (int mf = 0; mf < 4; ++mf)
            #pragma unroll
            for (int nf = 0; nf < 4; ++nf) {
                int r = m0 + wm * 64 + mf * 16 + (lane >> 2);
                int c = nb + wn * 32 + nf * 8 + (lane & 3) * 2;
                *(__half2*)&g_Vh[(size_t)r * DINT + c] =
                    __float22half2_rn(make_float2(acc[mf][nf][0], acc[mf][nf][1]));
                *(__half2*)&g_Vh[(size_t)(r + 8) * DINT + c] =
                    __float22half2_rn(make_float2(acc[mf][nf][2], acc[mf][nf][3]));
            }
    }
}

// ---------------------------------------------------------------------------
// Kernel 2: RoPE + L2 norm + scale; writes fp16 Q,K.
// ---------------------------------------------------------------------------
__global__ __launch_bounds__(256)
void rope_norm_kernel(const float* __restrict__ sqk, float sqk_mul) {
    const int token = blockIdx.x;
    const int tpos = token & (TLEN - 1);
    const bool isQ = (blockIdx.y == 0);
    const float* row = (isQ ? g_Q : g_K) + (size_t)token * DINT;
    __half* outh = (isQ ? g_Qh : g_Kh) + (size_t)token * DINT;

    const int tid = threadIdx.x;
    float na[2], nb[2];
    float ss = 0.0f;
    #pragma unroll
    for (int h = 0; h < 2; ++h) {
        int p = tid + h * 256;
        float a = row[p];
        float b = row[p + HALFD];
        float ang = (float)tpos * g_invfreq[p];
        float s, c;
        sincosf(ang, &s, &c);
        na[h] = a * c - b * s;
        nb[h] = b * c + a * s;
        ss += na[h] * na[h] + nb[h] * nb[h];
    }
    __shared__ float warp_red[8];
    #pragma unroll
    for (int o = 16; o > 0; o >>= 1) ss += __shfl_xor_sync(0xffffffffu, ss, o);
    if ((tid & 31) == 0) warp_red[tid >> 5] = ss;
    __syncthreads();
    __shared__ float total_sh;
    if (tid == 0) {
        float t = 0.0f;
        #pragma unroll
        for (int w = 0; w < 8; ++w) t += warp_red[w];
        total_sh = t;
    }
    __syncthreads();
    float rnorm = 1.0f / sqrtf(total_sh);
    #pragma unroll
    for (int h = 0; h < 2; ++h) {
        int p = tid + h * 256;
        float va = na[h] * rnorm * (sqk[p] * sqk_mul);
        float vb = nb[h] * rnorm * (sqk[p + HALFD] * sqk_mul);
        outh[p]         = __float2half_rn(va);
        outh[p + HALFD] = __float2half_rn(vb);
    }
}

// ---------------------------------------------------------------------------
// Kernel 3: scores S = scale * Q K^T. grid (16, 16, 4), triangular skip.
// ---------------------------------------------------------------------------
__global__ __launch_bounds__(256, 2)
void qk_gemm_pipe(float scale) {
    const int b  = blockIdx.z;
    const int q0 = blockIdx.y * 128;
    const int k0n = blockIdx.x * 128;
    if (k0n > q0) return;                      // tile fully above diagonal
    extern __shared__ char sm[];

    float acc[4][4][4] = {};
    pipe_tn(g_Qh + ((size_t)b * TLEN + q0) * DINT, DINT,
            g_Kh + ((size_t)b * TLEN + k0n) * DINT, DINT, DINT / 32, sm, acc);

    float* S = g_S + (size_t)b * TLEN * TLEN;
    const int tid = threadIdx.x, lane = tid & 31, warp = tid >> 5;
    const int wm = warp >> 2, wn = warp & 3;
    #pragma unroll
    for (int mf = 0; mf < 4; ++mf)
        #pragma unroll
        for (int nf = 0; nf < 4; ++nf) {
            int q = q0 + wm * 64 + mf * 16 + (lane >> 2);
            int c = k0n + wn * 32 + nf * 8 + (lane & 3) * 2;
            *(float2*)&S[(size_t)q * TLEN + c] =
                make_float2(acc[mf][nf][0] * scale, acc[mf][nf][1] * scale);
            *(float2*)&S[(size_t)(q + 8) * TLEN + c] =
                make_float2(acc[mf][nf][2] * scale, acc[mf][nf][3] * scale);
        }
}

// ---------------------------------------------------------------------------
// Kernel 4: causal softmax; writes fp16 P (exact zeros above diagonal).
// ---------------------------------------------------------------------------
__global__ __launch_bounds__(256)
void softmax_kernel() {
    const int q = blockIdx.x;
    const int b = blockIdx.y;
    const float* row = g_S + ((size_t)b * TLEN + q) * TLEN;
    __half* ph = g_Ph + ((size_t)b * TLEN + q) * TLEN;
    const int tid = threadIdx.x;

    float vals[8];
    float m = -INFINITY;
    #pragma unroll
    for (int i = 0; i < 8; ++i) {
        int k = i * 256 + tid;
        float v = (k <= q) ? row[k] : -INFINITY;
        vals[i] = v;
        m = fmaxf(m, v);
    }
    __shared__ float warp_red[8];
    __shared__ float bcast;
    #pragma unroll
    for (int o = 16; o > 0; o >>= 1) m = fmaxf(m, __shfl_xor_sync(0xffffffffu, m, o));
    if ((tid & 31) == 0) warp_red[tid >> 5] = m;
    __syncthreads();
    if (tid == 0) {
        float t = warp_red[0];
        #pragma unroll
        for (int w = 1; w < 8; ++w) t = fmaxf(t, warp_red[w]);
        bcast = t;
    }
    __syncthreads();
    const float rowmax = bcast;

    float sum = 0.0f;
    #pragma unroll
    for (int i = 0; i < 8; ++i) {
        int k = i * 256 + tid;
        float e = (k <= q) ? expf(vals[i] - rowmax) : 0.0f;
        vals[i] = e;
        sum += e;
    }
    #pragma unroll
    for (int o = 16; o > 0; o >>= 1) sum += __shfl_xor_sync(0xffffffffu, sum, o);
    if ((tid & 31) == 0) warp_red[tid >> 5] = sum;
    __syncthreads();
    if (tid == 0) {
        float t = 0.0f;
        #pragma unroll
        for (int w = 0; w < 8; ++w) t += warp_red[w];
        bcast = t;
    }
    __syncthreads();
    const float inv = 1.0f / bcast;
    #pragma unroll
    for (int i = 0; i < 8; ++i) {
        int k = i * 256 + tid;
        ph[k] = __float2half_rn(vals[i] * inv);
    }
}

// ---------------------------------------------------------------------------
// Kernel 5: O = P V. P k-contig (non-trans A); V n-contig (trans B).
// CTA 128(M) x 128(N), V tile 32x128. grid (8, 16, 4).
// ---------------------------------------------------------------------------
__device__ __forceinline__ void load_pv(char* st,
    const __half* P, const __half* V, int tid)
{
    __half* s = (__half*)st;
    #pragma unroll
    for (int j = 0; j < 2; ++j) {   // P: 128 rows x 4 chunks(16B)
        int idx = j * 256 + tid;
        int r = idx >> 2, c = idx & 3;
        cp16(smem_u32(&s[r * 40 + c * 8]), P + (size_t)r * TLEN + c * 8);
    }
    #pragma unroll
    for (int j = 0; j < 2; ++j) {   // V: 32 rows x 16 chunks
        int idx = j * 256 + tid;
        int r = idx >> 4, c = idx & 15;
        cp16(smem_u32(&s[SB_OFF + r * 136 + c * 8]), V + (size_t)r * DINT + c * 8);
    }
}

__device__ __forceinline__ void frags_pv(const char* st, int lane, int wm, int wn,
                                         int ks, unsigned a[4][4], unsigned bv[2][4])
{
    const __half* sP = (const __half*)st;
    const __half* sV = sP + SB_OFF;
    const int lrA  = (lane & 7) + ((lane >> 3) & 1) * 8;
    const int kbA  = ks * 16 + (lane >> 4) * 8;
    const int kbV  = ks * 16 + (lane & 7) + ((lane >> 4) & 1) * 8;
    const int lcV8 = ((lane >> 3) & 1) * 8;
    #pragma unroll
    for (int mf = 0; mf < 4; ++mf) {
        int row = wm * 64 + mf * 16 + lrA;
        ldm_x4(smem_u32(&sP[row * 40 + kbA]), a[mf][0], a[mf][1], a[mf][2], a[mf][3]);
    }
    #pragma unroll
    for (int g = 0; g < 2; ++g) {
        int col = wn * 32 + g * 16 + lcV8;
        ldm_x4_t(smem_u32(&sV[kbV * 136 + col]), bv[g][0], bv[g][1], bv[g][2], bv[g][3]);
    }
}

__global__ __launch_bounds__(256, 2)
void pv_gemm_pipe(float* __restrict__ out) {
    const int b  = blockIdx.z;
    const int q0 = blockIdx.y * 128;
    const int n0 = blockIdx.x * 128;
    extern __shared__ char sm[];

    const __half* P = g_Ph + ((size_t)b * TLEN + q0) * TLEN;
    const __half* V = g_Vh + (size_t)b * TLEN * DINT + n0;
    const int nIter = (q0 + 128) / 32;

    const int tid = threadIdx.x, lane = tid & 31, warp = tid >> 5;
    const int wm = warp >> 2, wn = warp & 3;

    float acc[4][4][4] = {};

    load_pv(sm, P, V, tid);
    cp_commit();
    load_pv(sm + STG_PV, P + 32, V + (size_t)32 * DINT, tid);
    cp_commit();
    cp_wait<1>();
    __syncthreads();

    unsigned a0[4][4], b0[2][4], a1[4][4], b1[2][4];
    frags_pv(sm, lane, wm, wn, 0, a0, b0);

    for (int i = 0; i < nIter; ++i) {
        const char* cur = sm + (i % NSTG) * STG_PV;
        frags_pv(cur, lane, wm, wn, 1, a1, b1);
        mma_tile(a0, b0, acc);
        if (i + 2 < nIter) {
            load_pv(sm + ((i + 2) % NSTG) * STG_PV,
                    P + (i + 2) * 32, V + (size_t)(i + 2) * 32 * DINT, tid);
            cp_commit();
        }
        if (i + 1 < nIter) {
            if (i + 2 < nIter) cp_wait<1>(); else cp_wait<0>();
            __syncthreads();
            frags_pv(sm + ((i + 1) % NSTG) * STG_PV, lane, wm, wn, 0, a0, b0);
        }
        mma_tile(a1, b1, acc);
    }

    #pragma unroll
    for (int mf = 0; mf < 4; ++mf)
        #pragma unroll
        for (int nf = 0; nf < 4; ++nf) {
            int q = q0 + wm * 64 + mf * 16 + (lane >> 2);
            int c = n0 + wn * 32 + nf * 8 + (lane & 3) * 2;
            *(float2*)&out[((size_t)(b * TLEN + q)) * DINT + c] =
                make_float2(acc[mf][nf][0], acc[mf][nf][1]);
            *(float2*)&out[((size_t)(b * TLEN + q + 8)) * DINT + c] =
                make_float2(acc[mf][nf][2], acc[mf][nf][3]);
        }
}

// ---------------------------------------------------------------------------
// Launch
// ---------------------------------------------------------------------------
extern "C" void kernel_launch(void* const* d_in, const int* in_sizes, int n_in,
                              void* d_out, int out_size) {
    (void)n_in; (void)out_size; (void)in_sizes;
    const float* input_vecs = (const float*)d_in[0];
    const float* qkv_w      = (const float*)d_in[1];
    const float* sqk        = (const float*)d_in[2];
    float* out              = (float*)d_out;

    const float sqk_mul = sqrtf((float)DMODEL);
    const float scale   = sqrtf((float)DMODEL);
    const int DSMEM_TN = NSTG * STG_TN;   // 61440
    const int DSMEM_PV = NSTG * STG_PV;   // 56832

    cudaFuncSetAttribute(qkv_gemm_pipe, cudaFuncAttributeMaxDynamicSharedMemorySize, DSMEM_TN);
    cudaFuncSetAttribute(qk_gemm_pipe,  cudaFuncAttributeMaxDynamicSharedMemorySize, DSMEM_TN);
    cudaFuncSetAttribute(pv_gemm_pipe,  cudaFuncAttributeMaxDynamicSharedMemorySize, DSMEM_PV);

    init_freq_kernel<<<2, 256>>>();

    __half2 *xh, *wh;
    cudaGetSymbolAddress((void**)&xh, g_Xh);
    cudaGetSymbolAddress((void**)&wh, g_Wh);
    int nx2 = MTOT * DMODEL / 2, nw2 = 3 * DINT * DMODEL / 2;
    cvt_kernel<<<(nx2 + 255) / 256, 256>>>((const float2*)input_vecs, xh, nx2);
    cvt_kernel<<<(nw2 + 255) / 256, 256>>>((const float2*)qkv_w, wh, nw2);

    qkv_gemm_pipe<<<dim3(3 * DINT / 128, MTOT / 128), 256, DSMEM_TN>>>();

    rope_norm_kernel<<<dim3(MTOT, 2), 256>>>(sqk, sqk_mul);

    qk_gemm_pipe<<<dim3(TLEN / 128, TLEN / 128, BATCH), 256, DSMEM_TN>>>(scale);

    softmax_kernel<<<dim3(TLEN, BATCH), 256>>>();

    pv_gemm_pipe<<<dim3(DINT / 128, TLEN / 128, BATCH), 256, DSMEM_PV>>>(out);
}

// round 12
// speedup vs baseline: 3.1956x; 1.0539x over previous
#include <cuda_runtime.h>
#include <cuda_fp16.h>
#include <math.h>

#define BATCH 4
#define TLEN  2048
#define DMODEL 1024
#define DINT   1024
#define MTOT  (BATCH * TLEN)     // 8192
#define HALFD (DINT / 2)         // 512

// ---------------------------------------------------------------------------
// Scratch (device globals; no allocation allowed)
// ---------------------------------------------------------------------------
__device__ float g_Q[MTOT * DINT];                 // f32 (rope input)
__device__ float g_K[MTOT * DINT];
__device__ float g_S[BATCH * TLEN * TLEN];         // scores f32
__device__ __half g_Qh[MTOT * DINT];               // post-rope fp16
__device__ __half g_Kh[MTOT * DINT];
__device__ __half g_Vh[MTOT * DINT];
__device__ __half g_Ph[BATCH * TLEN * TLEN];       // probs fp16
__device__ __half g_Xh[MTOT * DMODEL];
__device__ __half g_Wh[3 * DINT * DMODEL];
__device__ float g_invfreq[HALFD];

// ---------------------------------------------------------------------------
// Helpers
// ---------------------------------------------------------------------------
__device__ __forceinline__ unsigned smem_u32(const void* p) {
    return (unsigned)__cvta_generic_to_shared(p);
}
__device__ __forceinline__ void cp16(unsigned dst, const void* src) {
    asm volatile("cp.async.cg.shared.global [%0], [%1], 16;" :: "r"(dst), "l"(src));
}
__device__ __forceinline__ void cp_commit() {
    asm volatile("cp.async.commit_group;");
}
template <int N>
__device__ __forceinline__ void cp_wait() {
    asm volatile("cp.async.wait_group %0;" :: "n"(N));
}
__device__ __forceinline__ void ldm_x4(unsigned a, unsigned& r0, unsigned& r1,
                                       unsigned& r2, unsigned& r3) {
    asm volatile("ldmatrix.sync.aligned.m8n8.x4.shared.b16 {%0,%1,%2,%3}, [%4];"
                 : "=r"(r0), "=r"(r1), "=r"(r2), "=r"(r3) : "r"(a));
}
__device__ __forceinline__ void ldm_x4_t(unsigned a, unsigned& r0, unsigned& r1,
                                         unsigned& r2, unsigned& r3) {
    asm volatile("ldmatrix.sync.aligned.m8n8.x4.trans.shared.b16 {%0,%1,%2,%3}, [%4];"
                 : "=r"(r0), "=r"(r1), "=r"(r2), "=r"(r3) : "r"(a));
}
__device__ __forceinline__ void mma16816(float* c, const unsigned* a,
                                         unsigned b0, unsigned b1) {
    asm volatile("mma.sync.aligned.m16n8k16.row.col.f32.f16.f16.f32 "
                 "{%0,%1,%2,%3}, {%4,%5,%6,%7}, {%8,%9}, {%0,%1,%2,%3};"
                 : "+f"(c[0]), "+f"(c[1]), "+f"(c[2]), "+f"(c[3])
                 : "r"(a[0]), "r"(a[1]), "r"(a[2]), "r"(a[3]), "r"(b0), "r"(b1));
}

// CTA tile 128(M) x 128(N) x 64(K). 8 warps: wm in {0,1}, wn in {0..3}.
// Stage (halfs): TN: A[128*72] B[128*72]; PV: P[128*72] V[64*136]
#define SB_OFF   (128 * 72)
#define STG_TN   ((128 * 72 + 128 * 72) * 2)   // 36864 B
#define STG_PV   ((128 * 72 + 64 * 136) * 2)   // 35840 B
#define NSTG 3

// ---------------------------------------------------------------------------
// TN loaders / fragment ops (K-stage = 64 halfs = 8 x 16B chunks per row)
// ---------------------------------------------------------------------------
__device__ __forceinline__ void load_tn(char* st,
    const __half* A, int strideA, const __half* B, int strideB, int tid)
{
    __half* s = (__half*)st;
    #pragma unroll
    for (int j = 0; j < 4; ++j) {   // A: 128 rows x 8 chunks = 1024
        int idx = j * 256 + tid;
        int r = idx >> 3, c = idx & 7;
        cp16(smem_u32(&s[r * 72 + c * 8]), A + (size_t)r * strideA + c * 8);
    }
    #pragma unroll
    for (int j = 0; j < 4; ++j) {   // B: 128 rows x 8 chunks
        int idx = j * 256 + tid;
        int r = idx >> 3, c = idx & 7;
        cp16(smem_u32(&s[SB_OFF + r * 72 + c * 8]), B + (size_t)r * strideB + c * 8);
    }
}

__device__ __forceinline__ void frags_tn(const char* st, int lane, int wm, int wn,
                                         int ks, unsigned a[4][4], unsigned b[2][4])
{
    const __half* sA = (const __half*)st;
    const __half* sB = sA + SB_OFF;
    const int lr  = (lane & 7) + ((lane >> 3) & 1) * 8;
    const int kb  = ks * 16 + (lane >> 4) * 8;
    #pragma unroll
    for (int mf = 0; mf < 4; ++mf) {
        int row = wm * 64 + mf * 16 + lr;
        ldm_x4(smem_u32(&sA[row * 72 + kb]), a[mf][0], a[mf][1], a[mf][2], a[mf][3]);
    }
    #pragma unroll
    for (int g = 0; g < 2; ++g) {
        int row = wn * 32 + g * 16 + lr;
        ldm_x4(smem_u32(&sB[row * 72 + kb]), b[g][0], b[g][1], b[g][2], b[g][3]);
    }
}

__device__ __forceinline__ void mma_tile(unsigned a[4][4], unsigned b[2][4],
                                         float acc[4][4][4])
{
    #pragma unroll
    for (int mf = 0; mf < 4; ++mf)
        #pragma unroll
        for (int nf = 0; nf < 4; ++nf) {
            int g = nf >> 1, sdx = nf & 1;
            mma16816(acc[mf][nf], a[mf], b[g][sdx], b[g][sdx + 2]);
        }
}

// Mainloop: 64-k stages, one barrier per stage, register fragment double-buffer
// threads ldmatrix of k-step j+1 (or next stage's ks=0 post-barrier) under MMAs of j.
__device__ __forceinline__ void pipe_tn(
    const __half* A, int strideA, const __half* B, int strideB,
    int nIter, char* sm, float acc[4][4][4])
{
    const int tid = threadIdx.x, lane = tid & 31, warp = tid >> 5;
    const int wm = warp >> 2, wn = warp & 3;

    load_tn(sm, A, strideA, B, strideB, tid);
    cp_commit();
    if (nIter > 1) {
        load_tn(sm + STG_TN, A + 64, strideA, B + 64, strideB, tid);
        cp_commit();
        cp_wait<1>();
    } else {
        cp_wait<0>();
    }
    __syncthreads();

    unsigned f0[4][4], g0[2][4], f1[4][4], g1[2][4];
    frags_tn(sm, lane, wm, wn, 0, f0, g0);

    for (int i = 0; i < nIter; ++i) {
        const char* cur = sm + (i % NSTG) * STG_TN;
        frags_tn(cur, lane, wm, wn, 1, f1, g1);
        mma_tile(f0, g0, acc);
        frags_tn(cur, lane, wm, wn, 2, f0, g0);
        mma_tile(f1, g1, acc);
        frags_tn(cur, lane, wm, wn, 3, f1, g1);
        mma_tile(f0, g0, acc);
        if (i + 2 < nIter) {
            load_tn(sm + ((i + 2) % NSTG) * STG_TN,
                    A + (i + 2) * 64, strideA, B + (i + 2) * 64, strideB, tid);
            cp_commit();
        }
        if (i + 1 < nIter) {
            if (i + 2 < nIter) cp_wait<1>(); else cp_wait<0>();
            __syncthreads();
            frags_tn(sm + ((i + 1) % NSTG) * STG_TN, lane, wm, wn, 0, f0, g0);
        }
        mma_tile(f1, g1, acc);
    }
    __syncthreads();
}

// ---------------------------------------------------------------------------
// init + fp16 conversion
// ---------------------------------------------------------------------------
__global__ void init_freq_kernel() {
    int p = blockIdx.x * blockDim.x + threadIdx.x;
    if (p < HALFD) {
        double e = exp(-((double)(2 * p) / (double)DINT) * 9.210340371976184);
        g_invfreq[p] = (float)e;
    }
}

__global__ __launch_bounds__(256)
void cvt_kernel(const float2* __restrict__ src, __half2* __restrict__ dst, int n2) {
    int i = blockIdx.x * blockDim.x + threadIdx.x;
    if (i < n2) {
        float2 v = src[i];
        dst[i] = __float22half2_rn(v);
    }
}

// ---------------------------------------------------------------------------
// Kernel 1: QKV GEMM. M=8192, N=3072, K=1024. Q,K -> f32; V -> fp16.
// ---------------------------------------------------------------------------
__global__ __launch_bounds__(256, 2)
void qkv_gemm_pipe() {
    extern __shared__ char sm[];
    const int m0 = blockIdx.y * 128, n0 = blockIdx.x * 128;
    float acc[4][4][4] = {};
    pipe_tn(g_Xh + (size_t)m0 * DMODEL, DMODEL,
            g_Wh + (size_t)n0 * DMODEL, DMODEL, DMODEL / 64, sm, acc);

    const int tid = threadIdx.x, lane = tid & 31, warp = tid >> 5;
    const int wm = warp >> 2, wn = warp & 3;
    if (n0 < 2 * DINT) {
        float* dst = (n0 < DINT) ? g_Q : g_K;
        int nb = (n0 < DINT) ? n0 : n0 - DINT;
        #pragma unroll
        for (int mf = 0; mf < 4; ++mf)
            #pragma unroll
            for (int nf = 0; nf < 4; ++nf) {
                int r = m0 + wm * 64 + mf * 16 + (lane >> 2);
                int c = nb + wn * 32 + nf * 8 + (lane & 3) * 2;
                *(float2*)&dst[(size_t)r * DINT + c]       = make_float2(acc[mf][nf][0], acc[mf][nf][1]);
                *(float2*)&dst[(size_t)(r + 8) * DINT + c] = make_float2(acc[mf][nf][2], acc[mf][nf][3]);
            }
    } else {
        int nb = n0 - 2 * DINT;
        #pragma unroll
        for (int mf = 0; mf < 4; ++mf)
            #pragma unroll
            for (int nf = 0; nf < 4; ++nf) {
                int r = m0 + wm * 64 + mf * 16 + (lane >> 2);
                int c = nb + wn * 32 + nf * 8 + (lane & 3) * 2;
                *(__half2*)&g_Vh[(size_t)r * DINT + c] =
                    __float22half2_rn(make_float2(acc[mf][nf][0], acc[mf][nf][1]));
                *(__half2*)&g_Vh[(size_t)(r + 8) * DINT + c] =
                    __float22half2_rn(make_float2(acc[mf][nf][2], acc[mf][nf][3]));
            }
    }
}

// ---------------------------------------------------------------------------
// Kernel 2: RoPE + L2 norm + scale; writes fp16 Q,K.
// ---------------------------------------------------------------------------
__global__ __launch_bounds__(256)
void rope_norm_kernel(const float* __restrict__ sqk, float sqk_mul) {
    const int token = blockIdx.x;
    const int tpos = token & (TLEN - 1);
    const bool isQ = (blockIdx.y == 0);
    const float* row = (isQ ? g_Q : g_K) + (size_t)token * DINT;
    __half* outh = (isQ ? g_Qh : g_Kh) + (size_t)token * DINT;

    const int tid = threadIdx.x;
    float na[2], nb[2];
    float ss = 0.0f;
    #pragma unroll
    for (int h = 0; h < 2; ++h) {
        int p = tid + h * 256;
        float a = row[p];
        float b = row[p + HALFD];
        float ang = (float)tpos * g_invfreq[p];
        float s, c;
        sincosf(ang, &s, &c);
        na[h] = a * c - b * s;
        nb[h] = b * c + a * s;
        ss += na[h] * na[h] + nb[h] * nb[h];
    }
    __shared__ float warp_red[8];
    #pragma unroll
    for (int o = 16; o > 0; o >>= 1) ss += __shfl_xor_sync(0xffffffffu, ss, o);
    if ((tid & 31) == 0) warp_red[tid >> 5] = ss;
    __syncthreads();
    __shared__ float total_sh;
    if (tid == 0) {
        float t = 0.0f;
        #pragma unroll
        for (int w = 0; w < 8; ++w) t += warp_red[w];
        total_sh = t;
    }
    __syncthreads();
    float rnorm = 1.0f / sqrtf(total_sh);
    #pragma unroll
    for (int h = 0; h < 2; ++h) {
        int p = tid + h * 256;
        float va = na[h] * rnorm * (sqk[p] * sqk_mul);
        float vb = nb[h] * rnorm * (sqk[p + HALFD] * sqk_mul);
        outh[p]         = __float2half_rn(va);
        outh[p + HALFD] = __float2half_rn(vb);
    }
}

// ---------------------------------------------------------------------------
// Kernel 3: scores S = scale * Q K^T. grid (16, 16, 4), triangular skip.
// ---------------------------------------------------------------------------
__global__ __launch_bounds__(256, 2)
void qk_gemm_pipe(float scale) {
    const int b  = blockIdx.z;
    const int q0 = blockIdx.y * 128;
    const int k0n = blockIdx.x * 128;
    if (k0n > q0) return;                      // tile fully above diagonal
    extern __shared__ char sm[];

    float acc[4][4][4] = {};
    pipe_tn(g_Qh + ((size_t)b * TLEN + q0) * DINT, DINT,
            g_Kh + ((size_t)b * TLEN + k0n) * DINT, DINT, DINT / 64, sm, acc);

    float* S = g_S + (size_t)b * TLEN * TLEN;
    const int tid = threadIdx.x, lane = tid & 31, warp = tid >> 5;
    const int wm = warp >> 2, wn = warp & 3;
    #pragma unroll
    for (int mf = 0; mf < 4; ++mf)
        #pragma unroll
        for (int nf = 0; nf < 4; ++nf) {
            int q = q0 + wm * 64 + mf * 16 + (lane >> 2);
            int c = k0n + wn * 32 + nf * 8 + (lane & 3) * 2;
            *(float2*)&S[(size_t)q * TLEN + c] =
                make_float2(acc[mf][nf][0] * scale, acc[mf][nf][1] * scale);
            *(float2*)&S[(size_t)(q + 8) * TLEN + c] =
                make_float2(acc[mf][nf][2] * scale, acc[mf][nf][3] * scale);
        }
}

// ---------------------------------------------------------------------------
// Kernel 4: causal softmax; writes fp16 P (exact zeros above diagonal).
// ---------------------------------------------------------------------------
__global__ __launch_bounds__(256)
void softmax_kernel() {
    const int q = blockIdx.x;
    const int b = blockIdx.y;
    const float* row = g_S + ((size_t)b * TLEN + q) * TLEN;
    __half* ph = g_Ph + ((size_t)b * TLEN + q) * TLEN;
    const int tid = threadIdx.x;

    float vals[8];
    float m = -INFINITY;
    #pragma unroll
    for (int i = 0; i < 8; ++i) {
        int k = i * 256 + tid;
        float v = (k <= q) ? row[k] : -INFINITY;
        vals[i] = v;
        m = fmaxf(m, v);
    }
    __shared__ float warp_red[8];
    __shared__ float bcast;
    #pragma unroll
    for (int o = 16; o > 0; o >>= 1) m = fmaxf(m, __shfl_xor_sync(0xffffffffu, m, o));
    if ((tid & 31) == 0) warp_red[tid >> 5] = m;
    __syncthreads();
    if (tid == 0) {
        float t = warp_red[0];
        #pragma unroll
        for (int w = 1; w < 8; ++w) t = fmaxf(t, warp_red[w]);
        bcast = t;
    }
    __syncthreads();
    const float rowmax = bcast;

    float sum = 0.0f;
    #pragma unroll
    for (int i = 0; i < 8; ++i) {
        int k = i * 256 + tid;
        float e = (k <= q) ? expf(vals[i] - rowmax) : 0.0f;
        vals[i] = e;
        sum += e;
    }
    #pragma unroll
    for (int o = 16; o > 0; o >>= 1) sum += __shfl_xor_sync(0xffffffffu, sum, o);
    if ((tid & 31) == 0) warp_red[tid >> 5] = sum;
    __syncthreads();
    if (tid == 0) {
        float t = 0.0f;
        #pragma unroll
        for (int w = 0; w < 8; ++w) t += warp_red[w];
        bcast = t;
    }
    __syncthreads();
    const float inv = 1.0f / bcast;
    #pragma unroll
    for (int i = 0; i < 8; ++i) {
        int k = i * 256 + tid;
        ph[k] = __float2half_rn(vals[i] * inv);
    }
}

// ---------------------------------------------------------------------------
// Kernel 5: O = P V. P k-contig (non-trans A); V n-contig (trans B).
// CTA 128(M) x 128(N) x 64(K). V stage 64x136 halfs. grid (8, 16, 4).
// ---------------------------------------------------------------------------
__device__ __forceinline__ void load_pv(char* st,
    const __half* P, const __half* V, int tid)
{
    __half* s = (__half*)st;
    #pragma unroll
    for (int j = 0; j < 4; ++j) {   // P: 128 rows x 8 chunks
        int idx = j * 256 + tid;
        int r = idx >> 3, c = idx & 7;
        cp16(smem_u32(&s[r * 72 + c * 8]), P + (size_t)r * TLEN + c * 8);
    }
    #pragma unroll
    for (int j = 0; j < 4; ++j) {   // V: 64 rows x 16 chunks
        int idx = j * 256 + tid;
        int r = idx >> 4, c = idx & 15;
        cp16(smem_u32(&s[SB_OFF + r * 136 + c * 8]), V + (size_t)r * DINT + c * 8);
    }
}

__device__ __forceinline__ void frags_pv(const char* st, int lane, int wm, int wn,
                                         int ks, unsigned a[4][4], unsigned bv[2][4])
{
    const __half* sP = (const __half*)st;
    const __half* sV = sP + SB_OFF;
    const int lrA  = (lane & 7) + ((lane >> 3) & 1) * 8;
    const int kbA  = ks * 16 + (lane >> 4) * 8;
    const int kbV  = ks * 16 + (lane & 7) + ((lane >> 4) & 1) * 8;
    const int lcV8 = ((lane >> 3) & 1) * 8;
    #pragma unroll
    for (int mf = 0; mf < 4; ++mf) {
        int row = wm * 64 + mf * 16 + lrA;
        ldm_x4(smem_u32(&sP[row * 72 + kbA]), a[mf][0], a[mf][1], a[mf][2], a[mf][3]);
    }
    #pragma unroll
    for (int g = 0; g < 2; ++g) {
        int col = wn * 32 + g * 16 + lcV8;
        ldm_x4_t(smem_u32(&sV[kbV * 136 + col]), bv[g][0], bv[g][1], bv[g][2], bv[g][3]);
    }
}

__global__ __launch_bounds__(256, 2)
void pv_gemm_pipe(float* __restrict__ out) {
    const int b  = blockIdx.z;
    const int q0 = blockIdx.y * 128;
    const int n0 = blockIdx.x * 128;
    extern __shared__ char sm[];

    const __half* P = g_Ph + ((size_t)b * TLEN + q0) * TLEN;
    const __half* V = g_Vh + (size_t)b * TLEN * DINT + n0;
    const int nIter = (q0 + 128) / 64;

    const int tid = threadIdx.x, lane = tid & 31, warp = tid >> 5;
    const int wm = warp >> 2, wn = warp & 3;

    float acc[4][4][4] = {};

    load_pv(sm, P, V, tid);
    cp_commit();
    if (nIter > 1) {
        load_pv(sm + STG_PV, P + 64, V + (size_t)64 * DINT, tid);
        cp_commit();
        cp_wait<1>();
    } else {
        cp_wait<0>();
    }
    __syncthreads();

    unsigned f0[4][4], g0[2][4], f1[4][4], g1[2][4];
    frags_pv(sm, lane, wm, wn, 0, f0, g0);

    for (int i = 0; i < nIter; ++i) {
        const char* cur = sm + (i % NSTG) * STG_PV;
        frags_pv(cur, lane, wm, wn, 1, f1, g1);
        mma_tile(f0, g0, acc);
        frags_pv(cur, lane, wm, wn, 2, f0, g0);
        mma_tile(f1, g1, acc);
        frags_pv(cur, lane, wm, wn, 3, f1, g1);
        mma_tile(f0, g0, acc);
        if (i + 2 < nIter) {
            load_pv(sm + ((i + 2) % NSTG) * STG_PV,
                    P + (i + 2) * 64, V + (size_t)(i + 2) * 64 * DINT, tid);
            cp_commit();
        }
        if (i + 1 < nIter) {
            if (i + 2 < nIter) cp_wait<1>(); else cp_wait<0>();
            __syncthreads();
            frags_pv(sm + ((i + 1) % NSTG) * STG_PV, lane, wm, wn, 0, f0, g0);
        }
        mma_tile(f1, g1, acc);
    }

    #pragma unroll
    for (int mf = 0; mf < 4; ++mf)
        #pragma unroll
        for (int nf = 0; nf < 4; ++nf) {
            int q = q0 + wm * 64 + mf * 16 + (lane >> 2);
            int c = n0 + wn * 32 + nf * 8 + (lane & 3) * 2;
            *(float2*)&out[((size_t)(b * TLEN + q)) * DINT + c] =
                make_float2(acc[mf][nf][0], acc[mf][nf][1]);
            *(float2*)&out[((size_t)(b * TLEN + q + 8)) * DINT + c] =
                make_float2(acc[mf][nf][2], acc[mf][nf][3]);
        }
}

// ---------------------------------------------------------------------------
// Launch
// ---------------------------------------------------------------------------
extern "C" void kernel_launch(void* const* d_in, const int* in_sizes, int n_in,
                              void* d_out, int out_size) {
    (void)n_in; (void)out_size; (void)in_sizes;
    const float* input_vecs = (const float*)d_in[0];
    const float* qkv_w      = (const float*)d_in[1];
    const float* sqk        = (const float*)d_in[2];
    float* out              = (float*)d_out;

    const float sqk_mul = sqrtf((float)DMODEL);
    const float scale   = sqrtf((float)DMODEL);
    const int DSMEM_TN = NSTG * STG_TN;   // 110592
    const int DSMEM_PV = NSTG * STG_PV;   // 107520

    cudaFuncSetAttribute(qkv_gemm_pipe, cudaFuncAttributeMaxDynamicSharedMemorySize, DSMEM_TN);
    cudaFuncSetAttribute(qk_gemm_pipe,  cudaFuncAttributeMaxDynamicSharedMemorySize, DSMEM_TN);
    cudaFuncSetAttribute(pv_gemm_pipe,  cudaFuncAttributeMaxDynamicSharedMemorySize, DSMEM_PV);

    init_freq_kernel<<<2, 256>>>();

    __half2 *xh, *wh;
    cudaGetSymbolAddress((void**)&xh, g_Xh);
    cudaGetSymbolAddress((void**)&wh, g_Wh);
    int nx2 = MTOT * DMODEL / 2, nw2 = 3 * DINT * DMODEL / 2;
    cvt_kernel<<<(nx2 + 255) / 256, 256>>>((const float2*)input_vecs, xh, nx2);
    cvt_kernel<<<(nw2 + 255) / 256, 256>>>((const float2*)qkv_w, wh, nw2);

    qkv_gemm_pipe<<<dim3(3 * DINT / 128, MTOT / 128), 256, DSMEM_TN>>>();

    rope_norm_kernel<<<dim3(MTOT, 2), 256>>>(sqk, sqk_mul);

    qk_gemm_pipe<<<dim3(TLEN / 128, TLEN / 128, BATCH), 256, DSMEM_TN>>>(scale);

    softmax_kernel<<<dim3(TLEN, BATCH), 256>>>();

    pv_gemm_pipe<<<dim3(DINT / 128, TLEN / 128, BATCH), 256, DSMEM_PV>>>(out);
}

// round 14
// speedup vs baseline: 3.2185x; 1.0072x over previous
#include <cuda_runtime.h>
#include <cuda_fp16.h>
#include <math.h>

#define BATCH 4
#define TLEN  2048
#define DMODEL 1024
#define DINT   1024
#define MTOT  (BATCH * TLEN)     // 8192
#define HALFD (DINT / 2)         // 512

// ---------------------------------------------------------------------------
// Scratch (device globals; no allocation allowed)
// ---------------------------------------------------------------------------
__device__ float g_Q[MTOT * DINT];                 // f32 (rope input)
__device__ float g_K[MTOT * DINT];
__device__ float g_S[BATCH * TLEN * TLEN];         // scores f32
__device__ __half g_Qh[MTOT * DINT];               // post-rope fp16
__device__ __half g_Kh[MTOT * DINT];
__device__ __half g_Vh[MTOT * DINT];
__device__ __half g_Ph[BATCH * TLEN * TLEN];       // probs fp16
__device__ __half g_Xh[MTOT * DMODEL];
__device__ __half g_Wh[3 * DINT * DMODEL];
__device__ float g_invfreq[HALFD];

// ---------------------------------------------------------------------------
// Helpers
// ---------------------------------------------------------------------------
__device__ __forceinline__ unsigned smem_u32(const void* p) {
    return (unsigned)__cvta_generic_to_shared(p);
}
__device__ __forceinline__ void cp16(unsigned dst, const void* src) {
    asm volatile("cp.async.cg.shared.global [%0], [%1], 16;" :: "r"(dst), "l"(src));
}
__device__ __forceinline__ void cp_commit() {
    asm volatile("cp.async.commit_group;");
}
template <int N>
__device__ __forceinline__ void cp_wait() {
    asm volatile("cp.async.wait_group %0;" :: "n"(N));
}
__device__ __forceinline__ void ldm_x4(unsigned a, unsigned& r0, unsigned& r1,
                                       unsigned& r2, unsigned& r3) {
    asm volatile("ldmatrix.sync.aligned.m8n8.x4.shared.b16 {%0,%1,%2,%3}, [%4];"
                 : "=r"(r0), "=r"(r1), "=r"(r2), "=r"(r3) : "r"(a));
}
__device__ __forceinline__ void ldm_x4_t(unsigned a, unsigned& r0, unsigned& r1,
                                         unsigned& r2, unsigned& r3) {
    asm volatile("ldmatrix.sync.aligned.m8n8.x4.trans.shared.b16 {%0,%1,%2,%3}, [%4];"
                 : "=r"(r0), "=r"(r1), "=r"(r2), "=r"(r3) : "r"(a));
}
__device__ __forceinline__ void mma16816(float* c, const unsigned* a,
                                         unsigned b0, unsigned b1) {
    asm volatile("mma.sync.aligned.m16n8k16.row.col.f32.f16.f16.f32 "
                 "{%0,%1,%2,%3}, {%4,%5,%6,%7}, {%8,%9}, {%0,%1,%2,%3};"
                 : "+f"(c[0]), "+f"(c[1]), "+f"(c[2]), "+f"(c[3])
                 : "r"(a[0]), "r"(a[1]), "r"(a[2]), "r"(a[3]), "r"(b0), "r"(b1));
}

// CTA tile 128(M) x 128(N) x 64(K). 4 warps, warp tile 64x64: wm, wn in {0,1}.
// Stage (halfs): TN: A[128*72] B[128*72]; PV: P[128*72] V[64*136]
#define SB_OFF   (128 * 72)
#define STG_TN   ((128 * 72 + 128 * 72) * 2)   // 36864 B
#define STG_PV   ((128 * 72 + 64 * 136) * 2)   // 35840 B
#define NSTG 3
#define NTHR 128

// ---------------------------------------------------------------------------
// TN loaders / fragment ops (K-stage = 64 halfs = 8 x 16B chunks per row)
// ---------------------------------------------------------------------------
__device__ __forceinline__ void load_tn(char* st,
    const __half* A, int strideA, const __half* B, int strideB, int tid)
{
    __half* s = (__half*)st;
    #pragma unroll
    for (int j = 0; j < 8; ++j) {   // A: 128 rows x 8 chunks = 1024
        int idx = j * NTHR + tid;
        int r = idx >> 3, c = idx & 7;
        cp16(smem_u32(&s[r * 72 + c * 8]), A + (size_t)r * strideA + c * 8);
    }
    #pragma unroll
    for (int j = 0; j < 8; ++j) {   // B: 128 rows x 8 chunks
        int idx = j * NTHR + tid;
        int r = idx >> 3, c = idx & 7;
        cp16(smem_u32(&s[SB_OFF + r * 72 + c * 8]), B + (size_t)r * strideB + c * 8);
    }
}

__device__ __forceinline__ void frags_tn(const char* st, int lane, int wm, int wn,
                                         int ks, unsigned a[4][4], unsigned b[4][4])
{
    const __half* sA = (const __half*)st;
    const __half* sB = sA + SB_OFF;
    const int lr  = (lane & 7) + ((lane >> 3) & 1) * 8;
    const int kb  = ks * 16 + (lane >> 4) * 8;
    #pragma unroll
    for (int mf = 0; mf < 4; ++mf) {
        int row = wm * 64 + mf * 16 + lr;
        ldm_x4(smem_u32(&sA[row * 72 + kb]), a[mf][0], a[mf][1], a[mf][2], a[mf][3]);
    }
    #pragma unroll
    for (int g = 0; g < 4; ++g) {
        int row = wn * 64 + g * 16 + lr;
        ldm_x4(smem_u32(&sB[row * 72 + kb]), b[g][0], b[g][1], b[g][2], b[g][3]);
    }
}

__device__ __forceinline__ void mma_tile(unsigned a[4][4], unsigned b[4][4],
                                         float acc[4][8][4])
{
    #pragma unroll
    for (int mf = 0; mf < 4; ++mf)
        #pragma unroll
        for (int nf = 0; nf < 8; ++nf) {
            int g = nf >> 1, sdx = nf & 1;
            mma16816(acc[mf][nf], a[mf], b[g][sdx], b[g][sdx + 2]);
        }
}

// Mainloop: 64-k stages, one barrier per stage, register fragment double-buffer.
__device__ __forceinline__ void pipe_tn(
    const __half* A, int strideA, const __half* B, int strideB,
    int nIter, char* sm, float acc[4][8][4])
{
    const int tid = threadIdx.x, lane = tid & 31, warp = tid >> 5;
    const int wm = warp >> 1, wn = warp & 1;

    load_tn(sm, A, strideA, B, strideB, tid);
    cp_commit();
    if (nIter > 1) {
        load_tn(sm + STG_TN, A + 64, strideA, B + 64, strideB, tid);
        cp_commit();
        cp_wait<1>();
    } else {
        cp_wait<0>();
    }
    __syncthreads();

    unsigned f0[4][4], g0[4][4], f1[4][4], g1[4][4];
    frags_tn(sm, lane, wm, wn, 0, f0, g0);

    for (int i = 0; i < nIter; ++i) {
        const char* cur = sm + (i % NSTG) * STG_TN;
        frags_tn(cur, lane, wm, wn, 1, f1, g1);
        mma_tile(f0, g0, acc);
        frags_tn(cur, lane, wm, wn, 2, f0, g0);
        mma_tile(f1, g1, acc);
        frags_tn(cur, lane, wm, wn, 3, f1, g1);
        mma_tile(f0, g0, acc);
        if (i + 2 < nIter) {
            load_tn(sm + ((i + 2) % NSTG) * STG_TN,
                    A + (i + 2) * 64, strideA, B + (i + 2) * 64, strideB, tid);
            cp_commit();
        }
        if (i + 1 < nIter) {
            if (i + 2 < nIter) cp_wait<1>(); else cp_wait<0>();
            __syncthreads();
            frags_tn(sm + ((i + 1) % NSTG) * STG_TN, lane, wm, wn, 0, f0, g0);
        }
        mma_tile(f1, g1, acc);
    }
    __syncthreads();
}

// ---------------------------------------------------------------------------
// init + fp16 conversion
// ---------------------------------------------------------------------------
__global__ void init_freq_kernel() {
    int p = blockIdx.x * blockDim.x + threadIdx.x;
    if (p < HALFD) {
        double e = exp(-((double)(2 * p) / (double)DINT) * 9.210340371976184);
        g_invfreq[p] = (float)e;
    }
}

__global__ __launch_bounds__(256)
void cvt_kernel(const float2* __restrict__ src, __half2* __restrict__ dst, int n2) {
    int i = blockIdx.x * blockDim.x + threadIdx.x;
    if (i < n2) {
        float2 v = src[i];
        dst[i] = __float22half2_rn(v);
    }
}

// ---------------------------------------------------------------------------
// Kernel 1: QKV GEMM. M=8192, N=3072, K=1024. Q,K -> f32; V -> fp16.
// ---------------------------------------------------------------------------
__global__ __launch_bounds__(NTHR, 2)
void qkv_gemm_pipe() {
    extern __shared__ char sm[];
    const int m0 = blockIdx.y * 128, n0 = blockIdx.x * 128;
    float acc[4][8][4] = {};
    pipe_tn(g_Xh + (size_t)m0 * DMODEL, DMODEL,
            g_Wh + (size_t)n0 * DMODEL, DMODEL, DMODEL / 64, sm, acc);

    const int tid = threadIdx.x, lane = tid & 31, warp = tid >> 5;
    const int wm = warp >> 1, wn = warp & 1;
    if (n0 < 2 * DINT) {
        float* dst = (n0 < DINT) ? g_Q : g_K;
        int nb = (n0 < DINT) ? n0 : n0 - DINT;
        #pragma unroll
        for (int mf = 0; mf < 4; ++mf)
            #pragma unroll
            for (int nf = 0; nf < 8; ++nf) {
                int r = m0 + wm * 64 + mf * 16 + (lane >> 2);
                int c = nb + wn * 64 + nf * 8 + (lane & 3) * 2;
                *(float2*)&dst[(size_t)r * DINT + c]       = make_float2(acc[mf][nf][0], acc[mf][nf][1]);
                *(float2*)&dst[(size_t)(r + 8) * DINT + c] = make_float2(acc[mf][nf][2], acc[mf][nf][3]);
            }
    } else {
        int nb = n0 - 2 * DINT;
        #pragma unroll
        for (int mf = 0; mf < 4; ++mf)
            #pragma unroll
            for (int nf = 0; nf < 8; ++nf) {
                int r = m0 + wm * 64 + mf * 16 + (lane >> 2);
                int c = nb + wn * 64 + nf * 8 + (lane & 3) * 2;
                *(__half2*)&g_Vh[(size_t)r * DINT + c] =
                    __float22half2_rn(make_float2(acc[mf][nf][0], acc[mf][nf][1]));
                *(__half2*)&g_Vh[(size_t)(r + 8) * DINT + c] =
                    __float22half2_rn(make_float2(acc[mf][nf][2], acc[mf][nf][3]));
            }
    }
}

// ---------------------------------------------------------------------------
// Kernel 2: RoPE + L2 norm + scale; writes fp16 Q,K.
// ---------------------------------------------------------------------------
__global__ __launch_bounds__(256)
void rope_norm_kernel(const float* __restrict__ sqk, float sqk_mul) {
    const int token = blockIdx.x;
    const int tpos = token & (TLEN - 1);
    const bool isQ = (blockIdx.y == 0);
    const float* row = (isQ ? g_Q : g_K) + (size_t)token * DINT;
    __half* outh = (isQ ? g_Qh : g_Kh) + (size_t)token * DINT;

    const int tid = threadIdx.x;
    float na[2], nb[2];
    float ss = 0.0f;
    #pragma unroll
    for (int h = 0; h < 2; ++h) {
        int p = tid + h * 256;
        float a = row[p];
        float b = row[p + HALFD];
        float ang = (float)tpos * g_invfreq[p];
        float s, c;
        sincosf(ang, &s, &c);
        na[h] = a * c - b * s;
        nb[h] = b * c + a * s;
        ss += na[h] * na[h] + nb[h] * nb[h];
    }
    __shared__ float warp_red[8];
    #pragma unroll
    for (int o = 16; o > 0; o >>= 1) ss += __shfl_xor_sync(0xffffffffu, ss, o);
    if ((tid & 31) == 0) warp_red[tid >> 5] = ss;
    __syncthreads();
    __shared__ float total_sh;
    if (tid == 0) {
        float t = 0.0f;
        #pragma unroll
        for (int w = 0; w < 8; ++w) t += warp_red[w];
        total_sh = t;
    }
    __syncthreads();
    float rnorm = 1.0f / sqrtf(total_sh);
    #pragma unroll
    for (int h = 0; h < 2; ++h) {
        int p = tid + h * 256;
        float va = na[h] * rnorm * (sqk[p] * sqk_mul);
        float vb = nb[h] * rnorm * (sqk[p + HALFD] * sqk_mul);
        outh[p]         = __float2half_rn(va);
        outh[p + HALFD] = __float2half_rn(vb);
    }
}

// ---------------------------------------------------------------------------
// Kernel 3: scores S = scale * Q K^T. grid (16, 16, 4), triangular skip.
// ---------------------------------------------------------------------------
__global__ __launch_bounds__(NTHR, 2)
void qk_gemm_pipe(float scale) {
    const int b  = blockIdx.z;
    const int q0 = blockIdx.y * 128;
    const int k0n = blockIdx.x * 128;
    if (k0n > q0) return;                      // tile fully above diagonal
    extern __shared__ char sm[];

    float acc[4][8][4] = {};
    pipe_tn(g_Qh + ((size_t)b * TLEN + q0) * DINT, DINT,
            g_Kh + ((size_t)b * TLEN + k0n) * DINT, DINT, DINT / 64, sm, acc);

    float* S = g_S + (size_t)b * TLEN * TLEN;
    const int tid = threadIdx.x, lane = tid & 31, warp = tid >> 5;
    const int wm = warp >> 1, wn = warp & 1;
    #pragma unroll
    for (int mf = 0; mf < 4; ++mf)
        #pragma unroll
        for (int nf = 0; nf < 8; ++nf) {
            int q = q0 + wm * 64 + mf * 16 + (lane >> 2);
            int c = k0n + wn * 64 + nf * 8 + (lane & 3) * 2;
            *(float2*)&S[(size_t)q * TLEN + c] =
                make_float2(acc[mf][nf][0] * scale, acc[mf][nf][1] * scale);
            *(float2*)&S[(size_t)(q + 8) * TLEN + c] =
                make_float2(acc[mf][nf][2] * scale, acc[mf][nf][3] * scale);
        }
}

// ---------------------------------------------------------------------------
// Kernel 4: causal softmax; writes fp16 P (exact zeros above diagonal).
// ---------------------------------------------------------------------------
__global__ __launch_bounds__(256)
void softmax_kernel() {
    const int q = blockIdx.x;
    const int b = blockIdx.y;
    const float* row = g_S + ((size_t)b * TLEN + q) * TLEN;
    __half* ph = g_Ph + ((size_t)b * TLEN + q) * TLEN;
    const int tid = threadIdx.x;

    float vals[8];
    float m = -INFINITY;
    #pragma unroll
    for (int i = 0; i < 8; ++i) {
        int k = i * 256 + tid;
        float v = (k <= q) ? row[k] : -INFINITY;
        vals[i] = v;
        m = fmaxf(m, v);
    }
    __shared__ float warp_red[8];
    __shared__ float bcast;
    #pragma unroll
    for (int o = 16; o > 0; o >>= 1) m = fmaxf(m, __shfl_xor_sync(0xffffffffu, m, o));
    if ((tid & 31) == 0) warp_red[tid >> 5] = m;
    __syncthreads();
    if (tid == 0) {
        float t = warp_red[0];
        #pragma unroll
        for (int w = 1; w < 8; ++w) t = fmaxf(t, warp_red[w]);
        bcast = t;
    }
    __syncthreads();
    const float rowmax = bcast;

    float sum = 0.0f;
    #pragma unroll
    for (int i = 0; i < 8; ++i) {
        int k = i * 256 + tid;
        float e = (k <= q) ? expf(vals[i] - rowmax) : 0.0f;
        vals[i] = e;
        sum += e;
    }
    #pragma unroll
    for (int o = 16; o > 0; o >>= 1) sum += __shfl_xor_sync(0xffffffffu, sum, o);
    if ((tid & 31) == 0) warp_red[tid >> 5] = sum;
    __syncthreads();
    if (tid == 0) {
        float t = 0.0f;
        #pragma unroll
        for (int w = 0; w < 8; ++w) t += warp_red[w];
        bcast = t;
    }
    __syncthreads();
    const float inv = 1.0f / bcast;
    #pragma unroll
    for (int i = 0; i < 8; ++i) {
        int k = i * 256 + tid;
        ph[k] = __float2half_rn(vals[i] * inv);
    }
}

// ---------------------------------------------------------------------------
// Kernel 5: O = P V. P k-contig (non-trans A); V n-contig (trans B).
// CTA 128(M) x 128(N) x 64(K), 4 warps 64x64. grid (8, 16, 4).
// ---------------------------------------------------------------------------
__device__ __forceinline__ void load_pv(char* st,
    const __half* P, const __half* V, int tid)
{
    __half* s = (__half*)st;
    #pragma unroll
    for (int j = 0; j < 8; ++j) {   // P: 128 rows x 8 chunks
        int idx = j * NTHR + tid;
        int r = idx >> 3, c = idx & 7;
        cp16(smem_u32(&s[r * 72 + c * 8]), P + (size_t)r * TLEN + c * 8);
    }
    #pragma unroll
    for (int j = 0; j < 8; ++j) {   // V: 64 rows x 16 chunks
        int idx = j * NTHR + tid;
        int r = idx >> 4, c = idx & 15;
        cp16(smem_u32(&s[SB_OFF + r * 136 + c * 8]), V + (size_t)r * DINT + c * 8);
    }
}

__device__ __forceinline__ void frags_pv(const char* st, int lane, int wm, int wn,
                                         int ks, unsigned a[4][4], unsigned bv[4][4])
{
    const __half* sP = (const __half*)st;
    const __half* sV = sP + SB_OFF;
    const int lrA  = (lane & 7) + ((lane >> 3) & 1) * 8;
    const int kbA  = ks * 16 + (lane >> 4) * 8;
    const int kbV  = ks * 16 + (lane & 7) + ((lane >> 4) & 1) * 8;
    const int lcV8 = ((lane >> 3) & 1) * 8;
    #pragma unroll
    for (int mf = 0; mf < 4; ++mf) {
        int row = wm * 64 + mf * 16 + lrA;
        ldm_x4(smem_u32(&sP[row * 72 + kbA]), a[mf][0], a[mf][1], a[mf][2], a[mf][3]);
    }
    #pragma unroll
    for (int g = 0; g < 4; ++g) {
        int col = wn * 64 + g * 16 + lcV8;
        ldm_x4_t(smem_u32(&sV[kbV * 136 + col]), bv[g][0], bv[g][1], bv[g][2], bv[g][3]);
    }
}

__global__ __launch_bounds__(NTHR, 2)
void pv_gemm_pipe(float* __restrict__ out) {
    const int b  = blockIdx.z;
    const int q0 = blockIdx.y * 128;
    const int n0 = blockIdx.x * 128;
    extern __shared__ char sm[];

    const __half* P = g_Ph + ((size_t)b * TLEN + q0) * TLEN;
    const __half* V = g_Vh + (size_t)b * TLEN * DINT + n0;
    const int nIter = (q0 + 128) / 64;

    const int tid = threadIdx.x, lane = tid & 31, warp = tid >> 5;
    const int wm = warp >> 1, wn = warp & 1;

    float acc[4][8][4] = {};

    load_pv(sm, P, V, tid);
    cp_commit();
    if (nIter > 1) {
        load_pv(sm + STG_PV, P + 64, V + (size_t)64 * DINT, tid);
        cp_commit();
        cp_wait<1>();
    } else {
        cp_wait<0>();
    }
    __syncthreads();

    unsigned f0[4][4], g0[4][4], f1[4][4], g1[4][4];
    frags_pv(sm, lane, wm, wn, 0, f0, g0);

    for (int i = 0; i < nIter; ++i) {
        const char* cur = sm + (i % NSTG) * STG_PV;
        frags_pv(cur, lane, wm, wn, 1, f1, g1);
        mma_tile(f0, g0, acc);
        frags_pv(cur, lane, wm, wn, 2, f0, g0);
        mma_tile(f1, g1, acc);
        frags_pv(cur, lane, wm, wn, 3, f1, g1);
        mma_tile(f0, g0, acc);
        if (i + 2 < nIter) {
            load_pv(sm + ((i + 2) % NSTG) * STG_PV,
                    P + (i + 2) * 64, V + (size_t)(i + 2) * 64 * DINT, tid);
            cp_commit();
        }
        if (i + 1 < nIter) {
            if (i + 2 < nIter) cp_wait<1>(); else cp_wait<0>();
            __syncthreads();
            frags_pv(sm + ((i + 1) % NSTG) * STG_PV, lane, wm, wn, 0, f0, g0);
        }
        mma_tile(f1, g1, acc);
    }

    #pragma unroll
    for (int mf = 0; mf < 4; ++mf)
        #pragma unroll
        for (int nf = 0; nf < 8; ++nf) {
            int q = q0 + wm * 64 + mf * 16 + (lane >> 2);
            int c = n0 + wn * 64 + nf * 8 + (lane & 3) * 2;
            *(float2*)&out[((size_t)(b * TLEN + q)) * DINT + c] =
                make_float2(acc[mf][nf][0], acc[mf][nf][1]);
            *(float2*)&out[((size_t)(b * TLEN + q + 8)) * DINT + c] =
                make_float2(acc[mf][nf][2], acc[mf][nf][3]);
        }
}

// ---------------------------------------------------------------------------
// Launch
// ---------------------------------------------------------------------------
extern "C" void kernel_launch(void* const* d_in, const int* in_sizes, int n_in,
                              void* d_out, int out_size) {
    (void)n_in; (void)out_size; (void)in_sizes;
    const float* input_vecs = (const float*)d_in[0];
    const float* qkv_w      = (const float*)d_in[1];
    const float* sqk        = (const float*)d_in[2];
    float* out              = (float*)d_out;

    const float sqk_mul = sqrtf((float)DMODEL);
    const float scale   = sqrtf((float)DMODEL);
    const int DSMEM_TN = NSTG * STG_TN;   // 110592
    const int DSMEM_PV = NSTG * STG_PV;   // 107520

    cudaFuncSetAttribute(qkv_gemm_pipe, cudaFuncAttributeMaxDynamicSharedMemorySize, DSMEM_TN);
    cudaFuncSetAttribute(qk_gemm_pipe,  cudaFuncAttributeMaxDynamicSharedMemorySize, DSMEM_TN);
    cudaFuncSetAttribute(pv_gemm_pipe,  cudaFuncAttributeMaxDynamicSharedMemorySize, DSMEM_PV);

    init_freq_kernel<<<2, 256>>>();

    __half2 *xh, *wh;
    cudaGetSymbolAddress((void**)&xh, g_Xh);
    cudaGetSymbolAddress((void**)&wh, g_Wh);
    int nx2 = MTOT * DMODEL / 2, nw2 = 3 * DINT * DMODEL / 2;
    cvt_kernel<<<(nx2 + 255) / 256, 256>>>((const float2*)input_vecs, xh, nx2);
    cvt_kernel<<<(nw2 + 255) / 256, 256>>>((const float2*)qkv_w, wh, nw2);

    qkv_gemm_pipe<<<dim3(3 * DINT / 128, MTOT / 128), NTHR, DSMEM_TN>>>();

    rope_norm_kernel<<<dim3(MTOT, 2), 256>>>(sqk, sqk_mul);

    qk_gemm_pipe<<<dim3(TLEN / 128, TLEN / 128, BATCH), NTHR, DSMEM_TN>>>(scale);

    softmax_kernel<<<dim3(TLEN, BATCH), 256>>>();

    pv_gemm_pipe<<<dim3(DINT / 128, TLEN / 128, BATCH), NTHR, DSMEM_PV>>>(out);
}

// round 15
// speedup vs baseline: 3.3089x; 1.0281x over previous
#include <cuda_runtime.h>
#include <cuda_fp16.h>
#include <math.h>

#define BATCH 4
#define TLEN  2048
#define DMODEL 1024
#define DINT   1024
#define MTOT  (BATCH * TLEN)     // 8192
#define HALFD (DINT / 2)         // 512

// ---------------------------------------------------------------------------
// Scratch (device globals; no allocation allowed)
// ---------------------------------------------------------------------------
__device__ float g_Q[MTOT * DINT];                 // f32 (rope input)
__device__ float g_K[MTOT * DINT];
__device__ float g_S[BATCH * TLEN * TLEN];         // scores f32
__device__ __half g_Qh[MTOT * DINT];               // post-rope fp16
__device__ __half g_Kh[MTOT * DINT];
__device__ __half g_Vh[MTOT * DINT];
__device__ __half g_Ph[BATCH * TLEN * TLEN];       // probs fp16
__device__ __half g_Xh[MTOT * DMODEL];
__device__ __half g_Wh[3 * DINT * DMODEL];
__device__ float g_invfreq[HALFD];

// ---------------------------------------------------------------------------
// Helpers
// ---------------------------------------------------------------------------
__device__ __forceinline__ unsigned smem_u32(const void* p) {
    return (unsigned)__cvta_generic_to_shared(p);
}
__device__ __forceinline__ void cp16(unsigned dst, const void* src) {
    asm volatile("cp.async.cg.shared.global [%0], [%1], 16;" :: "r"(dst), "l"(src));
}
__device__ __forceinline__ void cp_commit() {
    asm volatile("cp.async.commit_group;");
}
template <int N>
__device__ __forceinline__ void cp_wait() {
    asm volatile("cp.async.wait_group %0;" :: "n"(N));
}
__device__ __forceinline__ void ldm_x4(unsigned a, unsigned& r0, unsigned& r1,
                                       unsigned& r2, unsigned& r3) {
    asm volatile("ldmatrix.sync.aligned.m8n8.x4.shared.b16 {%0,%1,%2,%3}, [%4];"
                 : "=r"(r0), "=r"(r1), "=r"(r2), "=r"(r3) : "r"(a));
}
__device__ __forceinline__ void ldm_x4_t(unsigned a, unsigned& r0, unsigned& r1,
                                         unsigned& r2, unsigned& r3) {
    asm volatile("ldmatrix.sync.aligned.m8n8.x4.trans.shared.b16 {%0,%1,%2,%3}, [%4];"
                 : "=r"(r0), "=r"(r1), "=r"(r2), "=r"(r3) : "r"(a));
}
__device__ __forceinline__ void mma16816(float* c, const unsigned* a,
                                         unsigned b0, unsigned b1) {
    asm volatile("mma.sync.aligned.m16n8k16.row.col.f32.f16.f16.f32 "
                 "{%0,%1,%2,%3}, {%4,%5,%6,%7}, {%8,%9}, {%0,%1,%2,%3};"
                 : "+f"(c[0]), "+f"(c[1]), "+f"(c[2]), "+f"(c[3])
                 : "r"(a[0]), "r"(a[1]), "r"(a[2]), "r"(a[3]), "r"(b0), "r"(b1));
}

// CTA tile 128(M) x 128(N) x 64(K). 4 warps, warp tile 64x64: wm, wn in {0,1}.
// Stage (halfs): TN: A[128*72] B[128*72]; PV: P[128*72] V[64*136]
#define SB_OFF   (128 * 72)
#define STG_TN   ((128 * 72 + 128 * 72) * 2)   // 36864 B
#define STG_PV   ((128 * 72 + 64 * 136) * 2)   // 35840 B
#define NSTG 3
#define NTHR 128

// ---------------------------------------------------------------------------
// TN loaders / fragment ops (K-stage = 64 halfs = 8 x 16B chunks per row)
// ---------------------------------------------------------------------------
__device__ __forceinline__ void load_tn(char* st,
    const __half* A, int strideA, const __half* B, int strideB, int tid)
{
    __half* s = (__half*)st;
    #pragma unroll
    for (int j = 0; j < 8; ++j) {   // A: 128 rows x 8 chunks = 1024
        int idx = j * NTHR + tid;
        int r = idx >> 3, c = idx & 7;
        cp16(smem_u32(&s[r * 72 + c * 8]), A + (size_t)r * strideA + c * 8);
    }
    #pragma unroll
    for (int j = 0; j < 8; ++j) {   // B: 128 rows x 8 chunks
        int idx = j * NTHR + tid;
        int r = idx >> 3, c = idx & 7;
        cp16(smem_u32(&s[SB_OFF + r * 72 + c * 8]), B + (size_t)r * strideB + c * 8);
    }
}

__device__ __forceinline__ void frags_tn(const char* st, int lane, int wm, int wn,
                                         int ks, unsigned a[4][4], unsigned b[4][4])
{
    const __half* sA = (const __half*)st;
    const __half* sB = sA + SB_OFF;
    const int lr  = (lane & 7) + ((lane >> 3) & 1) * 8;
    const int kb  = ks * 16 + (lane >> 4) * 8;
    #pragma unroll
    for (int mf = 0; mf < 4; ++mf) {
        int row = wm * 64 + mf * 16 + lr;
        ldm_x4(smem_u32(&sA[row * 72 + kb]), a[mf][0], a[mf][1], a[mf][2], a[mf][3]);
    }
    #pragma unroll
    for (int g = 0; g < 4; ++g) {
        int row = wn * 64 + g * 16 + lr;
        ldm_x4(smem_u32(&sB[row * 72 + kb]), b[g][0], b[g][1], b[g][2], b[g][3]);
    }
}

__device__ __forceinline__ void mma_tile(unsigned a[4][4], unsigned b[4][4],
                                         float acc[4][8][4])
{
    #pragma unroll
    for (int mf = 0; mf < 4; ++mf)
        #pragma unroll
        for (int nf = 0; nf < 8; ++nf) {
            int g = nf >> 1, sdx = nf & 1;
            mma16816(acc[mf][nf], a[mf], b[g][sdx], b[g][sdx + 2]);
        }
}

// Mainloop: 64-k stages, one barrier per stage, register fragment double-buffer.
// Stage indices maintained incrementally (no % in the hot loop).
__device__ __forceinline__ void pipe_tn(
    const __half* A, int strideA, const __half* B, int strideB,
    int nIter, char* sm, float acc[4][8][4])
{
    const int tid = threadIdx.x, lane = tid & 31, warp = tid >> 5;
    const int wm = warp >> 1, wn = warp & 1;

    load_tn(sm, A, strideA, B, strideB, tid);
    cp_commit();
    if (nIter > 1) {
        load_tn(sm + STG_TN, A + 64, strideA, B + 64, strideB, tid);
        cp_commit();
        cp_wait<1>();
    } else {
        cp_wait<0>();
    }
    __syncthreads();

    unsigned f0[4][4], g0[4][4], f1[4][4], g1[4][4];
    frags_tn(sm, lane, wm, wn, 0, f0, g0);

    int sc = 0;                                   // i % NSTG
    for (int i = 0; i < nIter; ++i) {
        const char* cur = sm + sc * STG_TN;
        int s1 = sc + 1; if (s1 == NSTG) s1 = 0;  // (i+1) % NSTG
        int s2 = s1 + 1; if (s2 == NSTG) s2 = 0;  // (i+2) % NSTG
        frags_tn(cur, lane, wm, wn, 1, f1, g1);
        mma_tile(f0, g0, acc);
        frags_tn(cur, lane, wm, wn, 2, f0, g0);
        mma_tile(f1, g1, acc);
        frags_tn(cur, lane, wm, wn, 3, f1, g1);
        mma_tile(f0, g0, acc);
        if (i + 2 < nIter) {
            load_tn(sm + s2 * STG_TN,
                    A + (i + 2) * 64, strideA, B + (i + 2) * 64, strideB, tid);
            cp_commit();
        }
        if (i + 1 < nIter) {
            if (i + 2 < nIter) cp_wait<1>(); else cp_wait<0>();
            __syncthreads();
            frags_tn(sm + s1 * STG_TN, lane, wm, wn, 0, f0, g0);
        }
        mma_tile(f1, g1, acc);
        sc = s1;
    }
    __syncthreads();
}

// ---------------------------------------------------------------------------
// init + fp16 conversion (float4 -> 2x half2)
// ---------------------------------------------------------------------------
__global__ void init_freq_kernel() {
    int p = blockIdx.x * blockDim.x + threadIdx.x;
    if (p < HALFD) {
        double e = exp(-((double)(2 * p) / (double)DINT) * 9.210340371976184);
        g_invfreq[p] = (float)e;
    }
}

__global__ __launch_bounds__(256)
void cvt_kernel(const float4* __restrict__ src, uint2* __restrict__ dst, int n4) {
    int i = blockIdx.x * blockDim.x + threadIdx.x;
    if (i < n4) {
        float4 v = src[i];
        __half2 h01 = __float22half2_rn(make_float2(v.x, v.y));
        __half2 h23 = __float22half2_rn(make_float2(v.z, v.w));
        dst[i] = make_uint2(*(unsigned*)&h01, *(unsigned*)&h23);
    }
}

// ---------------------------------------------------------------------------
// Kernel 1: QKV GEMM. M=8192, N=3072, K=1024. Q,K -> f32; V -> fp16.
// ---------------------------------------------------------------------------
__global__ __launch_bounds__(NTHR, 2)
void qkv_gemm_pipe() {
    extern __shared__ char sm[];
    const int m0 = blockIdx.y * 128, n0 = blockIdx.x * 128;
    float acc[4][8][4] = {};
    pipe_tn(g_Xh + (size_t)m0 * DMODEL, DMODEL,
            g_Wh + (size_t)n0 * DMODEL, DMODEL, DMODEL / 64, sm, acc);

    const int tid = threadIdx.x, lane = tid & 31, warp = tid >> 5;
    const int wm = warp >> 1, wn = warp & 1;
    if (n0 < 2 * DINT) {
        float* dst = (n0 < DINT) ? g_Q : g_K;
        int nb = (n0 < DINT) ? n0 : n0 - DINT;
        #pragma unroll
        for (int mf = 0; mf < 4; ++mf)
            #pragma unroll
            for (int nf = 0; nf < 8; ++nf) {
                int r = m0 + wm * 64 + mf * 16 + (lane >> 2);
                int c = nb + wn * 64 + nf * 8 + (lane & 3) * 2;
                *(float2*)&dst[(size_t)r * DINT + c]       = make_float2(acc[mf][nf][0], acc[mf][nf][1]);
                *(float2*)&dst[(size_t)(r + 8) * DINT + c] = make_float2(acc[mf][nf][2], acc[mf][nf][3]);
            }
    } else {
        int nb = n0 - 2 * DINT;
        #pragma unroll
        for (int mf = 0; mf < 4; ++mf)
            #pragma unroll
            for (int nf = 0; nf < 8; ++nf) {
                int r = m0 + wm * 64 + mf * 16 + (lane >> 2);
                int c = nb + wn * 64 + nf * 8 + (lane & 3) * 2;
                *(__half2*)&g_Vh[(size_t)r * DINT + c] =
                    __float22half2_rn(make_float2(acc[mf][nf][0], acc[mf][nf][1]));
                *(__half2*)&g_Vh[(size_t)(r + 8) * DINT + c] =
                    __float22half2_rn(make_float2(acc[mf][nf][2], acc[mf][nf][3]));
            }
    }
}

// ---------------------------------------------------------------------------
// Kernel 2: RoPE + L2 norm + scale; writes fp16 Q,K. Vectorized (2 pairs/thread).
// ---------------------------------------------------------------------------
__global__ __launch_bounds__(256)
void rope_norm_kernel(const float* __restrict__ sqk, float sqk_mul) {
    const int token = blockIdx.x;
    const float tpos = (float)(token & (TLEN - 1));
    const bool isQ = (blockIdx.y == 0);
    const float* row = (isQ ? g_Q : g_K) + (size_t)token * DINT;
    __half* outh = (isQ ? g_Qh : g_Kh) + (size_t)token * DINT;

    const int tid = threadIdx.x;
    const int p2 = tid * 2;                      // pair base: 2 pairs per thread
    float2 A  = *(const float2*)&row[p2];
    float2 Bv = *(const float2*)&row[p2 + HALFD];
    float2 fr = *(const float2*)&g_invfreq[p2];
    float s0, c0, s1, c1;
    sincosf(tpos * fr.x, &s0, &c0);
    sincosf(tpos * fr.y, &s1, &c1);
    float na0 = A.x * c0 - Bv.x * s0, nb0 = Bv.x * c0 + A.x * s0;
    float na1 = A.y * c1 - Bv.y * s1, nb1 = Bv.y * c1 + A.y * s1;
    float ss = na0 * na0 + nb0 * nb0 + na1 * na1 + nb1 * nb1;

    __shared__ float warp_red[8];
    #pragma unroll
    for (int o = 16; o > 0; o >>= 1) ss += __shfl_xor_sync(0xffffffffu, ss, o);
    if ((tid & 31) == 0) warp_red[tid >> 5] = ss;
    __syncthreads();
    __shared__ float total_sh;
    if (tid == 0) {
        float t = 0.0f;
        #pragma unroll
        for (int w = 0; w < 8; ++w) t += warp_red[w];
        total_sh = t;
    }
    __syncthreads();
    const float rnorm = 1.0f / sqrtf(total_sh);

    float2 sq0 = *(const float2*)&sqk[p2];
    float2 sq1 = *(const float2*)&sqk[p2 + HALFD];
    float va0 = na0 * rnorm * (sq0.x * sqk_mul);
    float va1 = na1 * rnorm * (sq0.y * sqk_mul);
    float vb0 = nb0 * rnorm * (sq1.x * sqk_mul);
    float vb1 = nb1 * rnorm * (sq1.y * sqk_mul);
    *(__half2*)&outh[p2]         = __float22half2_rn(make_float2(va0, va1));
    *(__half2*)&outh[p2 + HALFD] = __float22half2_rn(make_float2(vb0, vb1));
}

// ---------------------------------------------------------------------------
// Kernel 3: scores S = scale * Q K^T. grid (16, 16, 4), triangular skip.
// ---------------------------------------------------------------------------
__global__ __launch_bounds__(NTHR, 2)
void qk_gemm_pipe(float scale) {
    const int b  = blockIdx.z;
    const int q0 = blockIdx.y * 128;
    const int k0n = blockIdx.x * 128;
    if (k0n > q0) return;                      // tile fully above diagonal
    extern __shared__ char sm[];

    float acc[4][8][4] = {};
    pipe_tn(g_Qh + ((size_t)b * TLEN + q0) * DINT, DINT,
            g_Kh + ((size_t)b * TLEN + k0n) * DINT, DINT, DINT / 64, sm, acc);

    float* S = g_S + (size_t)b * TLEN * TLEN;
    const int tid = threadIdx.x, lane = tid & 31, warp = tid >> 5;
    const int wm = warp >> 1, wn = warp & 1;
    #pragma unroll
    for (int mf = 0; mf < 4; ++mf)
        #pragma unroll
        for (int nf = 0; nf < 8; ++nf) {
            int q = q0 + wm * 64 + mf * 16 + (lane >> 2);
            int c = k0n + wn * 64 + nf * 8 + (lane & 3) * 2;
            *(float2*)&S[(size_t)q * TLEN + c] =
                make_float2(acc[mf][nf][0] * scale, acc[mf][nf][1] * scale);
            *(float2*)&S[(size_t)(q + 8) * TLEN + c] =
                make_float2(acc[mf][nf][2] * scale, acc[mf][nf][3] * scale);
        }
}

// ---------------------------------------------------------------------------
// Kernel 4: causal softmax; writes fp16 P (exact zeros above diagonal).
// Vectorized: float4 loads, 4-half packed stores.
// ---------------------------------------------------------------------------
__global__ __launch_bounds__(256)
void softmax_kernel() {
    const int q = blockIdx.x;
    const int b = blockIdx.y;
    const float4* row4 = (const float4*)(g_S + ((size_t)b * TLEN + q) * TLEN);
    __half* ph = g_Ph + ((size_t)b * TLEN + q) * TLEN;
    const int tid = threadIdx.x;

    float4 v[2];
    float m = -INFINITY;
    #pragma unroll
    for (int i = 0; i < 2; ++i) {
        int k4 = i * 256 + tid;
        float4 x = row4[k4];
        int k = k4 * 4;
        x.x = (k     <= q) ? x.x : -INFINITY;
        x.y = (k + 1 <= q) ? x.y : -INFINITY;
        x.z = (k + 2 <= q) ? x.z : -INFINITY;
        x.w = (k + 3 <= q) ? x.w : -INFINITY;
        v[i] = x;
        m = fmaxf(m, fmaxf(fmaxf(x.x, x.y), fmaxf(x.z, x.w)));
    }

    __shared__ float warp_red[8];
    __shared__ float bcast;
    #pragma unroll
    for (int o = 16; o > 0; o >>= 1) m = fmaxf(m, __shfl_xor_sync(0xffffffffu, m, o));
    if ((tid & 31) == 0) warp_red[tid >> 5] = m;
    __syncthreads();
    if (tid == 0) {
        float t = warp_red[0];
        #pragma unroll
        for (int w = 1; w < 8; ++w) t = fmaxf(t, warp_red[w]);
        bcast = t;
    }
    __syncthreads();
    const float rowmax = bcast;

    float sum = 0.0f;
    #pragma unroll
    for (int i = 0; i < 2; ++i) {
        float4 x = v[i];
        x.x = expf(x.x - rowmax);       // exp(-INF - m) == 0 exactly
        x.y = expf(x.y - rowmax);
        x.z = expf(x.z - rowmax);
        x.w = expf(x.w - rowmax);
        v[i] = x;
        sum += (x.x + x.y) + (x.z + x.w);
    }
    #pragma unroll
    for (int o = 16; o > 0; o >>= 1) sum += __shfl_xor_sync(0xffffffffu, sum, o);
    if ((tid & 31) == 0) warp_red[tid >> 5] = sum;
    __syncthreads();
    if (tid == 0) {
        float t = 0.0f;
        #pragma unroll
        for (int w = 0; w < 8; ++w) t += warp_red[w];
        bcast = t;
    }
    __syncthreads();
    const float inv = 1.0f / bcast;

    #pragma unroll
    for (int i = 0; i < 2; ++i) {
        int k4 = i * 256 + tid;
        float4 x = v[i];
        __half2 h01 = __float22half2_rn(make_float2(x.x * inv, x.y * inv));
        __half2 h23 = __float22half2_rn(make_float2(x.z * inv, x.w * inv));
        *(uint2*)&ph[k4 * 4] = make_uint2(*(unsigned*)&h01, *(unsigned*)&h23);
    }
}

// ---------------------------------------------------------------------------
// Kernel 5: O = P V. P k-contig (non-trans A); V n-contig (trans B).
// CTA 128(M) x 128(N) x 64(K), 4 warps 64x64. grid (8, 16, 4).
// ---------------------------------------------------------------------------
__device__ __forceinline__ void load_pv(char* st,
    const __half* P, const __half* V, int tid)
{
    __half* s = (__half*)st;
    #pragma unroll
    for (int j = 0; j < 8; ++j) {   // P: 128 rows x 8 chunks
        int idx = j * NTHR + tid;
        int r = idx >> 3, c = idx & 7;
        cp16(smem_u32(&s[r * 72 + c * 8]), P + (size_t)r * TLEN + c * 8);
    }
    #pragma unroll
    for (int j = 0; j < 8; ++j) {   // V: 64 rows x 16 chunks
        int idx = j * NTHR + tid;
        int r = idx >> 4, c = idx & 15;
        cp16(smem_u32(&s[SB_OFF + r * 136 + c * 8]), V + (size_t)r * DINT + c * 8);
    }
}

__device__ __forceinline__ void frags_pv(const char* st, int lane, int wm, int wn,
                                         int ks, unsigned a[4][4], unsigned bv[4][4])
{
    const __half* sP = (const __half*)st;
    const __half* sV = sP + SB_OFF;
    const int lrA  = (lane & 7) + ((lane >> 3) & 1) * 8;
    const int kbA  = ks * 16 + (lane >> 4) * 8;
    const int kbV  = ks * 16 + (lane & 7) + ((lane >> 4) & 1) * 8;
    const int lcV8 = ((lane >> 3) & 1) * 8;
    #pragma unroll
    for (int mf = 0; mf < 4; ++mf) {
        int row = wm * 64 + mf * 16 + lrA;
        ldm_x4(smem_u32(&sP[row * 72 + kbA]), a[mf][0], a[mf][1], a[mf][2], a[mf][3]);
    }
    #pragma unroll
    for (int g = 0; g < 4; ++g) {
        int col = wn * 64 + g * 16 + lcV8;
        ldm_x4_t(smem_u32(&sV[kbV * 136 + col]), bv[g][0], bv[g][1], bv[g][2], bv[g][3]);
    }
}

__global__ __launch_bounds__(NTHR, 2)
void pv_gemm_pipe(float* __restrict__ out) {
    const int b  = blockIdx.z;
    const int q0 = blockIdx.y * 128;
    const int n0 = blockIdx.x * 128;
    extern __shared__ char sm[];

    const __half* P = g_Ph + ((size_t)b * TLEN + q0) * TLEN;
    const __half* V = g_Vh + (size_t)b * TLEN * DINT + n0;
    const int nIter = (q0 + 128) / 64;

    const int tid = threadIdx.x, lane = tid & 31, warp = tid >> 5;
    const int wm = warp >> 1, wn = warp & 1;

    float acc[4][8][4] = {};

    load_pv(sm, P, V, tid);
    cp_commit();
    if (nIter > 1) {
        load_pv(sm + STG_PV, P + 64, V + (size_t)64 * DINT, tid);
        cp_commit();
        cp_wait<1>();
    } else {
        cp_wait<0>();
    }
    __syncthreads();

    unsigned f0[4][4], g0[4][4], f1[4][4], g1[4][4];
    frags_pv(sm, lane, wm, wn, 0, f0, g0);

    int sc = 0;
    for (int i = 0; i < nIter; ++i) {
        const char* cur = sm + sc * STG_PV;
        int s1 = sc + 1; if (s1 == NSTG) s1 = 0;
        int s2 = s1 + 1; if (s2 == NSTG) s2 = 0;
        frags_pv(cur, lane, wm, wn, 1, f1, g1);
        mma_tile(f0, g0, acc);
        frags_pv(cur, lane, wm, wn, 2, f0, g0);
        mma_tile(f1, g1, acc);
        frags_pv(cur, lane, wm, wn, 3, f1, g1);
        mma_tile(f0, g0, acc);
        if (i + 2 < nIter) {
            load_pv(sm + s2 * STG_PV,
                    P + (i + 2) * 64, V + (size_t)(i + 2) * 64 * DINT, tid);
            cp_commit();
        }
        if (i + 1 < nIter) {
            if (i + 2 < nIter) cp_wait<1>(); else cp_wait<0>();
            __syncthreads();
            frags_pv(sm + s1 * STG_PV, lane, wm, wn, 0, f0, g0);
        }
        mma_tile(f1, g1, acc);
        sc = s1;
    }

    #pragma unroll
    for (int mf = 0; mf < 4; ++mf)
        #pragma unroll
        for (int nf = 0; nf < 8; ++nf) {
            int q = q0 + wm * 64 + mf * 16 + (lane >> 2);
            int c = n0 + wn * 64 + nf * 8 + (lane & 3) * 2;
            *(float2*)&out[((size_t)(b * TLEN + q)) * DINT + c] =
                make_float2(acc[mf][nf][0], acc[mf][nf][1]);
            *(float2*)&out[((size_t)(b * TLEN + q + 8)) * DINT + c] =
                make_float2(acc[mf][nf][2], acc[mf][nf][3]);
        }
}

// ---------------------------------------------------------------------------
// Launch
// ---------------------------------------------------------------------------
extern "C" void kernel_launch(void* const* d_in, const int* in_sizes, int n_in,
                              void* d_out, int out_size) {
    (void)n_in; (void)out_size; (void)in_sizes;
    const float* input_vecs = (const float*)d_in[0];
    const float* qkv_w      = (const float*)d_in[1];
    const float* sqk        = (const float*)d_in[2];
    float* out              = (float*)d_out;

    const float sqk_mul = sqrtf((float)DMODEL);
    const float scale   = sqrtf((float)DMODEL);
    const int DSMEM_TN = NSTG * STG_TN;   // 110592
    const int DSMEM_PV = NSTG * STG_PV;   // 107520

    cudaFuncSetAttribute(qkv_gemm_pipe, cudaFuncAttributeMaxDynamicSharedMemorySize, DSMEM_TN);
    cudaFuncSetAttribute(qk_gemm_pipe,  cudaFuncAttributeMaxDynamicSharedMemorySize, DSMEM_TN);
    cudaFuncSetAttribute(pv_gemm_pipe,  cudaFuncAttributeMaxDynamicSharedMemorySize, DSMEM_PV);

    init_freq_kernel<<<2, 256>>>();

    __half *xh, *wh;
    cudaGetSymbolAddress((void**)&xh, g_Xh);
    cudaGetSymbolAddress((void**)&wh, g_Wh);
    int nx4 = MTOT * DMODEL / 4, nw4 = 3 * DINT * DMODEL / 4;
    cvt_kernel<<<(nx4 + 255) / 256, 256>>>((const float4*)input_vecs, (uint2*)xh, nx4);
    cvt_kernel<<<(nw4 + 255) / 256, 256>>>((const float4*)qkv_w, (uint2*)wh, nw4);

    qkv_gemm_pipe<<<dim3(3 * DINT / 128, MTOT / 128), NTHR, DSMEM_TN>>>();

    rope_norm_kernel<<<dim3(MTOT, 2), 256>>>(sqk, sqk_mul);

    qk_gemm_pipe<<<dim3(TLEN / 128, TLEN / 128, BATCH), NTHR, DSMEM_TN>>>(scale);

    softmax_kernel<<<dim3(TLEN, BATCH), 256>>>();

    pv_gemm_pipe<<<dim3(DINT / 128, TLEN / 128, BATCH), NTHR, DSMEM_PV>>>(out);
}

// round 16
// speedup vs baseline: 3.3110x; 1.0006x over previous
#include <cuda_runtime.h>
#include <cuda_fp16.h>
#include <math.h>

#define BATCH 4
#define TLEN  2048
#define DMODEL 1024
#define DINT   1024
#define MTOT  (BATCH * TLEN)     // 8192
#define HALFD (DINT / 2)         // 512

// ---------------------------------------------------------------------------
// Scratch (device globals; no allocation allowed)
// ---------------------------------------------------------------------------
__device__ float g_Q[MTOT * DINT];                 // f32 (rope input)
__device__ float g_K[MTOT * DINT];
__device__ float g_S[BATCH * TLEN * TLEN];         // scores f32
__device__ __half g_Qh[MTOT * DINT];               // post-rope fp16
__device__ __half g_Kh[MTOT * DINT];
__device__ __half g_Vh[MTOT * DINT];
__device__ __half g_Ph[BATCH * TLEN * TLEN];       // probs fp16
__device__ __half g_Xh[MTOT * DMODEL];
__device__ __half g_Wh[3 * DINT * DMODEL];
__device__ float g_invfreq[HALFD];

// ---------------------------------------------------------------------------
// Helpers
// ---------------------------------------------------------------------------
__device__ __forceinline__ unsigned smem_u32(const void* p) {
    return (unsigned)__cvta_generic_to_shared(p);
}
__device__ __forceinline__ void cp16(unsigned dst, const void* src) {
    asm volatile("cp.async.cg.shared.global [%0], [%1], 16;" :: "r"(dst), "l"(src));
}
__device__ __forceinline__ void cp_commit() {
    asm volatile("cp.async.commit_group;");
}
template <int N>
__device__ __forceinline__ void cp_wait() {
    asm volatile("cp.async.wait_group %0;" :: "n"(N));
}
__device__ __forceinline__ void ldm_x4(unsigned a, unsigned& r0, unsigned& r1,
                                       unsigned& r2, unsigned& r3) {
    asm volatile("ldmatrix.sync.aligned.m8n8.x4.shared.b16 {%0,%1,%2,%3}, [%4];"
                 : "=r"(r0), "=r"(r1), "=r"(r2), "=r"(r3) : "r"(a));
}
__device__ __forceinline__ void ldm_x4_t(unsigned a, unsigned& r0, unsigned& r1,
                                         unsigned& r2, unsigned& r3) {
    asm volatile("ldmatrix.sync.aligned.m8n8.x4.trans.shared.b16 {%0,%1,%2,%3}, [%4];"
                 : "=r"(r0), "=r"(r1), "=r"(r2), "=r"(r3) : "r"(a));
}
__device__ __forceinline__ void mma16816(float* c, const unsigned* a,
                                         unsigned b0, unsigned b1) {
    asm volatile("mma.sync.aligned.m16n8k16.row.col.f32.f16.f16.f32 "
                 "{%0,%1,%2,%3}, {%4,%5,%6,%7}, {%8,%9}, {%0,%1,%2,%3};"
                 : "+f"(c[0]), "+f"(c[1]), "+f"(c[2]), "+f"(c[3])
                 : "r"(a[0]), "r"(a[1]), "r"(a[2]), "r"(a[3]), "r"(b0), "r"(b1));
}

// CTA tile 128(M) x 128(N) x 64(K). 4 warps, warp tile 64x64: wm, wn in {0,1}.
// Stage (halfs): TN: A[128*72] B[128*72]; PV: P[128*72] V[64*136]
#define SB_OFF   (128 * 72)
#define STG_TN   ((128 * 72 + 128 * 72) * 2)   // 36864 B
#define STG_PV   ((128 * 72 + 64 * 136) * 2)   // 35840 B
#define NSTG 3
#define NTHR 128

// ---------------------------------------------------------------------------
// TN loaders / fragment ops (K-stage = 64 halfs = 8 x 16B chunks per row)
// ---------------------------------------------------------------------------
__device__ __forceinline__ void load_tn(char* st,
    const __half* A, int strideA, const __half* B, int strideB, int tid)
{
    __half* s = (__half*)st;
    #pragma unroll
    for (int j = 0; j < 8; ++j) {   // A: 128 rows x 8 chunks = 1024
        int idx = j * NTHR + tid;
        int r = idx >> 3, c = idx & 7;
        cp16(smem_u32(&s[r * 72 + c * 8]), A + (size_t)r * strideA + c * 8);
    }
    #pragma unroll
    for (int j = 0; j < 8; ++j) {   // B: 128 rows x 8 chunks
        int idx = j * NTHR + tid;
        int r = idx >> 3, c = idx & 7;
        cp16(smem_u32(&s[SB_OFF + r * 72 + c * 8]), B + (size_t)r * strideB + c * 8);
    }
}

__device__ __forceinline__ void frags_tn(const char* st, int lane, int wm, int wn,
                                         int ks, unsigned a[4][4], unsigned b[4][4])
{
    const __half* sA = (const __half*)st;
    const __half* sB = sA + SB_OFF;
    const int lr  = (lane & 7) + ((lane >> 3) & 1) * 8;
    const int kb  = ks * 16 + (lane >> 4) * 8;
    #pragma unroll
    for (int mf = 0; mf < 4; ++mf) {
        int row = wm * 64 + mf * 16 + lr;
        ldm_x4(smem_u32(&sA[row * 72 + kb]), a[mf][0], a[mf][1], a[mf][2], a[mf][3]);
    }
    #pragma unroll
    for (int g = 0; g < 4; ++g) {
        int row = wn * 64 + g * 16 + lr;
        ldm_x4(smem_u32(&sB[row * 72 + kb]), b[g][0], b[g][1], b[g][2], b[g][3]);
    }
}

__device__ __forceinline__ void mma_tile(unsigned a[4][4], unsigned b[4][4],
                                         float acc[4][8][4])
{
    #pragma unroll
    for (int mf = 0; mf < 4; ++mf)
        #pragma unroll
        for (int nf = 0; nf < 8; ++nf) {
            int g = nf >> 1, sdx = nf & 1;
            mma16816(acc[mf][nf], a[mf], b[g][sdx], b[g][sdx + 2]);
        }
}

// Mainloop: 64-k stages, one barrier per stage, register fragment double-buffer.
// Stage indices maintained incrementally (no % in the hot loop).
__device__ __forceinline__ void pipe_tn(
    const __half* A, int strideA, const __half* B, int strideB,
    int nIter, char* sm, float acc[4][8][4])
{
    const int tid = threadIdx.x, lane = tid & 31, warp = tid >> 5;
    const int wm = warp >> 1, wn = warp & 1;

    load_tn(sm, A, strideA, B, strideB, tid);
    cp_commit();
    if (nIter > 1) {
        load_tn(sm + STG_TN, A + 64, strideA, B + 64, strideB, tid);
        cp_commit();
        cp_wait<1>();
    } else {
        cp_wait<0>();
    }
    __syncthreads();

    unsigned f0[4][4], g0[4][4], f1[4][4], g1[4][4];
    frags_tn(sm, lane, wm, wn, 0, f0, g0);

    int sc = 0;                                   // i % NSTG
    for (int i = 0; i < nIter; ++i) {
        const char* cur = sm + sc * STG_TN;
        int s1 = sc + 1; if (s1 == NSTG) s1 = 0;  // (i+1) % NSTG
        int s2 = s1 + 1; if (s2 == NSTG) s2 = 0;  // (i+2) % NSTG
        frags_tn(cur, lane, wm, wn, 1, f1, g1);
        mma_tile(f0, g0, acc);
        frags_tn(cur, lane, wm, wn, 2, f0, g0);
        mma_tile(f1, g1, acc);
        frags_tn(cur, lane, wm, wn, 3, f1, g1);
        mma_tile(f0, g0, acc);
        if (i + 2 < nIter) {
            load_tn(sm + s2 * STG_TN,
                    A + (i + 2) * 64, strideA, B + (i + 2) * 64, strideB, tid);
            cp_commit();
        }
        if (i + 1 < nIter) {
            if (i + 2 < nIter) cp_wait<1>(); else cp_wait<0>();
            __syncthreads();
            frags_tn(sm + s1 * STG_TN, lane, wm, wn, 0, f0, g0);
        }
        mma_tile(f1, g1, acc);
        sc = s1;
    }
    __syncthreads();
}

// ---------------------------------------------------------------------------
// init + fp16 conversion (float4 -> 2x half2)
// ---------------------------------------------------------------------------
__global__ void init_freq_kernel() {
    int p = blockIdx.x * blockDim.x + threadIdx.x;
    if (p < HALFD) {
        double e = exp(-((double)(2 * p) / (double)DINT) * 9.210340371976184);
        g_invfreq[p] = (float)e;
    }
}

__global__ __launch_bounds__(256)
void cvt_kernel(const float4* __restrict__ src, uint2* __restrict__ dst, int n4) {
    int i = blockIdx.x * blockDim.x + threadIdx.x;
    if (i < n4) {
        float4 v = src[i];
        __half2 h01 = __float22half2_rn(make_float2(v.x, v.y));
        __half2 h23 = __float22half2_rn(make_float2(v.z, v.w));
        dst[i] = make_uint2(*(unsigned*)&h01, *(unsigned*)&h23);
    }
}

// ---------------------------------------------------------------------------
// Kernel 1: QKV GEMM. M=8192, N=3072, K=1024. Q,K -> f32; V -> fp16.
// ---------------------------------------------------------------------------
__global__ __launch_bounds__(NTHR, 2)
void qkv_gemm_pipe() {
    extern __shared__ char sm[];
    const int m0 = blockIdx.y * 128, n0 = blockIdx.x * 128;
    float acc[4][8][4] = {};
    pipe_tn(g_Xh + (size_t)m0 * DMODEL, DMODEL,
            g_Wh + (size_t)n0 * DMODEL, DMODEL, DMODEL / 64, sm, acc);

    const int tid = threadIdx.x, lane = tid & 31, warp = tid >> 5;
    const int wm = warp >> 1, wn = warp & 1;
    if (n0 < 2 * DINT) {
        float* dst = (n0 < DINT) ? g_Q : g_K;
        int nb = (n0 < DINT) ? n0 : n0 - DINT;
        #pragma unroll
        for (int mf = 0; mf < 4; ++mf)
            #pragma unroll
            for (int nf = 0; nf < 8; ++nf) {
                int r = m0 + wm * 64 + mf * 16 + (lane >> 2);
                int c = nb + wn * 64 + nf * 8 + (lane & 3) * 2;
                *(float2*)&dst[(size_t)r * DINT + c]       = make_float2(acc[mf][nf][0], acc[mf][nf][1]);
                *(float2*)&dst[(size_t)(r + 8) * DINT + c] = make_float2(acc[mf][nf][2], acc[mf][nf][3]);
            }
    } else {
        int nb = n0 - 2 * DINT;
        #pragma unroll
        for (int mf = 0; mf < 4; ++mf)
            #pragma unroll
            for (int nf = 0; nf < 8; ++nf) {
                int r = m0 + wm * 64 + mf * 16 + (lane >> 2);
                int c = nb + wn * 64 + nf * 8 + (lane & 3) * 2;
                *(__half2*)&g_Vh[(size_t)r * DINT + c] =
                    __float22half2_rn(make_float2(acc[mf][nf][0], acc[mf][nf][1]));
                *(__half2*)&g_Vh[(size_t)(r + 8) * DINT + c] =
                    __float22half2_rn(make_float2(acc[mf][nf][2], acc[mf][nf][3]));
            }
    }
}

// ---------------------------------------------------------------------------
// Kernel 2: RoPE + L2 norm + scale; writes fp16 Q,K. Vectorized (2 pairs/thread).
// ---------------------------------------------------------------------------
__global__ __launch_bounds__(256)
void rope_norm_kernel(const float* __restrict__ sqk, float sqk_mul) {
    const int token = blockIdx.x;
    const float tpos = (float)(token & (TLEN - 1));
    const bool isQ = (blockIdx.y == 0);
    const float* row = (isQ ? g_Q : g_K) + (size_t)token * DINT;
    __half* outh = (isQ ? g_Qh : g_Kh) + (size_t)token * DINT;

    const int tid = threadIdx.x;
    const int p2 = tid * 2;                      // pair base: 2 pairs per thread
    float2 A  = *(const float2*)&row[p2];
    float2 Bv = *(const float2*)&row[p2 + HALFD];
    float2 fr = *(const float2*)&g_invfreq[p2];
    float s0, c0, s1, c1;
    sincosf(tpos * fr.x, &s0, &c0);
    sincosf(tpos * fr.y, &s1, &c1);
    float na0 = A.x * c0 - Bv.x * s0, nb0 = Bv.x * c0 + A.x * s0;
    float na1 = A.y * c1 - Bv.y * s1, nb1 = Bv.y * c1 + A.y * s1;
    float ss = na0 * na0 + nb0 * nb0 + na1 * na1 + nb1 * nb1;

    __shared__ float warp_red[8];
    #pragma unroll
    for (int o = 16; o > 0; o >>= 1) ss += __shfl_xor_sync(0xffffffffu, ss, o);
    if ((tid & 31) == 0) warp_red[tid >> 5] = ss;
    __syncthreads();
    __shared__ float total_sh;
    if (tid == 0) {
        float t = 0.0f;
        #pragma unroll
        for (int w = 0; w < 8; ++w) t += warp_red[w];
        total_sh = t;
    }
    __syncthreads();
    const float rnorm = 1.0f / sqrtf(total_sh);

    float2 sq0 = *(const float2*)&sqk[p2];
    float2 sq1 = *(const float2*)&sqk[p2 + HALFD];
    float va0 = na0 * rnorm * (sq0.x * sqk_mul);
    float va1 = na1 * rnorm * (sq0.y * sqk_mul);
    float vb0 = nb0 * rnorm * (sq1.x * sqk_mul);
    float vb1 = nb1 * rnorm * (sq1.y * sqk_mul);
    *(__half2*)&outh[p2]         = __float22half2_rn(make_float2(va0, va1));
    *(__half2*)&outh[p2 + HALFD] = __float22half2_rn(make_float2(vb0, vb1));
}

// ---------------------------------------------------------------------------
// Kernel 3: scores S = scale * Q K^T. grid (16, 16, 4), triangular skip.
// y launched heavy-first (reversed) so wave 1 is dense in active tiles.
// ---------------------------------------------------------------------------
__global__ __launch_bounds__(NTHR, 2)
void qk_gemm_pipe(float scale) {
    const int b  = blockIdx.z;
    const int yy = gridDim.y - 1 - blockIdx.y;  // heavy-first
    const int q0 = yy * 128;
    const int k0n = blockIdx.x * 128;
    if (k0n > q0) return;                      // tile fully above diagonal
    extern __shared__ char sm[];

    float acc[4][8][4] = {};
    pipe_tn(g_Qh + ((size_t)b * TLEN + q0) * DINT, DINT,
            g_Kh + ((size_t)b * TLEN + k0n) * DINT, DINT, DINT / 64, sm, acc);

    float* S = g_S + (size_t)b * TLEN * TLEN;
    const int tid = threadIdx.x, lane = tid & 31, warp = tid >> 5;
    const int wm = warp >> 1, wn = warp & 1;
    #pragma unroll
    for (int mf = 0; mf < 4; ++mf)
        #pragma unroll
        for (int nf = 0; nf < 8; ++nf) {
            int q = q0 + wm * 64 + mf * 16 + (lane >> 2);
            int c = k0n + wn * 64 + nf * 8 + (lane & 3) * 2;
            *(float2*)&S[(size_t)q * TLEN + c] =
                make_float2(acc[mf][nf][0] * scale, acc[mf][nf][1] * scale);
            *(float2*)&S[(size_t)(q + 8) * TLEN + c] =
                make_float2(acc[mf][nf][2] * scale, acc[mf][nf][3] * scale);
        }
}

// ---------------------------------------------------------------------------
// Kernel 4: causal softmax; writes fp16 P (exact zeros above diagonal).
// Vectorized: float4 loads, 4-half packed stores.
// ---------------------------------------------------------------------------
__global__ __launch_bounds__(256)
void softmax_kernel() {
    const int q = blockIdx.x;
    const int b = blockIdx.y;
    const float4* row4 = (const float4*)(g_S + ((size_t)b * TLEN + q) * TLEN);
    __half* ph = g_Ph + ((size_t)b * TLEN + q) * TLEN;
    const int tid = threadIdx.x;

    float4 v[2];
    float m = -INFINITY;
    #pragma unroll
    for (int i = 0; i < 2; ++i) {
        int k4 = i * 256 + tid;
        float4 x = row4[k4];
        int k = k4 * 4;
        x.x = (k     <= q) ? x.x : -INFINITY;
        x.y = (k + 1 <= q) ? x.y : -INFINITY;
        x.z = (k + 2 <= q) ? x.z : -INFINITY;
        x.w = (k + 3 <= q) ? x.w : -INFINITY;
        v[i] = x;
        m = fmaxf(m, fmaxf(fmaxf(x.x, x.y), fmaxf(x.z, x.w)));
    }

    __shared__ float warp_red[8];
    __shared__ float bcast;
    #pragma unroll
    for (int o = 16; o > 0; o >>= 1) m = fmaxf(m, __shfl_xor_sync(0xffffffffu, m, o));
    if ((tid & 31) == 0) warp_red[tid >> 5] = m;
    __syncthreads();
    if (tid == 0) {
        float t = warp_red[0];
        #pragma unroll
        for (int w = 1; w < 8; ++w) t = fmaxf(t, warp_red[w]);
        bcast = t;
    }
    __syncthreads();
    const float rowmax = bcast;

    float sum = 0.0f;
    #pragma unroll
    for (int i = 0; i < 2; ++i) {
        float4 x = v[i];
        x.x = expf(x.x - rowmax);       // exp(-INF - m) == 0 exactly
        x.y = expf(x.y - rowmax);
        x.z = expf(x.z - rowmax);
        x.w = expf(x.w - rowmax);
        v[i] = x;
        sum += (x.x + x.y) + (x.z + x.w);
    }
    #pragma unroll
    for (int o = 16; o > 0; o >>= 1) sum += __shfl_xor_sync(0xffffffffu, sum, o);
    if ((tid & 31) == 0) warp_red[tid >> 5] = sum;
    __syncthreads();
    if (tid == 0) {
        float t = 0.0f;
        #pragma unroll
        for (int w = 0; w < 8; ++w) t += warp_red[w];
        bcast = t;
    }
    __syncthreads();
    const float inv = 1.0f / bcast;

    #pragma unroll
    for (int i = 0; i < 2; ++i) {
        int k4 = i * 256 + tid;
        float4 x = v[i];
        __half2 h01 = __float22half2_rn(make_float2(x.x * inv, x.y * inv));
        __half2 h23 = __float22half2_rn(make_float2(x.z * inv, x.w * inv));
        *(uint2*)&ph[k4 * 4] = make_uint2(*(unsigned*)&h01, *(unsigned*)&h23);
    }
}

// ---------------------------------------------------------------------------
// Kernel 5: O = P V. P k-contig (non-trans A); V n-contig (trans B).
// CTA 128(M) x 128(N) x 64(K), 4 warps 64x64. grid (8, 16, 4).
// q tiles launched heavy-first (reversed y) for balanced waves.
// ---------------------------------------------------------------------------
__device__ __forceinline__ void load_pv(char* st,
    const __half* P, const __half* V, int tid)
{
    __half* s = (__half*)st;
    #pragma unroll
    for (int j = 0; j < 8; ++j) {   // P: 128 rows x 8 chunks
        int idx = j * NTHR + tid;
        int r = idx >> 3, c = idx & 7;
        cp16(smem_u32(&s[r * 72 + c * 8]), P + (size_t)r * TLEN + c * 8);
    }
    #pragma unroll
    for (int j = 0; j < 8; ++j) {   // V: 64 rows x 16 chunks
        int idx = j * NTHR + tid;
        int r = idx >> 4, c = idx & 15;
        cp16(smem_u32(&s[SB_OFF + r * 136 + c * 8]), V + (size_t)r * DINT + c * 8);
    }
}

__device__ __forceinline__ void frags_pv(const char* st, int lane, int wm, int wn,
                                         int ks, unsigned a[4][4], unsigned bv[4][4])
{
    const __half* sP = (const __half*)st;
    const __half* sV = sP + SB_OFF;
    const int lrA  = (lane & 7) + ((lane >> 3) & 1) * 8;
    const int kbA  = ks * 16 + (lane >> 4) * 8;
    const int kbV  = ks * 16 + (lane & 7) + ((lane >> 4) & 1) * 8;
    const int lcV8 = ((lane >> 3) & 1) * 8;
    #pragma unroll
    for (int mf = 0; mf < 4; ++mf) {
        int row = wm * 64 + mf * 16 + lrA;
        ldm_x4(smem_u32(&sP[row * 72 + kbA]), a[mf][0], a[mf][1], a[mf][2], a[mf][3]);
    }
    #pragma unroll
    for (int g = 0; g < 4; ++g) {
        int col = wn * 64 + g * 16 + lcV8;
        ldm_x4_t(smem_u32(&sV[kbV * 136 + col]), bv[g][0], bv[g][1], bv[g][2], bv[g][3]);
    }
}

__global__ __launch_bounds__(NTHR, 2)
void pv_gemm_pipe(float* __restrict__ out) {
    const int b  = blockIdx.z;
    const int yy = gridDim.y - 1 - blockIdx.y;  // heavy-first: large q0 launches first
    const int q0 = yy * 128;
    const int n0 = blockIdx.x * 128;
    extern __shared__ char sm[];

    const __half* P = g_Ph + ((size_t)b * TLEN + q0) * TLEN;
    const __half* V = g_Vh + (size_t)b * TLEN * DINT + n0;
    const int nIter = (q0 + 128) / 64;

    const int tid = threadIdx.x, lane = tid & 31, warp = tid >> 5;
    const int wm = warp >> 1, wn = warp & 1;

    float acc[4][8][4] = {};

    load_pv(sm, P, V, tid);
    cp_commit();
    if (nIter > 1) {
        load_pv(sm + STG_PV, P + 64, V + (size_t)64 * DINT, tid);
        cp_commit();
        cp_wait<1>();
    } else {
        cp_wait<0>();
    }
    __syncthreads();

    unsigned f0[4][4], g0[4][4], f1[4][4], g1[4][4];
    frags_pv(sm, lane, wm, wn, 0, f0, g0);

    int sc = 0;
    for (int i = 0; i < nIter; ++i) {
        const char* cur = sm + sc * STG_PV;
        int s1 = sc + 1; if (s1 == NSTG) s1 = 0;
        int s2 = s1 + 1; if (s2 == NSTG) s2 = 0;
        frags_pv(cur, lane, wm, wn, 1, f1, g1);
        mma_tile(f0, g0, acc);
        frags_pv(cur, lane, wm, wn, 2, f0, g0);
        mma_tile(f1, g1, acc);
        frags_pv(cur, lane, wm, wn, 3, f1, g1);
        mma_tile(f0, g0, acc);
        if (i + 2 < nIter) {
            load_pv(sm + s2 * STG_PV,
                    P + (i + 2) * 64, V + (size_t)(i + 2) * 64 * DINT, tid);
            cp_commit();
        }
        if (i + 1 < nIter) {
            if (i + 2 < nIter) cp_wait<1>(); else cp_wait<0>();
            __syncthreads();
            frags_pv(sm + s1 * STG_PV, lane, wm, wn, 0, f0, g0);
        }
        mma_tile(f1, g1, acc);
        sc = s1;
    }

    #pragma unroll
    for (int mf = 0; mf < 4; ++mf)
        #pragma unroll
        for (int nf = 0; nf < 8; ++nf) {
            int q = q0 + wm * 64 + mf * 16 + (lane >> 2);
            int c = n0 + wn * 64 + nf * 8 + (lane & 3) * 2;
            *(float2*)&out[((size_t)(b * TLEN + q)) * DINT + c] =
                make_float2(acc[mf][nf][0], acc[mf][nf][1]);
            *(float2*)&out[((size_t)(b * TLEN + q + 8)) * DINT + c] =
                make_float2(acc[mf][nf][2], acc[mf][nf][3]);
        }
}

// ---------------------------------------------------------------------------
// Launch
// ---------------------------------------------------------------------------
extern "C" void kernel_launch(void* const* d_in, const int* in_sizes, int n_in,
                              void* d_out, int out_size) {
    (void)n_in; (void)out_size; (void)in_sizes;
    const float* input_vecs = (const float*)d_in[0];
    const float* qkv_w      = (const float*)d_in[1];
    const float* sqk        = (const float*)d_in[2];
    float* out              = (float*)d_out;

    const float sqk_mul = sqrtf((float)DMODEL);
    const float scale   = sqrtf((float)DMODEL);
    const int DSMEM_TN = NSTG * STG_TN;   // 110592
    const int DSMEM_PV = NSTG * STG_PV;   // 107520

    cudaFuncSetAttribute(qkv_gemm_pipe, cudaFuncAttributeMaxDynamicSharedMemorySize, DSMEM_TN);
    cudaFuncSetAttribute(qk_gemm_pipe,  cudaFuncAttributeMaxDynamicSharedMemorySize, DSMEM_TN);
    cudaFuncSetAttribute(pv_gemm_pipe,  cudaFuncAttributeMaxDynamicSharedMemorySize, DSMEM_PV);

    init_freq_kernel<<<2, 256>>>();

    __half *xh, *wh;
    cudaGetSymbolAddress((void**)&xh, g_Xh);
    cudaGetSymbolAddress((void**)&wh, g_Wh);
    int nx4 = MTOT * DMODEL / 4, nw4 = 3 * DINT * DMODEL / 4;
    cvt_kernel<<<(nx4 + 255) / 256, 256>>>((const float4*)input_vecs, (uint2*)xh, nx4);
    cvt_kernel<<<(nw4 + 255) / 256, 256>>>((const float4*)qkv_w, (uint2*)wh, nw4);

    qkv_gemm_pipe<<<dim3(3 * DINT / 128, MTOT / 128), NTHR, DSMEM_TN>>>();

    rope_norm_kernel<<<dim3(MTOT, 2), 256>>>(sqk, sqk_mul);

    qk_gemm_pipe<<<dim3(TLEN / 128, TLEN / 128, BATCH), NTHR, DSMEM_TN>>>(scale);

    softmax_kernel<<<dim3(TLEN, BATCH), 256>>>();

    pv_gemm_pipe<<<dim3(DINT / 128, TLEN / 128, BATCH), NTHR, DSMEM_PV>>>(out);
}

// round 17
// speedup vs baseline: 3.3301x; 1.0058x over previous
#include <cuda_runtime.h>
#include <cuda_fp16.h>
#include <math.h>

#define BATCH 4
#define TLEN  2048
#define DMODEL 1024
#define DINT   1024
#define MTOT  (BATCH * TLEN)     // 8192
#define HALFD (DINT / 2)         // 512

// ---------------------------------------------------------------------------
// Scratch (device globals; no allocation allowed)
// ---------------------------------------------------------------------------
__device__ float g_Q[MTOT * DINT];                 // f32 (rope input)
__device__ float g_K[MTOT * DINT];
__device__ float g_S[BATCH * TLEN * TLEN];         // scores f32
__device__ __half g_Qh[MTOT * DINT];               // post-rope fp16
__device__ __half g_Kh[MTOT * DINT];
__device__ __half g_Vh[MTOT * DINT];
__device__ __half g_Ph[BATCH * TLEN * TLEN];       // probs fp16
__device__ __half g_Xh[MTOT * DMODEL];
__device__ __half g_Wh[3 * DINT * DMODEL];
__device__ float g_invfreq[HALFD];

// ---------------------------------------------------------------------------
// Helpers
// ---------------------------------------------------------------------------
__device__ __forceinline__ unsigned smem_u32(const void* p) {
    return (unsigned)__cvta_generic_to_shared(p);
}
__device__ __forceinline__ void cp16(unsigned dst, const void* src) {
    asm volatile("cp.async.cg.shared.global [%0], [%1], 16;" :: "r"(dst), "l"(src));
}
__device__ __forceinline__ void cp_commit() {
    asm volatile("cp.async.commit_group;");
}
template <int N>
__device__ __forceinline__ void cp_wait() {
    asm volatile("cp.async.wait_group %0;" :: "n"(N));
}
__device__ __forceinline__ void ldm_x4(unsigned a, unsigned& r0, unsigned& r1,
                                       unsigned& r2, unsigned& r3) {
    asm volatile("ldmatrix.sync.aligned.m8n8.x4.shared.b16 {%0,%1,%2,%3}, [%4];"
                 : "=r"(r0), "=r"(r1), "=r"(r2), "=r"(r3) : "r"(a));
}
__device__ __forceinline__ void ldm_x4_t(unsigned a, unsigned& r0, unsigned& r1,
                                         unsigned& r2, unsigned& r3) {
    asm volatile("ldmatrix.sync.aligned.m8n8.x4.trans.shared.b16 {%0,%1,%2,%3}, [%4];"
                 : "=r"(r0), "=r"(r1), "=r"(r2), "=r"(r3) : "r"(a));
}
__device__ __forceinline__ void mma16816(float* c, const unsigned* a,
                                         unsigned b0, unsigned b1) {
    asm volatile("mma.sync.aligned.m16n8k16.row.col.f32.f16.f16.f32 "
                 "{%0,%1,%2,%3}, {%4,%5,%6,%7}, {%8,%9}, {%0,%1,%2,%3};"
                 : "+f"(c[0]), "+f"(c[1]), "+f"(c[2]), "+f"(c[3])
                 : "r"(a[0]), "r"(a[1]), "r"(a[2]), "r"(a[3]), "r"(b0), "r"(b1));
}

// CTA tile 128(M) x 128(N) x 64(K). 4 warps, warp tile 64x64: wm, wn in {0,1}.
// Stage (halfs): TN: A[128*72] B[128*72]; PV: P[128*72] V[64*136]
#define SB_OFF   (128 * 72)
#define STG_TN   ((128 * 72 + 128 * 72) * 2)   // 36864 B
#define STG_PV   ((128 * 72 + 64 * 136) * 2)   // 35840 B
#define NSTG 3
#define NTHR 128

// ---------------------------------------------------------------------------
// TN loaders / fragment ops (K-stage = 64 halfs = 8 x 16B chunks per row)
// ---------------------------------------------------------------------------
__device__ __forceinline__ void load_tn(char* st,
    const __half* A, int strideA, const __half* B, int strideB, int tid)
{
    __half* s = (__half*)st;
    #pragma unroll
    for (int j = 0; j < 8; ++j) {   // A: 128 rows x 8 chunks = 1024
        int idx = j * NTHR + tid;
        int r = idx >> 3, c = idx & 7;
        cp16(smem_u32(&s[r * 72 + c * 8]), A + (size_t)r * strideA + c * 8);
    }
    #pragma unroll
    for (int j = 0; j < 8; ++j) {   // B: 128 rows x 8 chunks
        int idx = j * NTHR + tid;
        int r = idx >> 3, c = idx & 7;
        cp16(smem_u32(&s[SB_OFF + r * 72 + c * 8]), B + (size_t)r * strideB + c * 8);
    }
}

__device__ __forceinline__ void frags_tn(const char* st, int lane, int wm, int wn,
                                         int ks, unsigned a[4][4], unsigned b[4][4])
{
    const __half* sA = (const __half*)st;
    const __half* sB = sA + SB_OFF;
    const int lr  = (lane & 7) + ((lane >> 3) & 1) * 8;
    const int kb  = ks * 16 + (lane >> 4) * 8;
    #pragma unroll
    for (int mf = 0; mf < 4; ++mf) {
        int row = wm * 64 + mf * 16 + lr;
        ldm_x4(smem_u32(&sA[row * 72 + kb]), a[mf][0], a[mf][1], a[mf][2], a[mf][3]);
    }
    #pragma unroll
    for (int g = 0; g < 4; ++g) {
        int row = wn * 64 + g * 16 + lr;
        ldm_x4(smem_u32(&sB[row * 72 + kb]), b[g][0], b[g][1], b[g][2], b[g][3]);
    }
}

__device__ __forceinline__ void mma_tile(unsigned a[4][4], unsigned b[4][4],
                                         float acc[4][8][4])
{
    #pragma unroll
    for (int mf = 0; mf < 4; ++mf)
        #pragma unroll
        for (int nf = 0; nf < 8; ++nf) {
            int g = nf >> 1, sdx = nf & 1;
            mma16816(acc[mf][nf], a[mf], b[g][sdx], b[g][sdx + 2]);
        }
}

// Mainloop: 64-k stages, one barrier per stage, register fragment double-buffer.
__device__ __forceinline__ void pipe_tn(
    const __half* A, int strideA, const __half* B, int strideB,
    int nIter, char* sm, float acc[4][8][4])
{
    const int tid = threadIdx.x, lane = tid & 31, warp = tid >> 5;
    const int wm = warp >> 1, wn = warp & 1;

    load_tn(sm, A, strideA, B, strideB, tid);
    cp_commit();
    if (nIter > 1) {
        load_tn(sm + STG_TN, A + 64, strideA, B + 64, strideB, tid);
        cp_commit();
        cp_wait<1>();
    } else {
        cp_wait<0>();
    }
    __syncthreads();

    unsigned f0[4][4], g0[4][4], f1[4][4], g1[4][4];
    frags_tn(sm, lane, wm, wn, 0, f0, g0);

    int sc = 0;
    for (int i = 0; i < nIter; ++i) {
        const char* cur = sm + sc * STG_TN;
        int s1 = sc + 1; if (s1 == NSTG) s1 = 0;
        int s2 = s1 + 1; if (s2 == NSTG) s2 = 0;
        frags_tn(cur, lane, wm, wn, 1, f1, g1);
        mma_tile(f0, g0, acc);
        frags_tn(cur, lane, wm, wn, 2, f0, g0);
        mma_tile(f1, g1, acc);
        frags_tn(cur, lane, wm, wn, 3, f1, g1);
        mma_tile(f0, g0, acc);
        if (i + 2 < nIter) {
            load_tn(sm + s2 * STG_TN,
                    A + (i + 2) * 64, strideA, B + (i + 2) * 64, strideB, tid);
            cp_commit();
        }
        if (i + 1 < nIter) {
            if (i + 2 < nIter) cp_wait<1>(); else cp_wait<0>();
            __syncthreads();
            frags_tn(sm + s1 * STG_TN, lane, wm, wn, 0, f0, g0);
        }
        mma_tile(f1, g1, acc);
        sc = s1;
    }
    __syncthreads();
}

// ---------------------------------------------------------------------------
// init + fp16 conversion (float4 -> 2x half2)
// ---------------------------------------------------------------------------
__global__ void init_freq_kernel() {
    int p = blockIdx.x * blockDim.x + threadIdx.x;
    if (p < HALFD) {
        double e = exp(-((double)(2 * p) / (double)DINT) * 9.210340371976184);
        g_invfreq[p] = (float)e;
    }
}

__global__ __launch_bounds__(256)
void cvt_kernel(const float4* __restrict__ src, uint2* __restrict__ dst, int n4) {
    int i = blockIdx.x * blockDim.x + threadIdx.x;
    if (i < n4) {
        float4 v = src[i];
        __half2 h01 = __float22half2_rn(make_float2(v.x, v.y));
        __half2 h23 = __float22half2_rn(make_float2(v.z, v.w));
        dst[i] = make_uint2(*(unsigned*)&h01, *(unsigned*)&h23);
    }
}

// ---------------------------------------------------------------------------
// Kernel 1: QKV GEMM. M=8192, N=3072, K=1024. Q,K -> f32; V -> fp16.
// ---------------------------------------------------------------------------
__global__ __launch_bounds__(NTHR, 2)
void qkv_gemm_pipe() {
    extern __shared__ char sm[];
    const int m0 = blockIdx.y * 128, n0 = blockIdx.x * 128;
    float acc[4][8][4] = {};
    pipe_tn(g_Xh + (size_t)m0 * DMODEL, DMODEL,
            g_Wh + (size_t)n0 * DMODEL, DMODEL, DMODEL / 64, sm, acc);

    const int tid = threadIdx.x, lane = tid & 31, warp = tid >> 5;
    const int wm = warp >> 1, wn = warp & 1;
    if (n0 < 2 * DINT) {
        float* dst = (n0 < DINT) ? g_Q : g_K;
        int nb = (n0 < DINT) ? n0 : n0 - DINT;
        #pragma unroll
        for (int mf = 0; mf < 4; ++mf)
            #pragma unroll
            for (int nf = 0; nf < 8; ++nf) {
                int r = m0 + wm * 64 + mf * 16 + (lane >> 2);
                int c = nb + wn * 64 + nf * 8 + (lane & 3) * 2;
                *(float2*)&dst[(size_t)r * DINT + c]       = make_float2(acc[mf][nf][0], acc[mf][nf][1]);
                *(float2*)&dst[(size_t)(r + 8) * DINT + c] = make_float2(acc[mf][nf][2], acc[mf][nf][3]);
            }
    } else {
        int nb = n0 - 2 * DINT;
        #pragma unroll
        for (int mf = 0; mf < 4; ++mf)
            #pragma unroll
            for (int nf = 0; nf < 8; ++nf) {
                int r = m0 + wm * 64 + mf * 16 + (lane >> 2);
                int c = nb + wn * 64 + nf * 8 + (lane & 3) * 2;
                *(__half2*)&g_Vh[(size_t)r * DINT + c] =
                    __float22half2_rn(make_float2(acc[mf][nf][0], acc[mf][nf][1]));
                *(__half2*)&g_Vh[(size_t)(r + 8) * DINT + c] =
                    __float22half2_rn(make_float2(acc[mf][nf][2], acc[mf][nf][3]));
            }
    }
}

// ---------------------------------------------------------------------------
// Kernel 2: RoPE + L2 norm + scale; writes fp16 Q,K. Vectorized (2 pairs/thread).
// ---------------------------------------------------------------------------
__global__ __launch_bounds__(256)
void rope_norm_kernel(const float* __restrict__ sqk, float sqk_mul) {
    const int token = blockIdx.x;
    const float tpos = (float)(token & (TLEN - 1));
    const bool isQ = (blockIdx.y == 0);
    const float* row = (isQ ? g_Q : g_K) + (size_t)token * DINT;
    __half* outh = (isQ ? g_Qh : g_Kh) + (size_t)token * DINT;

    const int tid = threadIdx.x;
    const int p2 = tid * 2;
    float2 A  = *(const float2*)&row[p2];
    float2 Bv = *(const float2*)&row[p2 + HALFD];
    float2 fr = *(const float2*)&g_invfreq[p2];
    float s0, c0, s1, c1;
    sincosf(tpos * fr.x, &s0, &c0);
    sincosf(tpos * fr.y, &s1, &c1);
    float na0 = A.x * c0 - Bv.x * s0, nb0 = Bv.x * c0 + A.x * s0;
    float na1 = A.y * c1 - Bv.y * s1, nb1 = Bv.y * c1 + A.y * s1;
    float ss = na0 * na0 + nb0 * nb0 + na1 * na1 + nb1 * nb1;

    __shared__ float warp_red[8];
    #pragma unroll
    for (int o = 16; o > 0; o >>= 1) ss += __shfl_xor_sync(0xffffffffu, ss, o);
    if ((tid & 31) == 0) warp_red[tid >> 5] = ss;
    __syncthreads();
    __shared__ float total_sh;
    if (tid == 0) {
        float t = 0.0f;
        #pragma unroll
        for (int w = 0; w < 8; ++w) t += warp_red[w];
        total_sh = t;
    }
    __syncthreads();
    const float rnorm = 1.0f / sqrtf(total_sh);

    float2 sq0 = *(const float2*)&sqk[p2];
    float2 sq1 = *(const float2*)&sqk[p2 + HALFD];
    float va0 = na0 * rnorm * (sq0.x * sqk_mul);
    float va1 = na1 * rnorm * (sq0.y * sqk_mul);
    float vb0 = nb0 * rnorm * (sq1.x * sqk_mul);
    float vb1 = nb1 * rnorm * (sq1.y * sqk_mul);
    *(__half2*)&outh[p2]         = __float22half2_rn(make_float2(va0, va1));
    *(__half2*)&outh[p2 + HALFD] = __float22half2_rn(make_float2(vb0, vb1));
}

// ---------------------------------------------------------------------------
// Kernel 3: scores S = scale * Q K^T. grid (16, 16, 4), triangular skip.
// ---------------------------------------------------------------------------
__global__ __launch_bounds__(NTHR, 2)
void qk_gemm_pipe(float scale) {
    const int b  = blockIdx.z;
    const int yy = gridDim.y - 1 - blockIdx.y;
    const int q0 = yy * 128;
    const int k0n = blockIdx.x * 128;
    if (k0n > q0) return;
    extern __shared__ char sm[];

    float acc[4][8][4] = {};
    pipe_tn(g_Qh + ((size_t)b * TLEN + q0) * DINT, DINT,
            g_Kh + ((size_t)b * TLEN + k0n) * DINT, DINT, DINT / 64, sm, acc);

    float* S = g_S + (size_t)b * TLEN * TLEN;
    const int tid = threadIdx.x, lane = tid & 31, warp = tid >> 5;
    const int wm = warp >> 1, wn = warp & 1;
    #pragma unroll
    for (int mf = 0; mf < 4; ++mf)
        #pragma unroll
        for (int nf = 0; nf < 8; ++nf) {
            int q = q0 + wm * 64 + mf * 16 + (lane >> 2);
            int c = k0n + wn * 64 + nf * 8 + (lane & 3) * 2;
            *(float2*)&S[(size_t)q * TLEN + c] =
                make_float2(acc[mf][nf][0] * scale, acc[mf][nf][1] * scale);
            *(float2*)&S[(size_t)(q + 8) * TLEN + c] =
                make_float2(acc[mf][nf][2] * scale, acc[mf][nf][3] * scale);
        }
}

// ---------------------------------------------------------------------------
// Kernel 4: causal softmax; writes fp16 P.
// Causal traffic trim: loads only float4s with k <= q (rest -INF constant);
// stores only up to wlimit = ((q>>7)+1)<<7 — pv never reads beyond it.
// ---------------------------------------------------------------------------
__global__ __launch_bounds__(256)
void softmax_kernel() {
    const int q = blockIdx.x;
    const int b = blockIdx.y;
    const float4* row4 = (const float4*)(g_S + ((size_t)b * TLEN + q) * TLEN);
    __half* ph = g_Ph + ((size_t)b * TLEN + q) * TLEN;
    const int tid = threadIdx.x;
    const int wlimit4 = (((q >> 7) + 1) << 7) >> 2;   // float4 store bound

    float4 v[2];
    float m = -INFINITY;
    #pragma unroll
    for (int i = 0; i < 2; ++i) {
        int k4 = i * 256 + tid;
        int k = k4 * 4;
        float4 x;
        if (k <= q) {
            x = row4[k4];
            x.y = (k + 1 <= q) ? x.y : -INFINITY;
            x.z = (k + 2 <= q) ? x.z : -INFINITY;
            x.w = (k + 3 <= q) ? x.w : -INFINITY;
        } else {
            x = make_float4(-INFINITY, -INFINITY, -INFINITY, -INFINITY);
        }
        v[i] = x;
        m = fmaxf(m, fmaxf(fmaxf(x.x, x.y), fmaxf(x.z, x.w)));
    }

    __shared__ float warp_red[8];
    __shared__ float bcast;
    #pragma unroll
    for (int o = 16; o > 0; o >>= 1) m = fmaxf(m, __shfl_xor_sync(0xffffffffu, m, o));
    if ((tid & 31) == 0) warp_red[tid >> 5] = m;
    __syncthreads();
    if (tid == 0) {
        float t = warp_red[0];
        #pragma unroll
        for (int w = 1; w < 8; ++w) t = fmaxf(t, warp_red[w]);
        bcast = t;
    }
    __syncthreads();
    const float rowmax = bcast;

    float sum = 0.0f;
    #pragma unroll
    for (int i = 0; i < 2; ++i) {
        float4 x = v[i];
        x.x = expf(x.x - rowmax);
        x.y = expf(x.y - rowmax);
        x.z = expf(x.z - rowmax);
        x.w = expf(x.w - rowmax);
        v[i] = x;
        sum += (x.x + x.y) + (x.z + x.w);
    }
    #pragma unroll
    for (int o = 16; o > 0; o >>= 1) sum += __shfl_xor_sync(0xffffffffu, sum, o);
    if ((tid & 31) == 0) warp_red[tid >> 5] = sum;
    __syncthreads();
    if (tid == 0) {
        float t = 0.0f;
        #pragma unroll
        for (int w = 0; w < 8; ++w) t += warp_red[w];
        bcast = t;
    }
    __syncthreads();
    const float inv = 1.0f / bcast;

    #pragma unroll
    for (int i = 0; i < 2; ++i) {
        int k4 = i * 256 + tid;
        if (k4 < wlimit4) {
            float4 x = v[i];
            __half2 h01 = __float22half2_rn(make_float2(x.x * inv, x.y * inv));
            __half2 h23 = __float22half2_rn(make_float2(x.z * inv, x.w * inv));
            *(uint2*)&ph[k4 * 4] = make_uint2(*(unsigned*)&h01, *(unsigned*)&h23);
        }
    }
}

// ---------------------------------------------------------------------------
// Kernel 5: O = P V. P k-contig (non-trans A); V n-contig (trans B).
// CTA 128(M) x 128(N) x 64(K), 4 warps 64x64. grid (8, 16, 4).
// ---------------------------------------------------------------------------
__device__ __forceinline__ void load_pv(char* st,
    const __half* P, const __half* V, int tid)
{
    __half* s = (__half*)st;
    #pragma unroll
    for (int j = 0; j < 8; ++j) {   // P: 128 rows x 8 chunks
        int idx = j * NTHR + tid;
        int r = idx >> 3, c = idx & 7;
        cp16(smem_u32(&s[r * 72 + c * 8]), P + (size_t)r * TLEN + c * 8);
    }
    #pragma unroll
    for (int j = 0; j < 8; ++j) {   // V: 64 rows x 16 chunks
        int idx = j * NTHR + tid;
        int r = idx >> 4, c = idx & 15;
        cp16(smem_u32(&s[SB_OFF + r * 136 + c * 8]), V + (size_t)r * DINT + c * 8);
    }
}

__device__ __forceinline__ void frags_pv(const char* st, int lane, int wm, int wn,
                                         int ks, unsigned a[4][4], unsigned bv[4][4])
{
    const __half* sP = (const __half*)st;
    const __half* sV = sP + SB_OFF;
    const int lrA  = (lane & 7) + ((lane >> 3) & 1) * 8;
    const int kbA  = ks * 16 + (lane >> 4) * 8;
    const int kbV  = ks * 16 + (lane & 7) + ((lane >> 4) & 1) * 8;
    const int lcV8 = ((lane >> 3) & 1) * 8;
    #pragma unroll
    for (int mf = 0; mf < 4; ++mf) {
        int row = wm * 64 + mf * 16 + lrA;
        ldm_x4(smem_u32(&sP[row * 72 + kbA]), a[mf][0], a[mf][1], a[mf][2], a[mf][3]);
    }
    #pragma unroll
    for (int g = 0; g < 4; ++g) {
        int col = wn * 64 + g * 16 + lcV8;
        ldm_x4_t(smem_u32(&sV[kbV * 136 + col]), bv[g][0], bv[g][1], bv[g][2], bv[g][3]);
    }
}

__global__ __launch_bounds__(NTHR, 2)
void pv_gemm_pipe(float* __restrict__ out) {
    const int b  = blockIdx.z;
    const int yy = gridDim.y - 1 - blockIdx.y;
    const int q0 = yy * 128;
    const int n0 = blockIdx.x * 128;
    extern __shared__ char sm[];

    const __half* P = g_Ph + ((size_t)b * TLEN + q0) * TLEN;
    const __half* V = g_Vh + (size_t)b * TLEN * DINT + n0;
    const int nIter = (q0 + 128) / 64;

    const int tid = threadIdx.x, lane = tid & 31, warp = tid >> 5;
    const int wm = warp >> 1, wn = warp & 1;

    float acc[4][8][4] = {};

    load_pv(sm, P, V, tid);
    cp_commit();
    if (nIter > 1) {
        load_pv(sm + STG_PV, P + 64, V + (size_t)64 * DINT, tid);
        cp_commit();
        cp_wait<1>();
    } else {
        cp_wait<0>();
    }
    __syncthreads();

    unsigned f0[4][4], g0[4][4], f1[4][4], g1[4][4];
    frags_pv(sm, lane, wm, wn, 0, f0, g0);

    int sc = 0;
    for (int i = 0; i < nIter; ++i) {
        const char* cur = sm + sc * STG_PV;
        int s1 = sc + 1; if (s1 == NSTG) s1 = 0;
        int s2 = s1 + 1; if (s2 == NSTG) s2 = 0;
        frags_pv(cur, lane, wm, wn, 1, f1, g1);
        mma_tile(f0, g0, acc);
        frags_pv(cur, lane, wm, wn, 2, f0, g0);
        mma_tile(f1, g1, acc);
        frags_pv(cur, lane, wm, wn, 3, f1, g1);
        mma_tile(f0, g0, acc);
        if (i + 2 < nIter) {
            load_pv(sm + s2 * STG_PV,
                    P + (i + 2) * 64, V + (size_t)(i + 2) * 64 * DINT, tid);
            cp_commit();
        }
        if (i + 1 < nIter) {
            if (i + 2 < nIter) cp_wait<1>(); else cp_wait<0>();
            __syncthreads();
            frags_pv(sm + s1 * STG_PV, lane, wm, wn, 0, f0, g0);
        }
        mma_tile(f1, g1, acc);
        sc = s1;
    }

    #pragma unroll
    for (int mf = 0; mf < 4; ++mf)
        #pragma unroll
        for (int nf = 0; nf < 8; ++nf) {
            int q = q0 + wm * 64 + mf * 16 + (lane >> 2);
            int c = n0 + wn * 64 + nf * 8 + (lane & 3) * 2;
            *(float2*)&out[((size_t)(b * TLEN + q)) * DINT + c] =
                make_float2(acc[mf][nf][0], acc[mf][nf][1]);
            *(float2*)&out[((size_t)(b * TLEN + q + 8)) * DINT + c] =
                make_float2(acc[mf][nf][2], acc[mf][nf][3]);
        }
}

// ---------------------------------------------------------------------------
// Launch
// ---------------------------------------------------------------------------
extern "C" void kernel_launch(void* const* d_in, const int* in_sizes, int n_in,
                              void* d_out, int out_size) {
    (void)n_in; (void)out_size; (void)in_sizes;
    const float* input_vecs = (const float*)d_in[0];
    const float* qkv_w      = (const float*)d_in[1];
    const float* sqk        = (const float*)d_in[2];
    float* out              = (float*)d_out;

    const float sqk_mul = sqrtf((float)DMODEL);
    const float scale   = sqrtf((float)DMODEL);
    const int DSMEM_TN = NSTG * STG_TN;   // 110592
    const int DSMEM_PV = NSTG * STG_PV;   // 107520

    cudaFuncSetAttribute(qkv_gemm_pipe, cudaFuncAttributeMaxDynamicSharedMemorySize, DSMEM_TN);
    cudaFuncSetAttribute(qk_gemm_pipe,  cudaFuncAttributeMaxDynamicSharedMemorySize, DSMEM_TN);
    cudaFuncSetAttribute(pv_gemm_pipe,  cudaFuncAttributeMaxDynamicSharedMemorySize, DSMEM_PV);

    init_freq_kernel<<<2, 256>>>();

    __half *xh, *wh;
    cudaGetSymbolAddress((void**)&xh, g_Xh);
    cudaGetSymbolAddress((void**)&wh, g_Wh);
    int nx4 = MTOT * DMODEL / 4, nw4 = 3 * DINT * DMODEL / 4;
    cvt_kernel<<<(nx4 + 255) / 256, 256>>>((const float4*)input_vecs, (uint2*)xh, nx4);
    cvt_kernel<<<(nw4 + 255) / 256, 256>>>((const float4*)qkv_w, (uint2*)wh, nw4);

    qkv_gemm_pipe<<<dim3(3 * DINT / 128, MTOT / 128), NTHR, DSMEM_TN>>>();

    rope_norm_kernel<<<dim3(MTOT, 2), 256>>>(sqk, sqk_mul);

    qk_gemm_pipe<<<dim3(TLEN / 128, TLEN / 128, BATCH), NTHR, DSMEM_TN>>>(scale);

    softmax_kernel<<<dim3(TLEN, BATCH), 256>>>();

    pv_gemm_pipe<<<dim3(DINT / 128, TLEN / 128, BATCH), NTHR, DSMEM_PV>>>(out);
}